// round 5
// baseline (speedup 1.0000x reference)
#include <cuda_runtime.h>
#include <math.h>

// Problem constants
#define C 128
#define L 54            // 6*9
#define NTOK 8
#define MAXB 8192
#define BPB 8

// attn smem strides (floats)
#define TS   132        // s_tgt row stride (16B-aligned rows: 132*4=528)
#define QS   132        // s_qkp row stride
#define WSM  132        // s_w row stride
#define WVS  132        // s_wv row stride
#define PS   17         // per-warp prob patch stride

// ffn strides
#define AS   132
#define WS   132

// Scratch
__device__ float g_qk[64 * 128];
__device__ float g_att[(size_t)MAXB * NTOK * C];

// ---------------------------------------------------------------------------
__device__ __forceinline__ unsigned smem_u32(const void* p) {
    unsigned a;
    asm("{ .reg .u64 t; cvta.to.shared.u64 t, %1; cvt.u32.u64 %0, t; }" : "=r"(a) : "l"(p));
    return a;
}

__device__ __forceinline__ void mma_tf32(float* acc, unsigned a0, unsigned a1,
                                         unsigned a2, unsigned a3,
                                         unsigned b0, unsigned b1) {
    asm volatile(
        "mma.sync.aligned.m16n8k8.row.col.f32.tf32.tf32.f32 "
        "{%0,%1,%2,%3},{%4,%5,%6,%7},{%8,%9},{%0,%1,%2,%3};\n"
        : "+f"(acc[0]), "+f"(acc[1]), "+f"(acc[2]), "+f"(acc[3])
        : "r"(a0), "r"(a1), "r"(a2), "r"(a3), "r"(b0), "r"(b1));
}

__device__ __forceinline__ unsigned f2u(float x) { return __float_as_uint(x); }

// ---------------------------------------------------------------------------
// K0: prep (unchanged)
// ---------------------------------------------------------------------------
__global__ void prep_kernel(const float* __restrict__ q_in,
                            const float* __restrict__ g1, const float* __restrict__ b1,
                            const float* __restrict__ Wq, const float* __restrict__ bq,
                            const float* __restrict__ Wk) {
    __shared__ float s_qn[128];
    __shared__ float s_qh[16];
    __shared__ float s_red[8];
    int th = blockIdx.x, t = th >> 3, h = th & 7;
    int tid = threadIdx.x, lane = tid & 31, warp = tid >> 5;

    float x = q_in[t * 128 + tid];
    float s = x;
    #pragma unroll
    for (int o = 16; o; o >>= 1) s += __shfl_xor_sync(~0u, s, o);
    if (lane == 0) s_red[warp] = s;
    __syncthreads();
    float mean = (s_red[0] + s_red[1] + s_red[2] + s_red[3]) * (1.0f / 128.0f);
    float dx = x - mean;
    float sq = dx * dx;
    #pragma unroll
    for (int o = 16; o; o >>= 1) sq += __shfl_xor_sync(~0u, sq, o);
    __syncthreads();
    if (lane == 0) s_red[warp] = sq;
    __syncthreads();
    float var = (s_red[0] + s_red[1] + s_red[2] + s_red[3]) * (1.0f / 128.0f);
    float inv = rsqrtf(var + 1e-5f);
    s_qn[tid] = dx * inv * g1[tid] + b1[tid];
    __syncthreads();

    int j = tid >> 3, seg = tid & 7;
    int o = h * 16 + j;
    float p = 0.0f;
    #pragma unroll
    for (int i = 0; i < 16; i++) p += s_qn[seg * 16 + i] * Wq[(seg * 16 + i) * 128 + o];
    #pragma unroll
    for (int off = 4; off; off >>= 1) p += __shfl_xor_sync(~0u, p, off);
    if (seg == 0) s_qh[j] = p + bq[o];
    __syncthreads();

    float acc = 0.0f;
    const float* wk = Wk + tid * 128 + h * 16;
    #pragma unroll
    for (int jj = 0; jj < 16; jj++) acc += s_qh[jj] * wk[jj];
    g_qk[th * 128 + tid] = acc * 0.25f;
}

// ---------------------------------------------------------------------------
// region-row offset within region for li (0..8); li>=9 -> 0 (padding)
__device__ __forceinline__ int loff(int li) {
    if (li >= 9) return 0;
    int a = li / 3, b = li - a * 3;
    return a * 9 + b;
}

// ---------------------------------------------------------------------------
// K1: fused attention. 512 threads. Per batch: 2 block barriers only.
// Warp jobs (static):
//   warps 0..7 : region r = warp>>2 (0,1), quarter q = warp&3 -> W cols q*32..+32
//   warps 8..15: region r = 2+((warp-8)>>1), half nh = warp&1 -> W cols nh*64..+64
// Each warp: D (m16n16, 32 mma) -> in-register softmax -> per-warp prob patch
//            -> W (its col slice). Then barrier, V phase (16 warps).
// Row layouts (as round 4):
//   s_qkp rows prow = pos(t)*8 + h (pos = t with 1<->2 swap); region bases
//   {0,16,32,40,48,56}. s_w rows vrow = h*8 + t.
// ---------------------------------------------------------------------------
__global__ __launch_bounds__(512, 1)
void attn_kernel(const float* __restrict__ tgt,
                 const float* __restrict__ Wv, const float* __restrict__ bv,
                 int B) {
    extern __shared__ float sm[];
    float* s_qkp = sm;                    // 72*132
    float* s_wv  = s_qkp + 72 * QS;       // 128*132
    float* s_bv  = s_wv  + 128 * WVS;     // 128
    float* s_tgt = s_bv  + 128;           // 2 * 54*132
    float* s_w   = s_tgt + 2 * L * TS;    // 64*132
    float* s_pw  = s_w   + 64 * WSM;      // 16 * 16*17

    int tid = threadIdx.x;
    int warp = tid >> 5, lane = tid & 31;
    int g = lane >> 2, t4 = lane & 3;

    // prologue: cp.async first batch into buffer 0
    {
        int b0 = blockIdx.x * BPB;
        if (b0 < B) {
            const float4* src = reinterpret_cast<const float4*>(tgt + (size_t)b0 * L * C);
            for (int idx = tid; idx < L * 32; idx += 512) {
                int row = idx >> 5, j = idx & 31;
                unsigned dst = smem_u32(s_tgt + row * TS + j * 4);
                asm volatile("cp.async.ca.shared.global [%0], [%1], 16;\n"
                             :: "r"(dst), "l"(src + idx));
            }
        }
        asm volatile("cp.async.commit_group;\n");
    }

    // stage qk permuted (region-major rows), zero pad rows 64..71
    for (int idx = tid; idx < 64 * 128; idx += 512) {
        int tr = idx >> 7, c = idx & 127;
        int t = tr >> 3, h = tr & 7;
        int pos = t + (t == 1) - (t == 2);
        s_qkp[(pos * 8 + h) * QS + c] = g_qk[idx];
    }
    for (int i = 64 * QS + tid; i < 72 * QS; i += 512) s_qkp[i] = 0.0f;
    for (int idx = tid; idx < 16384; idx += 512) {
        int c = idx >> 7, o = idx & 127;
        s_wv[c * WVS + o] = Wv[idx];
    }
    if (tid < 128) s_bv[tid] = bv[tid];

    // ---- per-warp static job parameters ----
    int rJ, c_base, n_tiles;
    if (warp < 8) { rJ = warp >> 2; c_base = (warp & 3) * 32; n_tiles = 4; }
    else          { rJ = 2 + ((warp - 8) >> 1); c_base = (warp & 1) * 64; n_tiles = 8; }
    int mb = (rJ < 2) ? rJ * 16 : 32 + (rJ - 2) * 8;
    int bl = (rJ / 3) * 27 + (rJ % 3) * 3;
    // D B-rows
    int lD0 = bl + loff(g);
    int lD1 = bl + loff(8 + g);     // g==0 -> col 8, else padding row bl
    // W B-rows per k position
    int lW0 = bl + loff(t4);
    int lW1 = bl + loff(t4 + 4);
    int lW2 = bl + loff(t4 + 8);
    int lW3 = bl + loff(t4 + 12);
    // output row mapping prow -> vrow
    int p0 = mb + g, pos0 = p0 >> 3;
    int tt0 = pos0 + (pos0 == 1) - (pos0 == 2);
    int v0 = (p0 & 7) * 8 + tt0;
    int p1 = mb + g + 8, pos1 = p1 >> 3;
    int tt1 = pos1 + (pos1 == 1) - (pos1 == 2);
    int v1 = (p1 & 7) * 8 + tt1;
    // V phase: 16 jobs = (head hV, half nhV)
    int hV = warp >> 1, nhV = warp & 1;
    int o0 = hV * 16 + nhV * 8;
    // per-warp prob patch
    float* pw = s_pw + warp * (16 * PS);

    __syncthreads();

    for (int bi = 0; bi < BPB; bi++) {
        int b = blockIdx.x * BPB + bi;
        if (b >= B) break;

        float* cur = s_tgt + (bi & 1) * (L * TS);
        float* nxt = s_tgt + ((bi + 1) & 1) * (L * TS);

        int nb = b + 1;
        if (bi + 1 < BPB && nb < B) {
            const float4* src = reinterpret_cast<const float4*>(tgt + (size_t)nb * L * C);
            for (int idx = tid; idx < L * 32; idx += 512) {
                int row = idx >> 5, j = idx & 31;
                unsigned dst = smem_u32(nxt + row * TS + j * 4);
                asm volatile("cp.async.ca.shared.global [%0], [%1], 16;\n"
                             :: "r"(dst), "l"(src + idx));
            }
        }
        asm volatile("cp.async.commit_group;\n");
        asm volatile("cp.async.wait_group 1;\n");
        __syncthreads();   // cur ready; also orders s_w (V of prev batch done)

        // ================= fused D -> softmax -> W (per warp) =================
        // ---- D: m16n16 dots ----
        float accD[2][4];
        #pragma unroll
        for (int i = 0; i < 4; i++) { accD[0][i] = 0.f; accD[1][i] = 0.f; }
        {
            const float* A0 = s_qkp + (mb + g) * QS;
            const float* A1 = s_qkp + (mb + g + 8) * QS;
            const float* B0 = cur + lD0 * TS;
            const float* B1 = cur + lD1 * TS;
            #pragma unroll
            for (int k0 = 0; k0 < 128; k0 += 8) {
                int kr = k0 + t4;
                unsigned ua0 = f2u(A0[kr]), ua1 = f2u(A1[kr]);
                unsigned ua2 = f2u(A0[kr + 4]), ua3 = f2u(A1[kr + 4]);
                unsigned ub0 = f2u(B0[kr]), ub1 = f2u(B0[kr + 4]);
                unsigned ub2 = f2u(B1[kr]), ub3 = f2u(B1[kr + 4]);
                mma_tf32(accD[0], ua0, ua1, ua2, ua3, ub0, ub1);
                mma_tf32(accD[1], ua0, ua1, ua2, ua3, ub2, ub3);
            }
        }

        // ---- softmax (rows g and g+8), valid cols 0..8 ----
        // row g: accD[0][0](c=2t4), accD[0][1](c=2t4+1), accD[1][0](c=8+2t4, valid t4==0)
        {
            bool col8 = (t4 == 0);
            float m0 = fmaxf(accD[0][0], accD[0][1]);
            if (col8) m0 = fmaxf(m0, accD[1][0]);
            float m1 = fmaxf(accD[0][2], accD[0][3]);
            if (col8) m1 = fmaxf(m1, accD[1][2]);
            m0 = fmaxf(m0, __shfl_xor_sync(~0u, m0, 1));
            m0 = fmaxf(m0, __shfl_xor_sync(~0u, m0, 2));
            m1 = fmaxf(m1, __shfl_xor_sync(~0u, m1, 1));
            m1 = fmaxf(m1, __shfl_xor_sync(~0u, m1, 2));
            float e00 = expf(accD[0][0] - m0);
            float e01 = expf(accD[0][1] - m0);
            float e08 = col8 ? expf(accD[1][0] - m0) : 0.0f;
            float e10 = expf(accD[0][2] - m1);
            float e11 = expf(accD[0][3] - m1);
            float e18 = col8 ? expf(accD[1][2] - m1) : 0.0f;
            float s0 = e00 + e01 + e08;
            float s1 = e10 + e11 + e18;
            s0 += __shfl_xor_sync(~0u, s0, 1); s0 += __shfl_xor_sync(~0u, s0, 2);
            s1 += __shfl_xor_sync(~0u, s1, 1); s1 += __shfl_xor_sync(~0u, s1, 2);
            float i0 = 1.0f / s0, i1 = 1.0f / s1;
            // store prob patch: cols 0..15 (cols >8 zero)
            pw[g * PS + 2 * t4]           = e00 * i0;
            pw[g * PS + 2 * t4 + 1]       = e01 * i0;
            pw[g * PS + 8 + 2 * t4]       = e08 * i0;   // 0 unless t4==0
            pw[g * PS + 9 + 2 * t4]       = 0.0f;
            pw[(g + 8) * PS + 2 * t4]     = e10 * i1;
            pw[(g + 8) * PS + 2 * t4 + 1] = e11 * i1;
            pw[(g + 8) * PS + 8 + 2 * t4] = e18 * i1;
            pw[(g + 8) * PS + 9 + 2 * t4] = 0.0f;
        }
        __syncwarp();

        // A-fragments for W (k=16)
        unsigned a0 = f2u(pw[g * PS + t4]);
        unsigned a1 = f2u(pw[(g + 8) * PS + t4]);
        unsigned a2 = f2u(pw[g * PS + t4 + 4]);
        unsigned a3 = f2u(pw[(g + 8) * PS + t4 + 4]);
        unsigned a4 = f2u(pw[g * PS + t4 + 8]);
        unsigned a5 = f2u(pw[(g + 8) * PS + t4 + 8]);
        unsigned a6 = f2u(pw[g * PS + t4 + 12]);
        unsigned a7 = f2u(pw[(g + 8) * PS + t4 + 12]);

        // ---- W: weighted sum for this warp's col slice ----
        #pragma unroll
        for (int nt = 0; nt < 8; nt++) {
            if (nt >= n_tiles) break;
            int c0 = c_base + nt * 8;
            float acc[4] = {0.f, 0.f, 0.f, 0.f};
            mma_tf32(acc, a0, a1, a2, a3,
                     f2u(cur[lW0 * TS + c0 + g]), f2u(cur[lW1 * TS + c0 + g]));
            mma_tf32(acc, a4, a5, a6, a7,
                     f2u(cur[lW2 * TS + c0 + g]), f2u(cur[lW3 * TS + c0 + g]));
            int cc = c0 + 2 * t4;
            *reinterpret_cast<float2*>(&s_w[v0 * WSM + cc]) = make_float2(acc[0], acc[1]);
            if (rJ < 2)
                *reinterpret_cast<float2*>(&s_w[v1 * WSM + cc]) = make_float2(acc[2], acc[3]);
        }
        __syncthreads();   // s_w complete

        // ---- V: att[t, o] = w[vrow=hV*8+t] . Wv[:, o] + bv ----
        {
            float acc[4] = {0.f, 0.f, 0.f, 0.f};
            const float* Ar0 = s_w + (hV * 8 + g) * WSM;
            const float* Ar1 = s_w + (hV * 8 + g + 8) * WSM;
            #pragma unroll
            for (int k0 = 0; k0 < 128; k0 += 8) {
                int kr = k0 + t4;
                mma_tf32(acc,
                         f2u(Ar0[kr]), f2u(Ar1[kr]),
                         f2u(Ar0[kr + 4]), f2u(Ar1[kr + 4]),
                         f2u(s_wv[kr * WVS + o0 + g]),
                         f2u(s_wv[(kr + 4) * WVS + o0 + g]));
            }
            int o = o0 + 2 * t4;
            float* op = g_att + ((size_t)b * NTOK + g) * C + o;
            *reinterpret_cast<float2*>(op) =
                make_float2(acc[0] + s_bv[o], acc[1] + s_bv[o + 1]);
        }
        // no trailing barrier: next iteration's post-wait __syncthreads orders
        // s_w reads (V) before the next W writes, and tgt reads before prefetch
        // overwrite (prefetch targets the buffer last read before prev barrier).
    }
}

// ---------------------------------------------------------------------------
// K2: FFN chain via mma.sync tf32 (unchanged)
// ---------------------------------------------------------------------------
__device__ __forceinline__ void gemm_mma(const float* __restrict__ P,
                                         const float* __restrict__ WB,
                                         float acc[2][4][4], int RM, int CN, int lane) {
    #pragma unroll
    for (int mt = 0; mt < 2; mt++)
        #pragma unroll
        for (int nt = 0; nt < 4; nt++)
            #pragma unroll
            for (int i = 0; i < 4; i++) acc[mt][nt][i] = 0.0f;

    const unsigned* Pu = reinterpret_cast<const unsigned*>(P);
    const unsigned* Wu = reinterpret_cast<const unsigned*>(WB);
    int g = lane >> 2, t = lane & 3;

    #pragma unroll
    for (int k0 = 0; k0 < 128; k0 += 8) {
        int kr = k0 + t;
        unsigned a[2][4];
        #pragma unroll
        for (int mt = 0; mt < 2; mt++) {
            int r0 = RM + mt * 16 + g;
            a[mt][0] = Pu[r0 * AS + kr];
            a[mt][1] = Pu[(r0 + 8) * AS + kr];
            a[mt][2] = Pu[r0 * AS + kr + 4];
            a[mt][3] = Pu[(r0 + 8) * AS + kr + 4];
        }
        unsigned bfr[4][2];
        #pragma unroll
        for (int nt = 0; nt < 4; nt++) {
            int c0 = CN + nt * 8 + g;
            bfr[nt][0] = Wu[kr * WS + c0];
            bfr[nt][1] = Wu[(kr + 4) * WS + c0];
        }
        #pragma unroll
        for (int mt = 0; mt < 2; mt++)
            #pragma unroll
            for (int nt = 0; nt < 4; nt++)
                mma_tf32(acc[mt][nt], a[mt][0], a[mt][1], a[mt][2], a[mt][3],
                         bfr[nt][0], bfr[nt][1]);
    }
}

__global__ __launch_bounds__(512, 1)
void ffn_kernel(const float* __restrict__ query,
                const float* __restrict__ g2, const float* __restrict__ b2,
                const float* __restrict__ Wp, const float* __restrict__ bp,
                const float* __restrict__ Wf1, const float* __restrict__ bf1,
                const float* __restrict__ Wf2, const float* __restrict__ bf2,
                float* __restrict__ out, int nrows) {
    extern __shared__ float sm[];
    float* WB  = sm;
    float* P   = WB + 128 * WS;
    float* Q   = P  + 128 * AS;
    float* s_qr  = Q + 128 * AS;
    float* s_bp  = s_qr + 1024;
    float* s_bf1 = s_bp + 128;
    float* s_bf2 = s_bf1 + 128;
    float* s_g2  = s_bf2 + 128;
    float* s_b2  = s_g2 + 128;

    int tid = threadIdx.x;
    int warp = tid >> 5, lane = tid & 31;
    int g = lane >> 2, t4 = lane & 3;
    int RM = (warp >> 2) * 32, CN = (warp & 3) * 32;
    int R0 = blockIdx.x * 128;
    if (R0 >= nrows) return;

    {
        const float4* src = reinterpret_cast<const float4*>(g_att + (size_t)R0 * C);
        for (int idx = tid; idx < 128 * 32; idx += 512) {
            int row = idx >> 5, j = idx & 31;
            reinterpret_cast<float4*>(P + row * AS)[j] = src[row * 32 + j];
        }
        for (int idx = tid; idx < 128 * 32; idx += 512) {
            int row = idx >> 5, j = idx & 31;
            reinterpret_cast<float4*>(WB + row * WS)[j] =
                reinterpret_cast<const float4*>(Wp)[row * 32 + j];
        }
        for (int i = tid; i < 1024; i += 512) s_qr[i] = query[i];
        if (tid < 128) {
            s_bp[tid] = bp[tid]; s_bf1[tid] = bf1[tid]; s_bf2[tid] = bf2[tid];
            s_g2[tid] = g2[tid]; s_b2[tid] = b2[tid];
        }
    }
    __syncthreads();

    float acc[2][4][4];

    gemm_mma(P, WB, acc, RM, CN, lane);
    #pragma unroll
    for (int mt = 0; mt < 2; mt++) {
        int r = RM + mt * 16 + g;
        #pragma unroll
        for (int nt = 0; nt < 4; nt++) {
            int c = CN + nt * 8 + 2 * t4;
            int tq = r & 7;
            *reinterpret_cast<float2*>(&Q[r * AS + c]) = make_float2(
                acc[mt][nt][0] + s_bp[c]     + s_qr[tq * 128 + c],
                acc[mt][nt][1] + s_bp[c + 1] + s_qr[tq * 128 + c + 1]);
            *reinterpret_cast<float2*>(&Q[(r + 8) * AS + c]) = make_float2(
                acc[mt][nt][2] + s_bp[c]     + s_qr[tq * 128 + c],
                acc[mt][nt][3] + s_bp[c + 1] + s_qr[tq * 128 + c + 1]);
        }
    }
    __syncthreads();

    {
        for (int r = warp; r < 128; r += 16) {
            float4 v = *reinterpret_cast<const float4*>(&Q[r * AS + lane * 4]);
            float s = v.x + v.y + v.z + v.w;
            #pragma unroll
            for (int o = 16; o; o >>= 1) s += __shfl_xor_sync(~0u, s, o);
            float mean = s * (1.0f / 128.0f);
            float dx = v.x - mean, dy = v.y - mean, dz = v.z - mean, dw = v.w - mean;
            float sq = dx * dx + dy * dy + dz * dz + dw * dw;
            #pragma unroll
            for (int o = 16; o; o >>= 1) sq += __shfl_xor_sync(~0u, sq, o);
            float inv = rsqrtf(sq * (1.0f / 128.0f) + 1e-5f);
            int c = lane * 4;
            float4 gg = *reinterpret_cast<const float4*>(&s_g2[c]);
            float4 bb = *reinterpret_cast<const float4*>(&s_b2[c]);
            float4 o4;
            o4.x = dx * inv * gg.x + bb.x;
            o4.y = dy * inv * gg.y + bb.y;
            o4.z = dz * inv * gg.z + bb.z;
            o4.w = dw * inv * gg.w + bb.w;
            *reinterpret_cast<float4*>(&P[r * AS + c]) = o4;
        }
        for (int idx = tid; idx < 128 * 32; idx += 512) {
            int row = idx >> 5, j = idx & 31;
            reinterpret_cast<float4*>(WB + row * WS)[j] =
                reinterpret_cast<const float4*>(Wf1)[row * 32 + j];
        }
    }
    __syncthreads();

    gemm_mma(P, WB, acc, RM, CN, lane);
    __syncthreads();
    #pragma unroll
    for (int mt = 0; mt < 2; mt++) {
        int r = RM + mt * 16 + g;
        #pragma unroll
        for (int nt = 0; nt < 4; nt++) {
            int c = CN + nt * 8 + 2 * t4;
            float v0 = acc[mt][nt][0] + s_bf1[c];
            float v1 = acc[mt][nt][1] + s_bf1[c + 1];
            float v2 = acc[mt][nt][2] + s_bf1[c];
            float v3 = acc[mt][nt][3] + s_bf1[c + 1];
            const float k = 0.70710678118654752f;
            *reinterpret_cast<float2*>(&P[r * AS + c]) = make_float2(
                0.5f * v0 * (1.0f + erff(v0 * k)),
                0.5f * v1 * (1.0f + erff(v1 * k)));
            *reinterpret_cast<float2*>(&P[(r + 8) * AS + c]) = make_float2(
                0.5f * v2 * (1.0f + erff(v2 * k)),
                0.5f * v3 * (1.0f + erff(v3 * k)));
        }
    }
    for (int idx = tid; idx < 128 * 32; idx += 512) {
        int row = idx >> 5, j = idx & 31;
        reinterpret_cast<float4*>(WB + row * WS)[j] =
            reinterpret_cast<const float4*>(Wf2)[row * 32 + j];
    }
    __syncthreads();

    gemm_mma(P, WB, acc, RM, CN, lane);
    #pragma unroll
    for (int mt = 0; mt < 2; mt++) {
        int r = RM + mt * 16 + g;
        #pragma unroll
        for (int nt = 0; nt < 4; nt++) {
            int c = CN + nt * 8 + 2 * t4;
            float2 q0 = *reinterpret_cast<const float2*>(&Q[r * AS + c]);
            float2 q1 = *reinterpret_cast<const float2*>(&Q[(r + 8) * AS + c]);
            float* o0 = out + (size_t)(R0 + r) * C + c;
            float* o1 = out + (size_t)(R0 + r + 8) * C + c;
            *reinterpret_cast<float2*>(o0) = make_float2(
                acc[mt][nt][0] + s_bf2[c] + q0.x,
                acc[mt][nt][1] + s_bf2[c + 1] + q0.y);
            *reinterpret_cast<float2*>(o1) = make_float2(
                acc[mt][nt][2] + s_bf2[c] + q1.x,
                acc[mt][nt][3] + s_bf2[c + 1] + q1.y);
        }
    }
}

// ---------------------------------------------------------------------------
extern "C" void kernel_launch(void* const* d_in, const int* in_sizes, int n_in,
                              void* d_out, int out_size) {
    const float* query = (const float*)d_in[0];
    const float* tgt   = (const float*)d_in[1];
    const float* ln1g  = (const float*)d_in[2];
    const float* ln1b  = (const float*)d_in[3];
    const float* ln2g  = (const float*)d_in[4];
    const float* ln2b  = (const float*)d_in[5];
    const float* Wq    = (const float*)d_in[6];
    const float* bq    = (const float*)d_in[7];
    const float* Wk    = (const float*)d_in[8];
    // d_in[9] = bk (cancels in softmax)
    const float* Wv    = (const float*)d_in[10];
    const float* bv    = (const float*)d_in[11];
    const float* Wp    = (const float*)d_in[12];
    const float* bp    = (const float*)d_in[13];
    const float* Wf1   = (const float*)d_in[14];
    const float* bf1   = (const float*)d_in[15];
    const float* Wf2   = (const float*)d_in[16];
    const float* bf2   = (const float*)d_in[17];

    int B = in_sizes[1] / (L * C);
    if (B > MAXB) B = MAXB;

    const int K1_SMEM = (72 * QS + 128 * WVS + 128 + 2 * L * TS + 64 * WSM + 16 * 16 * PS)
                        * sizeof(float);
    const int K2_SMEM = (128 * WS + 2 * 128 * AS + 1024 + 5 * 128) * sizeof(float);

    cudaFuncSetAttribute(attn_kernel, cudaFuncAttributeMaxDynamicSharedMemorySize, K1_SMEM);
    cudaFuncSetAttribute(ffn_kernel,  cudaFuncAttributeMaxDynamicSharedMemorySize, K2_SMEM);

    prep_kernel<<<64, 128>>>(query, ln1g, ln1b, Wq, bq, Wk);
    attn_kernel<<<(B + BPB - 1) / BPB, 512, K1_SMEM>>>(tgt, Wv, bv, B);

    int nrows = B * NTOK;
    ffn_kernel<<<(nrows + 127) / 128, 512, K2_SMEM>>>(query, ln2g, ln2b,
                                                      Wp, bp, Wf1, bf1, Wf2, bf2,
                                                      (float*)d_out, nrows);
}

// round 6
// speedup vs baseline: 1.0882x; 1.0882x over previous
#include <cuda_runtime.h>
#include <math.h>

// Problem constants
#define C 128
#define L 54            // 6*9
#define NTOK 8
#define MAXB 8192
#define BPB 8

// permuted k layout: element k stored at (k&3)*36 + (k>>2); row 144 floats
#define PERM(k) ((((k) & 3) * 36) + ((k) >> 2))

// attn smem strides
#define TS   148        // s_tgt row stride (592B = 37*16, aligned)
#define QS   148        // s_qkp row stride
#define WSM  148        // s_w row stride
#define SPS  20         // probs row stride (natural li layout)

// ffn strides
#define AS   148        // P (permuted operand)
#define WS   132        // weight (natural)
#define QAS  132        // Q (natural)

// Scratch
__device__ float g_qk[64 * 128];
__device__ float g_att[(size_t)MAXB * NTOK * C];

// ---------------------------------------------------------------------------
__device__ __forceinline__ void mma_tf32(float* acc, unsigned a0, unsigned a1,
                                         unsigned a2, unsigned a3,
                                         unsigned b0, unsigned b1) {
    asm volatile(
        "mma.sync.aligned.m16n8k8.row.col.f32.tf32.tf32.f32 "
        "{%0,%1,%2,%3},{%4,%5,%6,%7},{%8,%9},{%0,%1,%2,%3};\n"
        : "+f"(acc[0]), "+f"(acc[1]), "+f"(acc[2]), "+f"(acc[3])
        : "r"(a0), "r"(a1), "r"(a2), "r"(a3), "r"(b0), "r"(b1));
}
__device__ __forceinline__ unsigned f2u(float x) { return __float_as_uint(x); }

// ---------------------------------------------------------------------------
// K0: prep (unchanged)
// ---------------------------------------------------------------------------
__global__ void prep_kernel(const float* __restrict__ q_in,
                            const float* __restrict__ g1, const float* __restrict__ b1,
                            const float* __restrict__ Wq, const float* __restrict__ bq,
                            const float* __restrict__ Wk) {
    __shared__ float s_qn[128];
    __shared__ float s_qh[16];
    __shared__ float s_red[8];
    int th = blockIdx.x, t = th >> 3, h = th & 7;
    int tid = threadIdx.x, lane = tid & 31, warp = tid >> 5;

    float x = q_in[t * 128 + tid];
    float s = x;
    #pragma unroll
    for (int o = 16; o; o >>= 1) s += __shfl_xor_sync(~0u, s, o);
    if (lane == 0) s_red[warp] = s;
    __syncthreads();
    float mean = (s_red[0] + s_red[1] + s_red[2] + s_red[3]) * (1.0f / 128.0f);
    float dx = x - mean;
    float sq = dx * dx;
    #pragma unroll
    for (int o = 16; o; o >>= 1) sq += __shfl_xor_sync(~0u, sq, o);
    __syncthreads();
    if (lane == 0) s_red[warp] = sq;
    __syncthreads();
    float var = (s_red[0] + s_red[1] + s_red[2] + s_red[3]) * (1.0f / 128.0f);
    float inv = rsqrtf(var + 1e-5f);
    s_qn[tid] = dx * inv * g1[tid] + b1[tid];
    __syncthreads();

    int j = tid >> 3, seg = tid & 7;
    int o = h * 16 + j;
    float p = 0.0f;
    #pragma unroll
    for (int i = 0; i < 16; i++) p += s_qn[seg * 16 + i] * Wq[(seg * 16 + i) * 128 + o];
    #pragma unroll
    for (int off = 4; off; off >>= 1) p += __shfl_xor_sync(~0u, p, off);
    if (seg == 0) s_qh[j] = p + bq[o];
    __syncthreads();

    float acc = 0.0f;
    const float* wk = Wk + tid * 128 + h * 16;
    #pragma unroll
    for (int jj = 0; jj < 16; jj++) acc += s_qh[jj] * wk[jj];
    g_qk[th * 128 + tid] = acc * 0.25f;
}

// region-row offset for li (0..8); li>=9 -> 0 (padding)
__device__ __forceinline__ int loff(int li) {
    if (li >= 9) return 0;
    int a = li / 3, b = li - a * 3;
    return a * 9 + b;
}

// ---------------------------------------------------------------------------
// K1: fused attention, R4 phase structure + k-permuted layout + vector LDS.
// ---------------------------------------------------------------------------
__global__ __launch_bounds__(512, 1)
void attn_kernel(const float* __restrict__ tgt,
                 const float* __restrict__ Wv, const float* __restrict__ bv,
                 int B) {
    extern __shared__ float sm[];
    float* s_qkp = sm;                    // 72*148
    float* s_bv  = s_qkp + 72 * QS;       // 128
    float* s_tgt = s_bv  + 128;           // 2 * 54*148
    float* s_w   = s_tgt + 2 * L * TS;    // 64*148
    float* s_p   = s_w   + 64 * WSM;      // 72*20

    int tid = threadIdx.x;
    int warp = tid >> 5, lane = tid & 31;
    int g = lane >> 2, t4 = lane & 3;
    int B4 = t4 * 36;

    // ---- per-warp static job parameters (R4) ----
    bool okD = warp < 12;
    int rD  = warp >> 1, nhD = warp & 1;          // valid for warp<12
    int mbD = (rD < 2) ? rD * 16 : 32 + (rD - 2) * 8;
    int blD = (rD / 3) * 27 + (rD % 3) * 3;
    int lD  = blD + loff(nhD * 8 + g);            // D: B row per lane
    int lW0 = blD + loff(t4);
    int lW1 = blD + loff(t4 + 4);
    int lW2 = blD + loff(t4 + 8);
    int lW3 = blD + loff(t4 + 12);
    // prow -> vrow mapping for W outputs
    int p0 = mbD + g, pos0 = p0 >> 3;
    int tt0 = pos0 + (pos0 == 1) - (pos0 == 2);
    int v0 = (p0 & 7) * 8 + tt0;
    int p1 = mbD + g + 8, pos1 = p1 >> 3;
    int tt1 = pos1 + (pos1 == 1) - (pos1 == 2);
    int v1 = (p1 & 7) * 8 + tt1;
    // V phase
    int hV = warp >> 1, nhV = warp & 1;
    int o0 = hV * 16 + nhV * 8;

    // ---- hoist Wv B-fragments into registers (static) ----
    float bwv[16][2];
    #pragma unroll
    for (int jj = 0; jj < 16; jj++) {
        int k0 = 8 * jj;
        bwv[jj][0] = Wv[(k0 + t4) * 128 + o0 + g];
        bwv[jj][1] = Wv[(k0 + t4 + 4) * 128 + o0 + g];
    }

    // ---- staging ----
    // qk permuted rows
    for (int idx = tid; idx < 2048; idx += 512) {
        int tr = idx >> 5, j = idx & 31;
        int t = tr >> 3, h = tr & 7;
        int pos = t + (t == 1) - (t == 2);
        int prow = pos * 8 + h;
        float4 v = reinterpret_cast<const float4*>(g_qk)[idx];
        s_qkp[prow * QS + j]       = v.x;
        s_qkp[prow * QS + 36 + j]  = v.y;
        s_qkp[prow * QS + 72 + j]  = v.z;
        s_qkp[prow * QS + 108 + j] = v.w;
    }
    for (int i = 64 * QS + tid; i < 72 * QS; i += 512) s_qkp[i] = 0.0f;
    for (int i = tid; i < 72 * SPS; i += 512) s_p[i] = 0.0f;
    if (tid < 128) s_bv[tid] = bv[tid];

    // batch 0 into buffer 0 (permuted)
    {
        int b0 = blockIdx.x * BPB;
        if (b0 < B) {
            const float4* src = reinterpret_cast<const float4*>(tgt + (size_t)b0 * L * C);
            #pragma unroll
            for (int q = 0; q < 4; q++) {
                int id = tid + q * 512;
                if (id < L * 32) {
                    int row = id >> 5, j = id & 31;
                    float4 v = src[id];
                    s_tgt[row * TS + j]       = v.x;
                    s_tgt[row * TS + 36 + j]  = v.y;
                    s_tgt[row * TS + 72 + j]  = v.z;
                    s_tgt[row * TS + 108 + j] = v.w;
                }
            }
        }
    }
    __syncthreads();

    for (int bi = 0; bi < BPB; bi++) {
        int b = blockIdx.x * BPB + bi;
        if (b >= B) break;

        float* cur = s_tgt + (bi & 1) * (L * TS);
        float* nxt = s_tgt + ((bi + 1) & 1) * (L * TS);

        // register prefetch of next batch
        float4 pv[4];
        int nb = b + 1;
        bool pf = (bi + 1 < BPB) && (nb < B);
        if (pf) {
            const float4* src = reinterpret_cast<const float4*>(tgt + (size_t)nb * L * C);
            #pragma unroll
            for (int q = 0; q < 4; q++) {
                int id = tid + q * 512;
                if (id < L * 32) pv[q] = src[id];
            }
        }

        // ---- D: dots (12 warps, m16n8, vectorized LDS) ----
        if (okD) {
            float acc[4] = {0.f, 0.f, 0.f, 0.f};
            const float* A0 = s_qkp + (mbD + g) * QS + B4;
            const float* A1 = s_qkp + (mbD + g + 8) * QS + B4;
            const float* Br = cur + lD * TS + B4;
            #pragma unroll
            for (int m = 0; m < 8; m++) {
                float4 a0v = *reinterpret_cast<const float4*>(A0 + 4 * m);
                float4 a1v = *reinterpret_cast<const float4*>(A1 + 4 * m);
                float4 bv4 = *reinterpret_cast<const float4*>(Br + 4 * m);
                mma_tf32(acc, f2u(a0v.x), f2u(a1v.x), f2u(a0v.y), f2u(a1v.y),
                         f2u(bv4.x), f2u(bv4.y));
                mma_tf32(acc, f2u(a0v.z), f2u(a1v.z), f2u(a0v.w), f2u(a1v.w),
                         f2u(bv4.z), f2u(bv4.w));
            }
            int li0 = nhD * 8 + 2 * t4;
            if (li0 < 8) {
                *reinterpret_cast<float2*>(&s_p[(mbD + g) * SPS + li0]) =
                    make_float2(acc[0], acc[1]);
                if (rD < 2)
                    *reinterpret_cast<float2*>(&s_p[(mbD + g + 8) * SPS + li0]) =
                        make_float2(acc[2], acc[3]);
            } else if (li0 == 8) {
                s_p[(mbD + g) * SPS + 8] = acc[0];
                if (rD < 2) s_p[(mbD + g + 8) * SPS + 8] = acc[2];
            }
        }
        __syncthreads();

        // ---- softmax over 9 per row ----
        if (tid < 64) {
            float* pp = s_p + tid * SPS;
            float m = -1e30f;
            #pragma unroll
            for (int li = 0; li < 9; li++) m = fmaxf(m, pp[li]);
            float e[9]; float ssum = 0.0f;
            #pragma unroll
            for (int li = 0; li < 9; li++) { e[li] = expf(pp[li] - m); ssum += e[li]; }
            float invs = 1.0f / ssum;
            #pragma unroll
            for (int li = 0; li < 9; li++) pp[li] = e[li] * invs;
        }
        __syncthreads();

        // ---- W: weighted sum (12 warps), outputs permuted into s_w ----
        if (okD) {
            const float* Ar0 = s_p + (mbD + g) * SPS;
            const float* Ar1 = s_p + (mbD + g + 8) * SPS;
            unsigned a0 = f2u(Ar0[t4]),      a1 = f2u(Ar1[t4]);
            unsigned a2 = f2u(Ar0[t4 + 4]),  a3 = f2u(Ar1[t4 + 4]);
            unsigned a4 = f2u(Ar0[t4 + 8]),  a5 = f2u(Ar1[t4 + 8]);
            unsigned a6 = f2u(Ar0[t4 + 12]), a7 = f2u(Ar1[t4 + 12]);
            int pg = (g & 3) * 36 + (g >> 2);   // PERM(c0+g) - c0/4
            #pragma unroll
            for (int nt = 0; nt < 8; nt++) {
                int c0 = nhD * 64 + nt * 8;
                int bidx = pg + (c0 >> 2);
                float acc[4] = {0.f, 0.f, 0.f, 0.f};
                mma_tf32(acc, a0, a1, a2, a3,
                         f2u(cur[lW0 * TS + bidx]), f2u(cur[lW1 * TS + bidx]));
                mma_tf32(acc, a4, a5, a6, a7,
                         f2u(cur[lW2 * TS + bidx]), f2u(cur[lW3 * TS + bidx]));
                int cc = c0 + 2 * t4;
                int pcc = ((cc & 3) * 36) + (cc >> 2);
                s_w[v0 * WSM + pcc]      = acc[0];
                s_w[v0 * WSM + pcc + 36] = acc[1];
                if (rD < 2) {
                    s_w[v1 * WSM + pcc]      = acc[2];
                    s_w[v1 * WSM + pcc + 36] = acc[3];
                }
            }
        }

        // store prefetched batch into nxt (permuted)
        if (pf) {
            #pragma unroll
            for (int q = 0; q < 4; q++) {
                int id = tid + q * 512;
                if (id < L * 32) {
                    int row = id >> 5, j = id & 31;
                    nxt[row * TS + j]       = pv[q].x;
                    nxt[row * TS + 36 + j]  = pv[q].y;
                    nxt[row * TS + 72 + j]  = pv[q].z;
                    nxt[row * TS + 108 + j] = pv[q].w;
                }
            }
        }
        __syncthreads();

        // ---- V: att = w @ Wv + bv (16 warps, vec A, hoisted B) ----
        {
            float acc[4] = {0.f, 0.f, 0.f, 0.f};
            const float* Ar0 = s_w + (hV * 8 + g) * WSM + B4;
            const float* Ar1 = s_w + (hV * 8 + g + 8) * WSM + B4;
            #pragma unroll
            for (int m = 0; m < 8; m++) {
                float4 a0v = *reinterpret_cast<const float4*>(Ar0 + 4 * m);
                float4 a1v = *reinterpret_cast<const float4*>(Ar1 + 4 * m);
                mma_tf32(acc, f2u(a0v.x), f2u(a1v.x), f2u(a0v.y), f2u(a1v.y),
                         f2u(bwv[2 * m][0]), f2u(bwv[2 * m][1]));
                mma_tf32(acc, f2u(a0v.z), f2u(a1v.z), f2u(a0v.w), f2u(a1v.w),
                         f2u(bwv[2 * m + 1][0]), f2u(bwv[2 * m + 1][1]));
            }
            int o = o0 + 2 * t4;
            float* op = g_att + ((size_t)b * NTOK + g) * C + o;
            *reinterpret_cast<float2*>(op) =
                make_float2(acc[0] + s_bv[o], acc[1] + s_bv[o + 1]);
        }
        // loop: next D reads nxt (synced above); s_w reuse guarded by D+softmax syncs
    }
}

// ---------------------------------------------------------------------------
// K2: FFN chain, tf32 mma, A-side vectorized via permuted P.
// ---------------------------------------------------------------------------
__device__ __forceinline__ void gemm_mma_v(const float* __restrict__ P,
                                           const float* __restrict__ WB,
                                           float acc[2][4][4], int RM, int CN, int lane) {
    #pragma unroll
    for (int mt = 0; mt < 2; mt++)
        #pragma unroll
        for (int nt = 0; nt < 4; nt++)
            #pragma unroll
            for (int i = 0; i < 4; i++) acc[mt][nt][i] = 0.0f;

    int g = lane >> 2, t4 = lane & 3;
    const float* A0 = P + (RM + g) * AS + t4 * 36;
    const float* A1 = P + (RM + g + 8) * AS + t4 * 36;
    const float* A2 = P + (RM + 16 + g) * AS + t4 * 36;
    const float* A3 = P + (RM + 16 + g + 8) * AS + t4 * 36;
    const unsigned* Wu = reinterpret_cast<const unsigned*>(WB);

    #pragma unroll
    for (int m = 0; m < 8; m++) {
        float4 a0v = *reinterpret_cast<const float4*>(A0 + 4 * m);
        float4 a1v = *reinterpret_cast<const float4*>(A1 + 4 * m);
        float4 a2v = *reinterpret_cast<const float4*>(A2 + 4 * m);
        float4 a3v = *reinterpret_cast<const float4*>(A3 + 4 * m);
        int kr0 = 16 * m + t4;
        int kr1 = 16 * m + 8 + t4;
        #pragma unroll
        for (int nt = 0; nt < 4; nt++) {
            int c0 = CN + nt * 8 + g;
            unsigned b00 = Wu[kr0 * WS + c0];
            unsigned b01 = Wu[(kr0 + 4) * WS + c0];
            mma_tf32(acc[0][nt], f2u(a0v.x), f2u(a1v.x), f2u(a0v.y), f2u(a1v.y), b00, b01);
            mma_tf32(acc[1][nt], f2u(a2v.x), f2u(a3v.x), f2u(a2v.y), f2u(a3v.y), b00, b01);
        }
        #pragma unroll
        for (int nt = 0; nt < 4; nt++) {
            int c0 = CN + nt * 8 + g;
            unsigned b10 = Wu[kr1 * WS + c0];
            unsigned b11 = Wu[(kr1 + 4) * WS + c0];
            mma_tf32(acc[0][nt], f2u(a0v.z), f2u(a1v.z), f2u(a0v.w), f2u(a1v.w), b10, b11);
            mma_tf32(acc[1][nt], f2u(a2v.z), f2u(a3v.z), f2u(a2v.w), f2u(a3v.w), b10, b11);
        }
    }
}

__global__ __launch_bounds__(512, 1)
void ffn_kernel(const float* __restrict__ query,
                const float* __restrict__ g2, const float* __restrict__ b2,
                const float* __restrict__ Wp, const float* __restrict__ bp,
                const float* __restrict__ Wf1, const float* __restrict__ bf1,
                const float* __restrict__ Wf2, const float* __restrict__ bf2,
                float* __restrict__ out, int nrows) {
    extern __shared__ float sm[];
    float* WB  = sm;                    // 128*132
    float* P   = WB + 128 * WS;         // 128*148 (permuted)
    float* Q   = P  + 128 * AS;         // 128*132 (natural)
    float* s_qr  = Q + 128 * QAS;       // 1024
    float* s_bp  = s_qr + 1024;
    float* s_bf1 = s_bp + 128;
    float* s_bf2 = s_bf1 + 128;
    float* s_g2  = s_bf2 + 128;
    float* s_b2  = s_g2 + 128;

    int tid = threadIdx.x;
    int warp = tid >> 5, lane = tid & 31;
    int g = lane >> 2, t4 = lane & 3;
    int RM = (warp >> 2) * 32, CN = (warp & 3) * 32;
    int R0 = blockIdx.x * 128;
    if (R0 >= nrows) return;

    // stage: P = att tile (permuted), WB = Wp (natural), misc
    {
        const float4* src = reinterpret_cast<const float4*>(g_att + (size_t)R0 * C);
        for (int idx = tid; idx < 4096; idx += 512) {
            int row = idx >> 5, j = idx & 31;
            float4 v = src[idx];
            P[row * AS + j]       = v.x;
            P[row * AS + 36 + j]  = v.y;
            P[row * AS + 72 + j]  = v.z;
            P[row * AS + 108 + j] = v.w;
        }
        for (int idx = tid; idx < 4096; idx += 512) {
            int row = idx >> 5, j = idx & 31;
            reinterpret_cast<float4*>(WB + row * WS)[j] =
                reinterpret_cast<const float4*>(Wp)[idx];
        }
        for (int i = tid; i < 1024; i += 512) s_qr[i] = query[i];
        if (tid < 128) {
            s_bp[tid] = bp[tid]; s_bf1[tid] = bf1[tid]; s_bf2[tid] = bf2[tid];
            s_g2[tid] = g2[tid]; s_b2[tid] = b2[tid];
        }
    }
    __syncthreads();

    float acc[2][4][4];

    // ---- GEMM1: X = att@Wp + bp + shortcut -> Q (natural) ----
    gemm_mma_v(P, WB, acc, RM, CN, lane);
    #pragma unroll
    for (int mt = 0; mt < 2; mt++) {
        int r = RM + mt * 16 + g;
        #pragma unroll
        for (int nt = 0; nt < 4; nt++) {
            int c = CN + nt * 8 + 2 * t4;
            int tq = r & 7;
            *reinterpret_cast<float2*>(&Q[r * QAS + c]) = make_float2(
                acc[mt][nt][0] + s_bp[c]     + s_qr[tq * 128 + c],
                acc[mt][nt][1] + s_bp[c + 1] + s_qr[tq * 128 + c + 1]);
            *reinterpret_cast<float2*>(&Q[(r + 8) * QAS + c]) = make_float2(
                acc[mt][nt][2] + s_bp[c]     + s_qr[tq * 128 + c],
                acc[mt][nt][3] + s_bp[c + 1] + s_qr[tq * 128 + c + 1]);
        }
    }
    __syncthreads();

    // ---- LN rows Q -> P (permuted writes); load Wf1 -> WB ----
    {
        for (int r = warp; r < 128; r += 16) {
            float4 v = *reinterpret_cast<const float4*>(&Q[r * QAS + lane * 4]);
            float s = v.x + v.y + v.z + v.w;
            #pragma unroll
            for (int o = 16; o; o >>= 1) s += __shfl_xor_sync(~0u, s, o);
            float mean = s * (1.0f / 128.0f);
            float dx = v.x - mean, dy = v.y - mean, dz = v.z - mean, dw = v.w - mean;
            float sq = dx * dx + dy * dy + dz * dz + dw * dw;
            #pragma unroll
            for (int o = 16; o; o >>= 1) sq += __shfl_xor_sync(~0u, sq, o);
            float inv = rsqrtf(sq * (1.0f / 128.0f) + 1e-5f);
            int c = lane * 4;
            float4 gg = *reinterpret_cast<const float4*>(&s_g2[c]);
            float4 bb = *reinterpret_cast<const float4*>(&s_b2[c]);
            float* pr = P + r * AS + lane;   // PERM(c+e) = e*36 + lane
            pr[0]   = dx * inv * gg.x + bb.x;
            pr[36]  = dy * inv * gg.y + bb.y;
            pr[72]  = dz * inv * gg.z + bb.z;
            pr[108] = dw * inv * gg.w + bb.w;
        }
        for (int idx = tid; idx < 4096; idx += 512) {
            int row = idx >> 5, j = idx & 31;
            reinterpret_cast<float4*>(WB + row * WS)[j] =
                reinterpret_cast<const float4*>(Wf1)[idx];
        }
    }
    __syncthreads();

    // ---- GEMM2: H1 = gelu(Xn@Wf1 + bf1) -> P (permuted) ----
    gemm_mma_v(P, WB, acc, RM, CN, lane);
    __syncthreads();
    #pragma unroll
    for (int mt = 0; mt < 2; mt++) {
        int r = RM + mt * 16 + g;
        #pragma unroll
        for (int nt = 0; nt < 4; nt++) {
            int c = CN + nt * 8 + 2 * t4;
            int pcc = ((c & 3) * 36) + (c >> 2);
            float v0 = acc[mt][nt][0] + s_bf1[c];
            float v1 = acc[mt][nt][1] + s_bf1[c + 1];
            float v2 = acc[mt][nt][2] + s_bf1[c];
            float v3 = acc[mt][nt][3] + s_bf1[c + 1];
            const float k = 0.70710678118654752f;
            P[r * AS + pcc]            = 0.5f * v0 * (1.0f + erff(v0 * k));
            P[r * AS + pcc + 36]       = 0.5f * v1 * (1.0f + erff(v1 * k));
            P[(r + 8) * AS + pcc]      = 0.5f * v2 * (1.0f + erff(v2 * k));
            P[(r + 8) * AS + pcc + 36] = 0.5f * v3 * (1.0f + erff(v3 * k));
        }
    }
    for (int idx = tid; idx < 4096; idx += 512) {
        int row = idx >> 5, j = idx & 31;
        reinterpret_cast<float4*>(WB + row * WS)[j] =
            reinterpret_cast<const float4*>(Wf2)[idx];
    }
    __syncthreads();

    // ---- GEMM3: out = X + H1@Wf2 + bf2 ----
    gemm_mma_v(P, WB, acc, RM, CN, lane);
    #pragma unroll
    for (int mt = 0; mt < 2; mt++) {
        int r = RM + mt * 16 + g;
        #pragma unroll
        for (int nt = 0; nt < 4; nt++) {
            int c = CN + nt * 8 + 2 * t4;
            float2 q0 = *reinterpret_cast<const float2*>(&Q[r * QAS + c]);
            float2 q1 = *reinterpret_cast<const float2*>(&Q[(r + 8) * QAS + c]);
            float* o0 = out + (size_t)(R0 + r) * C + c;
            float* o1 = out + (size_t)(R0 + r + 8) * C + c;
            *reinterpret_cast<float2*>(o0) = make_float2(
                acc[mt][nt][0] + s_bf2[c] + q0.x,
                acc[mt][nt][1] + s_bf2[c + 1] + q0.y);
            *reinterpret_cast<float2*>(o1) = make_float2(
                acc[mt][nt][2] + s_bf2[c] + q1.x,
                acc[mt][nt][3] + s_bf2[c + 1] + q1.y);
        }
    }
}

// ---------------------------------------------------------------------------
extern "C" void kernel_launch(void* const* d_in, const int* in_sizes, int n_in,
                              void* d_out, int out_size) {
    const float* query = (const float*)d_in[0];
    const float* tgt   = (const float*)d_in[1];
    const float* ln1g  = (const float*)d_in[2];
    const float* ln1b  = (const float*)d_in[3];
    const float* ln2g  = (const float*)d_in[4];
    const float* ln2b  = (const float*)d_in[5];
    const float* Wq    = (const float*)d_in[6];
    const float* bq    = (const float*)d_in[7];
    const float* Wk    = (const float*)d_in[8];
    // d_in[9] = bk (cancels in softmax)
    const float* Wv    = (const float*)d_in[10];
    const float* bv    = (const float*)d_in[11];
    const float* Wp    = (const float*)d_in[12];
    const float* bp    = (const float*)d_in[13];
    const float* Wf1   = (const float*)d_in[14];
    const float* bf1   = (const float*)d_in[15];
    const float* Wf2   = (const float*)d_in[16];
    const float* bf2   = (const float*)d_in[17];

    int B = in_sizes[1] / (L * C);
    if (B > MAXB) B = MAXB;

    const int K1_SMEM = (72 * QS + 128 + 2 * L * TS + 64 * WSM + 72 * SPS) * sizeof(float);
    const int K2_SMEM = (128 * WS + 128 * AS + 128 * QAS + 1024 + 5 * 128) * sizeof(float);

    cudaFuncSetAttribute(attn_kernel, cudaFuncAttributeMaxDynamicSharedMemorySize, K1_SMEM);
    cudaFuncSetAttribute(ffn_kernel,  cudaFuncAttributeMaxDynamicSharedMemorySize, K2_SMEM);

    prep_kernel<<<64, 128>>>(query, ln1g, ln1b, Wq, bq, Wk);
    attn_kernel<<<(B + BPB - 1) / BPB, 512, K1_SMEM>>>(tgt, Wv, bv, B);

    int nrows = B * NTOK;
    ffn_kernel<<<(nrows + 127) / 128, 512, K2_SMEM>>>(query, ln2g, ln2b,
                                                      Wp, bp, Wf1, bf1, Wf2, bf2,
                                                      (float*)d_out, nrows);
}

// round 8
// speedup vs baseline: 1.1193x; 1.0285x over previous
#include <cuda_runtime.h>
#include <cuda_fp16.h>
#include <math.h>

// Problem constants
#define C 128
#define L 54            // 6*9
#define NTOK 8
#define MAXB 8192
#define BPB 16

// attn smem strides (floats) — R4 layout
#define TS   132        // s_tgt row stride
#define QS   132        // s_qkp row stride
#define WSM  132        // s_w row stride
#define SPS  20         // probs row stride
#define WVS  132        // s_wv row stride

// ffn strides (fp16 path)
#define PHS  68         // P half2 row stride
#define WFS  136        // WH half2 row stride (k-interleaved weights)
#define QAS  132        // Q f32 row stride

// Scratch
__device__ float g_qk[64 * 128];
__device__ float g_att[(size_t)MAXB * NTOK * C];

// ---------------------------------------------------------------------------
__device__ __forceinline__ unsigned smem_u32(const void* p) {
    unsigned a;
    asm("{ .reg .u64 t; cvta.to.shared.u64 t, %1; cvt.u32.u64 %0, t; }" : "=r"(a) : "l"(p));
    return a;
}

__device__ __forceinline__ void mma_tf32(float* acc, unsigned a0, unsigned a1,
                                         unsigned a2, unsigned a3,
                                         unsigned b0, unsigned b1) {
    asm volatile(
        "mma.sync.aligned.m16n8k8.row.col.f32.tf32.tf32.f32 "
        "{%0,%1,%2,%3},{%4,%5,%6,%7},{%8,%9},{%0,%1,%2,%3};\n"
        : "+f"(acc[0]), "+f"(acc[1]), "+f"(acc[2]), "+f"(acc[3])
        : "r"(a0), "r"(a1), "r"(a2), "r"(a3), "r"(b0), "r"(b1));
}

__device__ __forceinline__ void mma_f16(float* acc, unsigned a0, unsigned a1,
                                        unsigned a2, unsigned a3,
                                        unsigned b0, unsigned b1) {
    asm volatile(
        "mma.sync.aligned.m16n8k16.row.col.f32.f16.f16.f32 "
        "{%0,%1,%2,%3},{%4,%5,%6,%7},{%8,%9},{%0,%1,%2,%3};\n"
        : "+f"(acc[0]), "+f"(acc[1]), "+f"(acc[2]), "+f"(acc[3])
        : "r"(a0), "r"(a1), "r"(a2), "r"(a3), "r"(b0), "r"(b1));
}

__device__ __forceinline__ unsigned f2u(float x) { return __float_as_uint(x); }

__device__ __forceinline__ unsigned ph2(float a, float b) {
    __half2 h = __floats2half2_rn(a, b);
    return *reinterpret_cast<unsigned*>(&h);
}

// ---------------------------------------------------------------------------
// K0: prep (unchanged)
// ---------------------------------------------------------------------------
__global__ void prep_kernel(const float* __restrict__ q_in,
                            const float* __restrict__ g1, const float* __restrict__ b1,
                            const float* __restrict__ Wq, const float* __restrict__ bq,
                            const float* __restrict__ Wk) {
    __shared__ float s_qn[128];
    __shared__ float s_qh[16];
    __shared__ float s_red[8];
    int th = blockIdx.x, t = th >> 3, h = th & 7;
    int tid = threadIdx.x, lane = tid & 31, warp = tid >> 5;

    float x = q_in[t * 128 + tid];
    float s = x;
    #pragma unroll
    for (int o = 16; o; o >>= 1) s += __shfl_xor_sync(~0u, s, o);
    if (lane == 0) s_red[warp] = s;
    __syncthreads();
    float mean = (s_red[0] + s_red[1] + s_red[2] + s_red[3]) * (1.0f / 128.0f);
    float dx = x - mean;
    float sq = dx * dx;
    #pragma unroll
    for (int o = 16; o; o >>= 1) sq += __shfl_xor_sync(~0u, sq, o);
    __syncthreads();
    if (lane == 0) s_red[warp] = sq;
    __syncthreads();
    float var = (s_red[0] + s_red[1] + s_red[2] + s_red[3]) * (1.0f / 128.0f);
    float inv = rsqrtf(var + 1e-5f);
    s_qn[tid] = dx * inv * g1[tid] + b1[tid];
    __syncthreads();

    int j = tid >> 3, seg = tid & 7;
    int o = h * 16 + j;
    float p = 0.0f;
    #pragma unroll
    for (int i = 0; i < 16; i++) p += s_qn[seg * 16 + i] * Wq[(seg * 16 + i) * 128 + o];
    #pragma unroll
    for (int off = 4; off; off >>= 1) p += __shfl_xor_sync(~0u, p, off);
    if (seg == 0) s_qh[j] = p + bq[o];
    __syncthreads();

    float acc = 0.0f;
    const float* wk = Wk + tid * 128 + h * 16;
    #pragma unroll
    for (int jj = 0; jj < 16; jj++) acc += s_qh[jj] * wk[jj];
    g_qk[th * 128 + tid] = acc * 0.25f;
}

// region-row offset within region for li (0..8); li>=9 -> 0 (padding)
__device__ __forceinline__ int loff(int li) {
    if (li >= 9) return 0;
    int a = li / 3, b = li - a * 3;
    return a * 9 + b;
}

// ---------------------------------------------------------------------------
// K1: fused attention — R4 tf32 kernel verbatim (381.9us), BPB=16.
// ---------------------------------------------------------------------------
__global__ __launch_bounds__(512, 1)
void attn_kernel(const float* __restrict__ tgt,
                 const float* __restrict__ Wv, const float* __restrict__ bv,
                 int B) {
    extern __shared__ float sm[];
    float* s_qkp = sm;                    // 80*132
    float* s_wv  = s_qkp + 80 * QS;       // 128*132
    float* s_bv  = s_wv  + 128 * WVS;     // 128
    float* s_tgt = s_bv  + 128;           // 2 * 54*132
    float* s_w   = s_tgt + 2 * L * TS;    // 80*132
    float* s_p   = s_w   + 80 * WSM;      // 80*20

    int tid = threadIdx.x;
    int warp = tid >> 5, lane = tid & 31;
    int g = lane >> 2, t4 = lane & 3;

    // prologue: cp.async first batch into buffer 0
    {
        int b0 = blockIdx.x * BPB;
        if (b0 < B) {
            const float4* src = reinterpret_cast<const float4*>(tgt + (size_t)b0 * L * C);
            for (int idx = tid; idx < L * 32; idx += 512) {
                int row = idx >> 5, j = idx & 31;
                unsigned dst = smem_u32(s_tgt + row * TS + j * 4);
                asm volatile("cp.async.ca.shared.global [%0], [%1], 16;\n"
                             :: "r"(dst), "l"(src + idx));
            }
        }
        asm volatile("cp.async.commit_group;\n");
    }

    // stage qk permuted (region-major rows)
    for (int idx = tid; idx < 64 * 128; idx += 512) {
        int tr = idx >> 7, c = idx & 127;
        int t = tr >> 3, h = tr & 7;
        int pos = t + (t == 1) - (t == 2);
        s_qkp[(pos * 8 + h) * QS + c] = g_qk[idx];
    }
    for (int i = 64 * QS + tid; i < 80 * QS; i += 512) s_qkp[i] = 0.0f;
    for (int i = tid; i < 80 * SPS; i += 512) s_p[i] = 0.0f;
    for (int idx = tid; idx < 16384; idx += 512) {
        int c = idx >> 7, o = idx & 127;
        s_wv[c * WVS + o] = Wv[idx];
    }
    if (tid < 128) s_bv[tid] = bv[tid];

    // ---- per-warp job parameters (static across batches) ----
    bool okD = warp < 12;
    int rD  = warp >> 1, nhD = warp & 1;
    int mbD = (rD < 2) ? rD * 16 : 32 + (rD - 2) * 8;
    int blD = (rD / 3) * 27 + (rD % 3) * 3;
    int liD = nhD * 8 + g;
    int lD  = blD + loff(liD);
    int lW0 = blD + loff(t4);
    int lW1 = blD + loff(t4 + 4);
    int lW2 = blD + loff(t4 + 8);
    int lW3 = blD + loff(t4 + 12);
    int hV = warp >> 1, nhV = warp & 1;
    int o0 = hV * 16 + nhV * 8;

    __syncthreads();

    for (int bi = 0; bi < BPB; bi++) {
        int b = blockIdx.x * BPB + bi;
        if (b >= B) break;

        float* cur = s_tgt + (bi & 1) * (L * TS);
        float* nxt = s_tgt + ((bi + 1) & 1) * (L * TS);

        int nb = b + 1;
        if (bi + 1 < BPB && nb < B) {
            const float4* src = reinterpret_cast<const float4*>(tgt + (size_t)nb * L * C);
            for (int idx = tid; idx < L * 32; idx += 512) {
                int row = idx >> 5, j = idx & 31;
                unsigned dst = smem_u32(nxt + row * TS + j * 4);
                asm volatile("cp.async.ca.shared.global [%0], [%1], 16;\n"
                             :: "r"(dst), "l"(src + idx));
            }
        }
        asm volatile("cp.async.commit_group;\n");
        asm volatile("cp.async.wait_group 1;\n");
        __syncthreads();

        // ---- D: dots via mma ----
        if (okD) {
            float acc[4] = {0.f, 0.f, 0.f, 0.f};
            const float* Brow = cur + lD * TS;
            const float* Arow0 = s_qkp + (mbD + g) * QS;
            const float* Arow1 = s_qkp + (mbD + g + 8) * QS;
            #pragma unroll
            for (int k0 = 0; k0 < 128; k0 += 8) {
                int kr = k0 + t4;
                mma_tf32(acc,
                         f2u(Arow0[kr]), f2u(Arow1[kr]),
                         f2u(Arow0[kr + 4]), f2u(Arow1[kr + 4]),
                         f2u(Brow[kr]), f2u(Brow[kr + 4]));
            }
            int li0 = nhD * 8 + 2 * t4;
            if (li0 < 8) {
                *reinterpret_cast<float2*>(&s_p[(mbD + g) * SPS + li0]) =
                    make_float2(acc[0], acc[1]);
                if (rD < 2)
                    *reinterpret_cast<float2*>(&s_p[(mbD + g + 8) * SPS + li0]) =
                        make_float2(acc[2], acc[3]);
            } else if (li0 == 8) {
                s_p[(mbD + g) * SPS + 8] = acc[0];
                if (rD < 2) s_p[(mbD + g + 8) * SPS + 8] = acc[2];
            }
        }
        __syncthreads();

        // ---- softmax over 9 per row (64 rows) ----
        if (tid < 64) {
            float* pp = s_p + tid * SPS;
            float m = -1e30f;
            #pragma unroll
            for (int li = 0; li < 9; li++) m = fmaxf(m, pp[li]);
            float e[9]; float ssum = 0.0f;
            #pragma unroll
            for (int li = 0; li < 9; li++) { e[li] = expf(pp[li] - m); ssum += e[li]; }
            float invs = 1.0f / ssum;
            #pragma unroll
            for (int li = 0; li < 9; li++) pp[li] = e[li] * invs;
        }
        __syncthreads();

        // ---- W: weighted sum via mma ----
        if (okD) {
            const float* Ar0 = s_p + (mbD + g) * SPS;
            const float* Ar1 = s_p + (mbD + g + 8) * SPS;
            unsigned a0 = f2u(Ar0[t4]),      a1 = f2u(Ar1[t4]);
            unsigned a2 = f2u(Ar0[t4 + 4]),  a3 = f2u(Ar1[t4 + 4]);
            unsigned a4 = f2u(Ar0[t4 + 8]),  a5 = f2u(Ar1[t4 + 8]);
            unsigned a6 = f2u(Ar0[t4 + 12]), a7 = f2u(Ar1[t4 + 12]);
            int p0 = mbD + g;
            int pos0 = p0 >> 3;
            int t0 = pos0 + (pos0 == 1) - (pos0 == 2);
            int v0 = (p0 & 7) * 8 + t0;
            int p1 = mbD + g + 8;
            int pos1 = p1 >> 3;
            int t1 = pos1 + (pos1 == 1) - (pos1 == 2);
            int v1 = (p1 & 7) * 8 + t1;

            #pragma unroll
            for (int nt = 0; nt < 8; nt++) {
                int c0 = nhD * 64 + nt * 8;
                float acc[4] = {0.f, 0.f, 0.f, 0.f};
                mma_tf32(acc, a0, a1, a2, a3,
                         f2u(cur[lW0 * TS + c0 + g]), f2u(cur[lW1 * TS + c0 + g]));
                mma_tf32(acc, a4, a5, a6, a7,
                         f2u(cur[lW2 * TS + c0 + g]), f2u(cur[lW3 * TS + c0 + g]));
                int cc = c0 + 2 * t4;
                *reinterpret_cast<float2*>(&s_w[v0 * WSM + cc]) = make_float2(acc[0], acc[1]);
                if (rD < 2)
                    *reinterpret_cast<float2*>(&s_w[v1 * WSM + cc]) = make_float2(acc[2], acc[3]);
            }
        }
        __syncthreads();

        // ---- V: att[t, o] = w[vrow=hV*8+t] . Wv[:, o] + bv ----
        {
            float acc[4] = {0.f, 0.f, 0.f, 0.f};
            const float* Ar0 = s_w + (hV * 8 + g) * WSM;
            const float* Ar1 = s_w + (hV * 8 + g + 8) * WSM;
            #pragma unroll
            for (int k0 = 0; k0 < 128; k0 += 8) {
                int kr = k0 + t4;
                mma_tf32(acc,
                         f2u(Ar0[kr]), f2u(Ar1[kr]),
                         f2u(Ar0[kr + 4]), f2u(Ar1[kr + 4]),
                         f2u(s_wv[kr * WVS + o0 + g]),
                         f2u(s_wv[(kr + 4) * WVS + o0 + g]));
            }
            int o = o0 + 2 * t4;
            float* op = g_att + ((size_t)b * NTOK + g) * C + o;
            *reinterpret_cast<float2*>(op) =
                make_float2(acc[0] + s_bv[o], acc[1] + s_bv[o + 1]);
        }
        __syncthreads();
    }
}

// ---------------------------------------------------------------------------
// K2: FFN chain, fp16 mma. P half2 natural, weights half2 k-interleaved.
// ---------------------------------------------------------------------------
__device__ __forceinline__ void gemm_mma_h(const unsigned* __restrict__ P,
                                           const unsigned* __restrict__ WH,
                                           float acc[2][4][4], int RM, int CN, int lane) {
    #pragma unroll
    for (int mt = 0; mt < 2; mt++)
        #pragma unroll
        for (int nt = 0; nt < 4; nt++)
            #pragma unroll
            for (int i = 0; i < 4; i++) acc[mt][nt][i] = 0.0f;

    int g = lane >> 2, t4 = lane & 3;
    const unsigned* A0 = P + (RM + g) * PHS;
    const unsigned* A1 = P + (RM + g + 8) * PHS;
    const unsigned* A2 = P + (RM + 16 + g) * PHS;
    const unsigned* A3 = P + (RM + 16 + g + 8) * PHS;

    #pragma unroll
    for (int m = 0; m < 8; m++) {
        int hp = 8 * m + t4;
        unsigned a00 = A0[hp], a01 = A1[hp], a02 = A0[hp + 4], a03 = A1[hp + 4];
        unsigned a10 = A2[hp], a11 = A3[hp], a12 = A2[hp + 4], a13 = A3[hp + 4];
        const unsigned* W0 = WH + (8 * m + t4) * WFS + CN + g;
        const unsigned* W1 = WH + (8 * m + 4 + t4) * WFS + CN + g;
        #pragma unroll
        for (int nt = 0; nt < 4; nt++) {
            unsigned b0 = W0[nt * 8];
            unsigned b1 = W1[nt * 8];
            mma_f16(acc[0][nt], a00, a01, a02, a03, b0, b1);
            mma_f16(acc[1][nt], a10, a11, a12, a13, b0, b1);
        }
    }
}

__global__ __launch_bounds__(512, 1)
void ffn_kernel(const float* __restrict__ query,
                const float* __restrict__ g2, const float* __restrict__ b2,
                const float* __restrict__ Wp, const float* __restrict__ bp,
                const float* __restrict__ Wf1, const float* __restrict__ bf1,
                const float* __restrict__ Wf2, const float* __restrict__ bf2,
                float* __restrict__ out, int nrows) {
    extern __shared__ float sm[];
    unsigned* WH = reinterpret_cast<unsigned*>(sm);         // 64*136 half2
    unsigned* P  = WH + 64 * WFS;                           // 128*68 half2
    float* Q     = reinterpret_cast<float*>(P + 128 * PHS); // 128*132 f32
    float* s_qr  = Q + 128 * QAS;                           // 1024
    float* s_bp  = s_qr + 1024;
    float* s_bf1 = s_bp + 128;
    float* s_bf2 = s_bf1 + 128;
    float* s_g2  = s_bf2 + 128;
    float* s_b2  = s_g2 + 128;

    int tid = threadIdx.x;
    int warp = tid >> 5, lane = tid & 31;
    int g = lane >> 2, t4 = lane & 3;
    int RM = (warp >> 2) * 32, CN = (warp & 3) * 32;
    int R0 = blockIdx.x * 128;
    if (R0 >= nrows) return;

    // stage: P = att tile (half2), WH = Wp (k-interleaved half2), misc
    {
        const float4* src = reinterpret_cast<const float4*>(g_att + (size_t)R0 * C);
        for (int idx = tid; idx < 4096; idx += 512) {
            int row = idx >> 5, j = idx & 31;
            float4 v = src[idx];
            P[row * PHS + 2 * j]     = ph2(v.x, v.y);
            P[row * PHS + 2 * j + 1] = ph2(v.z, v.w);
        }
        for (int idx = tid; idx < 8192; idx += 512) {
            int m = idx >> 7, c = idx & 127;
            WH[m * WFS + c] = ph2(Wp[2 * m * 128 + c], Wp[(2 * m + 1) * 128 + c]);
        }
        for (int i = tid; i < 1024; i += 512) s_qr[i] = query[i];
        if (tid < 128) {
            s_bp[tid] = bp[tid]; s_bf1[tid] = bf1[tid]; s_bf2[tid] = bf2[tid];
            s_g2[tid] = g2[tid]; s_b2[tid] = b2[tid];
        }
    }
    __syncthreads();

    float acc[2][4][4];

    // ---- GEMM1: X = att@Wp + bp + shortcut -> Q (f32) ----
    gemm_mma_h(P, WH, acc, RM, CN, lane);
    #pragma unroll
    for (int mt = 0; mt < 2; mt++) {
        int r = RM + mt * 16 + g;
        #pragma unroll
        for (int nt = 0; nt < 4; nt++) {
            int c = CN + nt * 8 + 2 * t4;
            int tq = r & 7;
            *reinterpret_cast<float2*>(&Q[r * QAS + c]) = make_float2(
                acc[mt][nt][0] + s_bp[c]     + s_qr[tq * 128 + c],
                acc[mt][nt][1] + s_bp[c + 1] + s_qr[tq * 128 + c + 1]);
            *reinterpret_cast<float2*>(&Q[(r + 8) * QAS + c]) = make_float2(
                acc[mt][nt][2] + s_bp[c]     + s_qr[tq * 128 + c],
                acc[mt][nt][3] + s_bp[c + 1] + s_qr[tq * 128 + c + 1]);
        }
    }
    __syncthreads();

    // ---- LN rows Q -> P (half2); load Wf1 -> WH ----
    {
        for (int r = warp; r < 128; r += 16) {
            float4 v = *reinterpret_cast<const float4*>(&Q[r * QAS + lane * 4]);
            float s = v.x + v.y + v.z + v.w;
            #pragma unroll
            for (int o = 16; o; o >>= 1) s += __shfl_xor_sync(~0u, s, o);
            float mean = s * (1.0f / 128.0f);
            float dx = v.x - mean, dy = v.y - mean, dz = v.z - mean, dw = v.w - mean;
            float sq = dx * dx + dy * dy + dz * dz + dw * dw;
            #pragma unroll
            for (int o = 16; o; o >>= 1) sq += __shfl_xor_sync(~0u, sq, o);
            float inv = rsqrtf(sq * (1.0f / 128.0f) + 1e-5f);
            int c = lane * 4;
            float4 gg = *reinterpret_cast<const float4*>(&s_g2[c]);
            float4 bb = *reinterpret_cast<const float4*>(&s_b2[c]);
            P[r * PHS + 2 * lane]     = ph2(dx * inv * gg.x + bb.x, dy * inv * gg.y + bb.y);
            P[r * PHS + 2 * lane + 1] = ph2(dz * inv * gg.z + bb.z, dw * inv * gg.w + bb.w);
        }
        for (int idx = tid; idx < 8192; idx += 512) {
            int m = idx >> 7, c = idx & 127;
            WH[m * WFS + c] = ph2(Wf1[2 * m * 128 + c], Wf1[(2 * m + 1) * 128 + c]);
        }
    }
    __syncthreads();

    // ---- GEMM2: H1 = gelu(Xn@Wf1 + bf1) -> P (half2) ----
    gemm_mma_h(P, WH, acc, RM, CN, lane);
    __syncthreads();
    #pragma unroll
    for (int mt = 0; mt < 2; mt++) {
        int r = RM + mt * 16 + g;
        #pragma unroll
        for (int nt = 0; nt < 4; nt++) {
            int c = CN + nt * 8 + 2 * t4;
            float v0 = acc[mt][nt][0] + s_bf1[c];
            float v1 = acc[mt][nt][1] + s_bf1[c + 1];
            float v2 = acc[mt][nt][2] + s_bf1[c];
            float v3 = acc[mt][nt][3] + s_bf1[c + 1];
            const float k = 0.70710678118654752f;
            P[r * PHS + (c >> 1)] =
                ph2(0.5f * v0 * (1.0f + erff(v0 * k)), 0.5f * v1 * (1.0f + erff(v1 * k)));
            P[(r + 8) * PHS + (c >> 1)] =
                ph2(0.5f * v2 * (1.0f + erff(v2 * k)), 0.5f * v3 * (1.0f + erff(v3 * k)));
        }
    }
    for (int idx = tid; idx < 8192; idx += 512) {
        int m = idx >> 7, c = idx & 127;
        WH[m * WFS + c] = ph2(Wf2[2 * m * 128 + c], Wf2[(2 * m + 1) * 128 + c]);
    }
    __syncthreads();

    // ---- GEMM3: out = X + H1@Wf2 + bf2 ----
    gemm_mma_h(P, WH, acc, RM, CN, lane);
    #pragma unroll
    for (int mt = 0; mt < 2; mt++) {
        int r = RM + mt * 16 + g;
        #pragma unroll
        for (int nt = 0; nt < 4; nt++) {
            int c = CN + nt * 8 + 2 * t4;
            float2 q0 = *reinterpret_cast<const float2*>(&Q[r * QAS + c]);
            float2 q1 = *reinterpret_cast<const float2*>(&Q[(r + 8) * QAS + c]);
            float* o0 = out + (size_t)(R0 + r) * C + c;
            float* o1 = out + (size_t)(R0 + r + 8) * C + c;
            *reinterpret_cast<float2*>(o0) = make_float2(
                acc[mt][nt][0] + s_bf2[c] + q0.x,
                acc[mt][nt][1] + s_bf2[c + 1] + q0.y);
            *reinterpret_cast<float2*>(o1) = make_float2(
                acc[mt][nt][2] + s_bf2[c] + q1.x,
                acc[mt][nt][3] + s_bf2[c + 1] + q1.y);
        }
    }
}

// ---------------------------------------------------------------------------
extern "C" void kernel_launch(void* const* d_in, const int* in_sizes, int n_in,
                              void* d_out, int out_size) {
    const float* query = (const float*)d_in[0];
    const float* tgt   = (const float*)d_in[1];
    const float* ln1g  = (const float*)d_in[2];
    const float* ln1b  = (const float*)d_in[3];
    const float* ln2g  = (const float*)d_in[4];
    const float* ln2b  = (const float*)d_in[5];
    const float* Wq    = (const float*)d_in[6];
    const float* bq    = (const float*)d_in[7];
    const float* Wk    = (const float*)d_in[8];
    // d_in[9] = bk (cancels in softmax)
    const float* Wv    = (const float*)d_in[10];
    const float* bv    = (const float*)d_in[11];
    const float* Wp    = (const float*)d_in[12];
    const float* bp    = (const float*)d_in[13];
    const float* Wf1   = (const float*)d_in[14];
    const float* bf1   = (const float*)d_in[15];
    const float* Wf2   = (const float*)d_in[16];
    const float* bf2   = (const float*)d_in[17];

    int B = in_sizes[1] / (L * C);
    if (B > MAXB) B = MAXB;

    const int K1_SMEM = (80 * QS + 128 * WVS + 128 + 2 * L * TS + 80 * WSM + 80 * SPS)
                        * sizeof(float);
    const int K2_SMEM = (64 * WFS + 128 * PHS + 128 * QAS + 1024 + 5 * 128) * sizeof(float);

    cudaFuncSetAttribute(attn_kernel, cudaFuncAttributeMaxDynamicSharedMemorySize, K1_SMEM);
    cudaFuncSetAttribute(ffn_kernel,  cudaFuncAttributeMaxDynamicSharedMemorySize, K2_SMEM);

    prep_kernel<<<64, 128>>>(query, ln1g, ln1b, Wq, bq, Wk);
    attn_kernel<<<(B + BPB - 1) / BPB, 512, K1_SMEM>>>(tgt, Wv, bv, B);

    int nrows = B * NTOK;
    ffn_kernel<<<(nrows + 127) / 128, 512, K2_SMEM>>>(query, ln2g, ln2b,
                                                      Wp, bp, Wf1, bf1, Wf2, bf2,
                                                      (float*)d_out, nrows);
}

// round 9
// speedup vs baseline: 1.1664x; 1.0422x over previous
#include <cuda_runtime.h>
#include <cuda_fp16.h>
#include <math.h>

// Problem constants
#define C 128
#define L 54            // 6*9
#define NTOK 8
#define MAXB 8192
#define BPB 8

// attn smem strides (floats) — R4 layout
#define TS   132        // s_tgt row stride
#define QS   132        // s_qkp row stride
#define WSM  132        // s_w row stride
#define SPS  20         // probs row stride
#define WVS  132        // s_wv row stride

// ffn strides (fp16 path)
#define PHS  68         // P half2 row stride
#define WFS  136        // WH half2 row stride (k-interleaved weights)
#define QAS  132        // Q f32 row stride

// Scratch
__device__ float g_qk[64 * 128];
__device__ float g_att[(size_t)MAXB * NTOK * C];

// ---------------------------------------------------------------------------
__device__ __forceinline__ unsigned smem_u32(const void* p) {
    unsigned a;
    asm("{ .reg .u64 t; cvta.to.shared.u64 t, %1; cvt.u32.u64 %0, t; }" : "=r"(a) : "l"(p));
    return a;
}

__device__ __forceinline__ void mma_tf32(float* acc, unsigned a0, unsigned a1,
                                         unsigned a2, unsigned a3,
                                         unsigned b0, unsigned b1) {
    asm volatile(
        "mma.sync.aligned.m16n8k8.row.col.f32.tf32.tf32.f32 "
        "{%0,%1,%2,%3},{%4,%5,%6,%7},{%8,%9},{%0,%1,%2,%3};\n"
        : "+f"(acc[0]), "+f"(acc[1]), "+f"(acc[2]), "+f"(acc[3])
        : "r"(a0), "r"(a1), "r"(a2), "r"(a3), "r"(b0), "r"(b1));
}

__device__ __forceinline__ void mma_f16(float* acc, unsigned a0, unsigned a1,
                                        unsigned a2, unsigned a3,
                                        unsigned b0, unsigned b1) {
    asm volatile(
        "mma.sync.aligned.m16n8k16.row.col.f32.f16.f16.f32 "
        "{%0,%1,%2,%3},{%4,%5,%6,%7},{%8,%9},{%0,%1,%2,%3};\n"
        : "+f"(acc[0]), "+f"(acc[1]), "+f"(acc[2]), "+f"(acc[3])
        : "r"(a0), "r"(a1), "r"(a2), "r"(a3), "r"(b0), "r"(b1));
}

__device__ __forceinline__ unsigned f2u(float x) { return __float_as_uint(x); }

__device__ __forceinline__ unsigned ph2(float a, float b) {
    __half2 h = __floats2half2_rn(a, b);
    return *reinterpret_cast<unsigned*>(&h);
}

// ---------------------------------------------------------------------------
// K0: prep (unchanged)
// ---------------------------------------------------------------------------
__global__ void prep_kernel(const float* __restrict__ q_in,
                            const float* __restrict__ g1, const float* __restrict__ b1,
                            const float* __restrict__ Wq, const float* __restrict__ bq,
                            const float* __restrict__ Wk) {
    __shared__ float s_qn[128];
    __shared__ float s_qh[16];
    __shared__ float s_red[8];
    int th = blockIdx.x, t = th >> 3, h = th & 7;
    int tid = threadIdx.x, lane = tid & 31, warp = tid >> 5;

    float x = q_in[t * 128 + tid];
    float s = x;
    #pragma unroll
    for (int o = 16; o; o >>= 1) s += __shfl_xor_sync(~0u, s, o);
    if (lane == 0) s_red[warp] = s;
    __syncthreads();
    float mean = (s_red[0] + s_red[1] + s_red[2] + s_red[3]) * (1.0f / 128.0f);
    float dx = x - mean;
    float sq = dx * dx;
    #pragma unroll
    for (int o = 16; o; o >>= 1) sq += __shfl_xor_sync(~0u, sq, o);
    __syncthreads();
    if (lane == 0) s_red[warp] = sq;
    __syncthreads();
    float var = (s_red[0] + s_red[1] + s_red[2] + s_red[3]) * (1.0f / 128.0f);
    float inv = rsqrtf(var + 1e-5f);
    s_qn[tid] = dx * inv * g1[tid] + b1[tid];
    __syncthreads();

    int j = tid >> 3, seg = tid & 7;
    int o = h * 16 + j;
    float p = 0.0f;
    #pragma unroll
    for (int i = 0; i < 16; i++) p += s_qn[seg * 16 + i] * Wq[(seg * 16 + i) * 128 + o];
    #pragma unroll
    for (int off = 4; off; off >>= 1) p += __shfl_xor_sync(~0u, p, off);
    if (seg == 0) s_qh[j] = p + bq[o];
    __syncthreads();

    float acc = 0.0f;
    const float* wk = Wk + tid * 128 + h * 16;
    #pragma unroll
    for (int jj = 0; jj < 16; jj++) acc += s_qh[jj] * wk[jj];
    g_qk[th * 128 + tid] = acc * 0.25f;
}

// region-row offset within region for li (0..8); li>=9 -> 0 (padding)
__device__ __forceinline__ int loff(int li) {
    if (li >= 9) return 0;
    int a = li / 3, b = li - a * 3;
    return a * 9 + b;
}

// ---------------------------------------------------------------------------
// K1: fused attention — R4 tf32 kernel, BPB=8, split accumulator chains.
// ---------------------------------------------------------------------------
__global__ __launch_bounds__(512, 1)
void attn_kernel(const float* __restrict__ tgt,
                 const float* __restrict__ Wv, const float* __restrict__ bv,
                 int B) {
    extern __shared__ float sm[];
    float* s_qkp = sm;                    // 80*132
    float* s_wv  = s_qkp + 80 * QS;       // 128*132
    float* s_bv  = s_wv  + 128 * WVS;     // 128
    float* s_tgt = s_bv  + 128;           // 2 * 54*132
    float* s_w   = s_tgt + 2 * L * TS;    // 80*132
    float* s_p   = s_w   + 80 * WSM;      // 80*20

    int tid = threadIdx.x;
    int warp = tid >> 5, lane = tid & 31;
    int g = lane >> 2, t4 = lane & 3;

    // prologue: cp.async first batch into buffer 0
    {
        int b0 = blockIdx.x * BPB;
        if (b0 < B) {
            const float4* src = reinterpret_cast<const float4*>(tgt + (size_t)b0 * L * C);
            for (int idx = tid; idx < L * 32; idx += 512) {
                int row = idx >> 5, j = idx & 31;
                unsigned dst = smem_u32(s_tgt + row * TS + j * 4);
                asm volatile("cp.async.ca.shared.global [%0], [%1], 16;\n"
                             :: "r"(dst), "l"(src + idx));
            }
        }
        asm volatile("cp.async.commit_group;\n");
    }

    // stage qk permuted (region-major rows)
    for (int idx = tid; idx < 64 * 128; idx += 512) {
        int tr = idx >> 7, c = idx & 127;
        int t = tr >> 3, h = tr & 7;
        int pos = t + (t == 1) - (t == 2);
        s_qkp[(pos * 8 + h) * QS + c] = g_qk[idx];
    }
    for (int i = 64 * QS + tid; i < 80 * QS; i += 512) s_qkp[i] = 0.0f;
    for (int i = tid; i < 80 * SPS; i += 512) s_p[i] = 0.0f;
    for (int idx = tid; idx < 16384; idx += 512) {
        int c = idx >> 7, o = idx & 127;
        s_wv[c * WVS + o] = Wv[idx];
    }
    if (tid < 128) s_bv[tid] = bv[tid];

    // ---- per-warp job parameters (static across batches) ----
    bool okD = warp < 12;
    int rD  = warp >> 1, nhD = warp & 1;
    int mbD = (rD < 2) ? rD * 16 : 32 + (rD - 2) * 8;
    int blD = (rD / 3) * 27 + (rD % 3) * 3;
    int liD = nhD * 8 + g;
    int lD  = blD + loff(liD);
    int lW0 = blD + loff(t4);
    int lW1 = blD + loff(t4 + 4);
    int lW2 = blD + loff(t4 + 8);
    int lW3 = blD + loff(t4 + 12);
    int hV = warp >> 1, nhV = warp & 1;
    int o0 = hV * 16 + nhV * 8;

    __syncthreads();

    for (int bi = 0; bi < BPB; bi++) {
        int b = blockIdx.x * BPB + bi;
        if (b >= B) break;

        float* cur = s_tgt + (bi & 1) * (L * TS);
        float* nxt = s_tgt + ((bi + 1) & 1) * (L * TS);

        int nb = b + 1;
        if (bi + 1 < BPB && nb < B) {
            const float4* src = reinterpret_cast<const float4*>(tgt + (size_t)nb * L * C);
            for (int idx = tid; idx < L * 32; idx += 512) {
                int row = idx >> 5, j = idx & 31;
                unsigned dst = smem_u32(nxt + row * TS + j * 4);
                asm volatile("cp.async.ca.shared.global [%0], [%1], 16;\n"
                             :: "r"(dst), "l"(src + idx));
            }
        }
        asm volatile("cp.async.commit_group;\n");
        asm volatile("cp.async.wait_group 1;\n");
        __syncthreads();

        // ---- D: dots via mma (two independent 8-deep chains) ----
        if (okD) {
            float accA[4] = {0.f, 0.f, 0.f, 0.f};
            float accB[4] = {0.f, 0.f, 0.f, 0.f};
            const float* Brow = cur + lD * TS;
            const float* Arow0 = s_qkp + (mbD + g) * QS;
            const float* Arow1 = s_qkp + (mbD + g + 8) * QS;
            #pragma unroll
            for (int k0 = 0; k0 < 64; k0 += 8) {
                int kr = k0 + t4;
                mma_tf32(accA,
                         f2u(Arow0[kr]), f2u(Arow1[kr]),
                         f2u(Arow0[kr + 4]), f2u(Arow1[kr + 4]),
                         f2u(Brow[kr]), f2u(Brow[kr + 4]));
                int ks = kr + 64;
                mma_tf32(accB,
                         f2u(Arow0[ks]), f2u(Arow1[ks]),
                         f2u(Arow0[ks + 4]), f2u(Arow1[ks + 4]),
                         f2u(Brow[ks]), f2u(Brow[ks + 4]));
            }
            float acc[4];
            #pragma unroll
            for (int i = 0; i < 4; i++) acc[i] = accA[i] + accB[i];
            int li0 = nhD * 8 + 2 * t4;
            if (li0 < 8) {
                *reinterpret_cast<float2*>(&s_p[(mbD + g) * SPS + li0]) =
                    make_float2(acc[0], acc[1]);
                if (rD < 2)
                    *reinterpret_cast<float2*>(&s_p[(mbD + g + 8) * SPS + li0]) =
                        make_float2(acc[2], acc[3]);
            } else if (li0 == 8) {
                s_p[(mbD + g) * SPS + 8] = acc[0];
                if (rD < 2) s_p[(mbD + g + 8) * SPS + 8] = acc[2];
            }
        }
        __syncthreads();

        // ---- softmax over 9 per row (64 rows) ----
        if (tid < 64) {
            float* pp = s_p + tid * SPS;
            float m = -1e30f;
            #pragma unroll
            for (int li = 0; li < 9; li++) m = fmaxf(m, pp[li]);
            float e[9]; float ssum = 0.0f;
            #pragma unroll
            for (int li = 0; li < 9; li++) { e[li] = expf(pp[li] - m); ssum += e[li]; }
            float invs = 1.0f / ssum;
            #pragma unroll
            for (int li = 0; li < 9; li++) pp[li] = e[li] * invs;
        }
        __syncthreads();

        // ---- W: weighted sum via mma (two independent chains) ----
        if (okD) {
            const float* Ar0 = s_p + (mbD + g) * SPS;
            const float* Ar1 = s_p + (mbD + g + 8) * SPS;
            unsigned a0 = f2u(Ar0[t4]),      a1 = f2u(Ar1[t4]);
            unsigned a2 = f2u(Ar0[t4 + 4]),  a3 = f2u(Ar1[t4 + 4]);
            unsigned a4 = f2u(Ar0[t4 + 8]),  a5 = f2u(Ar1[t4 + 8]);
            unsigned a6 = f2u(Ar0[t4 + 12]), a7 = f2u(Ar1[t4 + 12]);
            int p0 = mbD + g;
            int pos0 = p0 >> 3;
            int t0 = pos0 + (pos0 == 1) - (pos0 == 2);
            int v0 = (p0 & 7) * 8 + t0;
            int p1 = mbD + g + 8;
            int pos1 = p1 >> 3;
            int t1 = pos1 + (pos1 == 1) - (pos1 == 2);
            int v1 = (p1 & 7) * 8 + t1;

            #pragma unroll
            for (int nt = 0; nt < 8; nt++) {
                int c0 = nhD * 64 + nt * 8;
                float accA[4] = {0.f, 0.f, 0.f, 0.f};
                float accB[4] = {0.f, 0.f, 0.f, 0.f};
                mma_tf32(accA, a0, a1, a2, a3,
                         f2u(cur[lW0 * TS + c0 + g]), f2u(cur[lW1 * TS + c0 + g]));
                mma_tf32(accB, a4, a5, a6, a7,
                         f2u(cur[lW2 * TS + c0 + g]), f2u(cur[lW3 * TS + c0 + g]));
                int cc = c0 + 2 * t4;
                *reinterpret_cast<float2*>(&s_w[v0 * WSM + cc]) =
                    make_float2(accA[0] + accB[0], accA[1] + accB[1]);
                if (rD < 2)
                    *reinterpret_cast<float2*>(&s_w[v1 * WSM + cc]) =
                        make_float2(accA[2] + accB[2], accA[3] + accB[3]);
            }
        }
        __syncthreads();

        // ---- V: att[t, o] = w[vrow=hV*8+t] . Wv[:, o] + bv (split chains) ----
        {
            float accA[4] = {0.f, 0.f, 0.f, 0.f};
            float accB[4] = {0.f, 0.f, 0.f, 0.f};
            const float* Ar0 = s_w + (hV * 8 + g) * WSM;
            const float* Ar1 = s_w + (hV * 8 + g + 8) * WSM;
            #pragma unroll
            for (int k0 = 0; k0 < 64; k0 += 8) {
                int kr = k0 + t4;
                mma_tf32(accA,
                         f2u(Ar0[kr]), f2u(Ar1[kr]),
                         f2u(Ar0[kr + 4]), f2u(Ar1[kr + 4]),
                         f2u(s_wv[kr * WVS + o0 + g]),
                         f2u(s_wv[(kr + 4) * WVS + o0 + g]));
                int ks = kr + 64;
                mma_tf32(accB,
                         f2u(Ar0[ks]), f2u(Ar1[ks]),
                         f2u(Ar0[ks + 4]), f2u(Ar1[ks + 4]),
                         f2u(s_wv[ks * WVS + o0 + g]),
                         f2u(s_wv[(ks + 4) * WVS + o0 + g]));
            }
            int o = o0 + 2 * t4;
            float* op = g_att + ((size_t)b * NTOK + g) * C + o;
            *reinterpret_cast<float2*>(op) =
                make_float2(accA[0] + accB[0] + s_bv[o],
                            accA[1] + accB[1] + s_bv[o + 1]);
        }
        __syncthreads();
    }
}

// ---------------------------------------------------------------------------
// K2: FFN chain, fp16 mma (R8-verified). P half2 natural, weights k-interleaved.
// ---------------------------------------------------------------------------
__device__ __forceinline__ void gemm_mma_h(const unsigned* __restrict__ P,
                                           const unsigned* __restrict__ WH,
                                           float acc[2][4][4], int RM, int CN, int lane) {
    #pragma unroll
    for (int mt = 0; mt < 2; mt++)
        #pragma unroll
        for (int nt = 0; nt < 4; nt++)
            #pragma unroll
            for (int i = 0; i < 4; i++) acc[mt][nt][i] = 0.0f;

    int g = lane >> 2, t4 = lane & 3;
    const unsigned* A0 = P + (RM + g) * PHS;
    const unsigned* A1 = P + (RM + g + 8) * PHS;
    const unsigned* A2 = P + (RM + 16 + g) * PHS;
    const unsigned* A3 = P + (RM + 16 + g + 8) * PHS;

    #pragma unroll
    for (int m = 0; m < 8; m++) {
        int hp = 8 * m + t4;
        unsigned a00 = A0[hp], a01 = A1[hp], a02 = A0[hp + 4], a03 = A1[hp + 4];
        unsigned a10 = A2[hp], a11 = A3[hp], a12 = A2[hp + 4], a13 = A3[hp + 4];
        const unsigned* W0 = WH + (8 * m + t4) * WFS + CN + g;
        const unsigned* W1 = WH + (8 * m + 4 + t4) * WFS + CN + g;
        #pragma unroll
        for (int nt = 0; nt < 4; nt++) {
            unsigned b0 = W0[nt * 8];
            unsigned b1 = W1[nt * 8];
            mma_f16(acc[0][nt], a00, a01, a02, a03, b0, b1);
            mma_f16(acc[1][nt], a10, a11, a12, a13, b0, b1);
        }
    }
}

__global__ __launch_bounds__(512, 1)
void ffn_kernel(const float* __restrict__ query,
                const float* __restrict__ g2, const float* __restrict__ b2,
                const float* __restrict__ Wp, const float* __restrict__ bp,
                const float* __restrict__ Wf1, const float* __restrict__ bf1,
                const float* __restrict__ Wf2, const float* __restrict__ bf2,
                float* __restrict__ out, int nrows) {
    extern __shared__ float sm[];
    unsigned* WH = reinterpret_cast<unsigned*>(sm);         // 64*136 half2
    unsigned* P  = WH + 64 * WFS;                           // 128*68 half2
    float* Q     = reinterpret_cast<float*>(P + 128 * PHS); // 128*132 f32
    float* s_qr  = Q + 128 * QAS;                           // 1024
    float* s_bp  = s_qr + 1024;
    float* s_bf1 = s_bp + 128;
    float* s_bf2 = s_bf1 + 128;
    float* s_g2  = s_bf2 + 128;
    float* s_b2  = s_g2 + 128;

    int tid = threadIdx.x;
    int warp = tid >> 5, lane = tid & 31;
    int g = lane >> 2, t4 = lane & 3;
    int RM = (warp >> 2) * 32, CN = (warp & 3) * 32;
    int R0 = blockIdx.x * 128;
    if (R0 >= nrows) return;

    // stage: P = att tile (half2), WH = Wp (k-interleaved half2), misc
    {
        const float4* src = reinterpret_cast<const float4*>(g_att + (size_t)R0 * C);
        for (int idx = tid; idx < 4096; idx += 512) {
            int row = idx >> 5, j = idx & 31;
            float4 v = src[idx];
            P[row * PHS + 2 * j]     = ph2(v.x, v.y);
            P[row * PHS + 2 * j + 1] = ph2(v.z, v.w);
        }
        for (int idx = tid; idx < 8192; idx += 512) {
            int m = idx >> 7, c = idx & 127;
            WH[m * WFS + c] = ph2(Wp[2 * m * 128 + c], Wp[(2 * m + 1) * 128 + c]);
        }
        for (int i = tid; i < 1024; i += 512) s_qr[i] = query[i];
        if (tid < 128) {
            s_bp[tid] = bp[tid]; s_bf1[tid] = bf1[tid]; s_bf2[tid] = bf2[tid];
            s_g2[tid] = g2[tid]; s_b2[tid] = b2[tid];
        }
    }
    __syncthreads();

    float acc[2][4][4];

    // ---- GEMM1: X = att@Wp + bp + shortcut -> Q (f32) ----
    gemm_mma_h(P, WH, acc, RM, CN, lane);
    #pragma unroll
    for (int mt = 0; mt < 2; mt++) {
        int r = RM + mt * 16 + g;
        #pragma unroll
        for (int nt = 0; nt < 4; nt++) {
            int c = CN + nt * 8 + 2 * t4;
            int tq = r & 7;
            *reinterpret_cast<float2*>(&Q[r * QAS + c]) = make_float2(
                acc[mt][nt][0] + s_bp[c]     + s_qr[tq * 128 + c],
                acc[mt][nt][1] + s_bp[c + 1] + s_qr[tq * 128 + c + 1]);
            *reinterpret_cast<float2*>(&Q[(r + 8) * QAS + c]) = make_float2(
                acc[mt][nt][2] + s_bp[c]     + s_qr[tq * 128 + c],
                acc[mt][nt][3] + s_bp[c + 1] + s_qr[tq * 128 + c + 1]);
        }
    }
    __syncthreads();

    // ---- LN rows Q -> P (half2); load Wf1 -> WH ----
    {
        for (int r = warp; r < 128; r += 16) {
            float4 v = *reinterpret_cast<const float4*>(&Q[r * QAS + lane * 4]);
            float s = v.x + v.y + v.z + v.w;
            #pragma unroll
            for (int o = 16; o; o >>= 1) s += __shfl_xor_sync(~0u, s, o);
            float mean = s * (1.0f / 128.0f);
            float dx = v.x - mean, dy = v.y - mean, dz = v.z - mean, dw = v.w - mean;
            float sq = dx * dx + dy * dy + dz * dz + dw * dw;
            #pragma unroll
            for (int o = 16; o; o >>= 1) sq += __shfl_xor_sync(~0u, sq, o);
            float inv = rsqrtf(sq * (1.0f / 128.0f) + 1e-5f);
            int c = lane * 4;
            float4 gg = *reinterpret_cast<const float4*>(&s_g2[c]);
            float4 bb = *reinterpret_cast<const float4*>(&s_b2[c]);
            P[r * PHS + 2 * lane]     = ph2(dx * inv * gg.x + bb.x, dy * inv * gg.y + bb.y);
            P[r * PHS + 2 * lane + 1] = ph2(dz * inv * gg.z + bb.z, dw * inv * gg.w + bb.w);
        }
        for (int idx = tid; idx < 8192; idx += 512) {
            int m = idx >> 7, c = idx & 127;
            WH[m * WFS + c] = ph2(Wf1[2 * m * 128 + c], Wf1[(2 * m + 1) * 128 + c]);
        }
    }
    __syncthreads();

    // ---- GEMM2: H1 = gelu(Xn@Wf1 + bf1) -> P (half2) ----
    gemm_mma_h(P, WH, acc, RM, CN, lane);
    __syncthreads();
    #pragma unroll
    for (int mt = 0; mt < 2; mt++) {
        int r = RM + mt * 16 + g;
        #pragma unroll
        for (int nt = 0; nt < 4; nt++) {
            int c = CN + nt * 8 + 2 * t4;
            float v0 = acc[mt][nt][0] + s_bf1[c];
            float v1 = acc[mt][nt][1] + s_bf1[c + 1];
            float v2 = acc[mt][nt][2] + s_bf1[c];
            float v3 = acc[mt][nt][3] + s_bf1[c + 1];
            const float k = 0.70710678118654752f;
            P[r * PHS + (c >> 1)] =
                ph2(0.5f * v0 * (1.0f + erff(v0 * k)), 0.5f * v1 * (1.0f + erff(v1 * k)));
            P[(r + 8) * PHS + (c >> 1)] =
                ph2(0.5f * v2 * (1.0f + erff(v2 * k)), 0.5f * v3 * (1.0f + erff(v3 * k)));
        }
    }
    for (int idx = tid; idx < 8192; idx += 512) {
        int m = idx >> 7, c = idx & 127;
        WH[m * WFS + c] = ph2(Wf2[2 * m * 128 + c], Wf2[(2 * m + 1) * 128 + c]);
    }
    __syncthreads();

    // ---- GEMM3: out = X + H1@Wf2 + bf2 ----
    gemm_mma_h(P, WH, acc, RM, CN, lane);
    #pragma unroll
    for (int mt = 0; mt < 2; mt++) {
        int r = RM + mt * 16 + g;
        #pragma unroll
        for (int nt = 0; nt < 4; nt++) {
            int c = CN + nt * 8 + 2 * t4;
            float2 q0 = *reinterpret_cast<const float2*>(&Q[r * QAS + c]);
            float2 q1 = *reinterpret_cast<const float2*>(&Q[(r + 8) * QAS + c]);
            float* o0 = out + (size_t)(R0 + r) * C + c;
            float* o1 = out + (size_t)(R0 + r + 8) * C + c;
            *reinterpret_cast<float2*>(o0) = make_float2(
                acc[mt][nt][0] + s_bf2[c] + q0.x,
                acc[mt][nt][1] + s_bf2[c + 1] + q0.y);
            *reinterpret_cast<float2*>(o1) = make_float2(
                acc[mt][nt][2] + s_bf2[c] + q1.x,
                acc[mt][nt][3] + s_bf2[c + 1] + q1.y);
        }
    }
}

// ---------------------------------------------------------------------------
extern "C" void kernel_launch(void* const* d_in, const int* in_sizes, int n_in,
                              void* d_out, int out_size) {
    const float* query = (const float*)d_in[0];
    const float* tgt   = (const float*)d_in[1];
    const float* ln1g  = (const float*)d_in[2];
    const float* ln1b  = (const float*)d_in[3];
    const float* ln2g  = (const float*)d_in[4];
    const float* ln2b  = (const float*)d_in[5];
    const float* Wq    = (const float*)d_in[6];
    const float* bq    = (const float*)d_in[7];
    const float* Wk    = (const float*)d_in[8];
    // d_in[9] = bk (cancels in softmax)
    const float* Wv    = (const float*)d_in[10];
    const float* bv    = (const float*)d_in[11];
    const float* Wp    = (const float*)d_in[12];
    const float* bp    = (const float*)d_in[13];
    const float* Wf1   = (const float*)d_in[14];
    const float* bf1   = (const float*)d_in[15];
    const float* Wf2   = (const float*)d_in[16];
    const float* bf2   = (const float*)d_in[17];

    int B = in_sizes[1] / (L * C);
    if (B > MAXB) B = MAXB;

    const int K1_SMEM = (80 * QS + 128 * WVS + 128 + 2 * L * TS + 80 * WSM + 80 * SPS)
                        * sizeof(float);
    const int K2_SMEM = (64 * WFS + 128 * PHS + 128 * QAS + 1024 + 5 * 128) * sizeof(float);

    cudaFuncSetAttribute(attn_kernel, cudaFuncAttributeMaxDynamicSharedMemorySize, K1_SMEM);
    cudaFuncSetAttribute(ffn_kernel,  cudaFuncAttributeMaxDynamicSharedMemorySize, K2_SMEM);

    prep_kernel<<<64, 128>>>(query, ln1g, ln1b, Wq, bq, Wk);
    attn_kernel<<<(B + BPB - 1) / BPB, 512, K1_SMEM>>>(tgt, Wv, bv, B);

    int nrows = B * NTOK;
    ffn_kernel<<<(nrows + 127) / 128, 512, K2_SMEM>>>(query, ln2g, ln2b,
                                                      Wp, bp, Wf1, bf1, Wf2, bf2,
                                                      (float*)d_out, nrows);
}

// round 10
// speedup vs baseline: 1.5175x; 1.3010x over previous
#include <cuda_runtime.h>
#include <cuda_fp16.h>
#include <math.h>

// Problem constants
#define C 128
#define L 54            // 6*9
#define NTOK 8
#define MAXB 8192
#define BPB 8

// attn smem strides
#define TS   132        // s_tgt f32 row stride
#define QS   132        // s_qkp f32 row stride
#define SPS  20         // probs f32 row stride
#define WHS2 69         // s_wh half2 row stride (odd -> <=2-way banks)

// ffn strides (fp16 path)
#define PHS  68         // P half2 row stride
#define WFS  136        // WH half2 row stride (k-interleaved weights)
#define QAS  132        // Q f32 row stride

// Scratch
__device__ float g_qk[64 * 128];
__device__ float g_att[(size_t)MAXB * NTOK * C];

// ---------------------------------------------------------------------------
__device__ __forceinline__ unsigned smem_u32(const void* p) {
    unsigned a;
    asm("{ .reg .u64 t; cvta.to.shared.u64 t, %1; cvt.u32.u64 %0, t; }" : "=r"(a) : "l"(p));
    return a;
}

__device__ __forceinline__ void mma_tf32(float* acc, unsigned a0, unsigned a1,
                                         unsigned a2, unsigned a3,
                                         unsigned b0, unsigned b1) {
    asm volatile(
        "mma.sync.aligned.m16n8k8.row.col.f32.tf32.tf32.f32 "
        "{%0,%1,%2,%3},{%4,%5,%6,%7},{%8,%9},{%0,%1,%2,%3};\n"
        : "+f"(acc[0]), "+f"(acc[1]), "+f"(acc[2]), "+f"(acc[3])
        : "r"(a0), "r"(a1), "r"(a2), "r"(a3), "r"(b0), "r"(b1));
}

__device__ __forceinline__ void mma_f16(float* acc, unsigned a0, unsigned a1,
                                        unsigned a2, unsigned a3,
                                        unsigned b0, unsigned b1) {
    asm volatile(
        "mma.sync.aligned.m16n8k16.row.col.f32.f16.f16.f32 "
        "{%0,%1,%2,%3},{%4,%5,%6,%7},{%8,%9},{%0,%1,%2,%3};\n"
        : "+f"(acc[0]), "+f"(acc[1]), "+f"(acc[2]), "+f"(acc[3])
        : "r"(a0), "r"(a1), "r"(a2), "r"(a3), "r"(b0), "r"(b1));
}

__device__ __forceinline__ unsigned f2u(float x) { return __float_as_uint(x); }

__device__ __forceinline__ unsigned ph2(float a, float b) {
    __half2 h = __floats2half2_rn(a, b);
    return *reinterpret_cast<unsigned*>(&h);
}

// ---------------------------------------------------------------------------
// K0: prep (unchanged)
// ---------------------------------------------------------------------------
__global__ void prep_kernel(const float* __restrict__ q_in,
                            const float* __restrict__ g1, const float* __restrict__ b1,
                            const float* __restrict__ Wq, const float* __restrict__ bq,
                            const float* __restrict__ Wk) {
    __shared__ float s_qn[128];
    __shared__ float s_qh[16];
    __shared__ float s_red[8];
    int th = blockIdx.x, t = th >> 3, h = th & 7;
    int tid = threadIdx.x, lane = tid & 31, warp = tid >> 5;

    float x = q_in[t * 128 + tid];
    float s = x;
    #pragma unroll
    for (int o = 16; o; o >>= 1) s += __shfl_xor_sync(~0u, s, o);
    if (lane == 0) s_red[warp] = s;
    __syncthreads();
    float mean = (s_red[0] + s_red[1] + s_red[2] + s_red[3]) * (1.0f / 128.0f);
    float dx = x - mean;
    float sq = dx * dx;
    #pragma unroll
    for (int o = 16; o; o >>= 1) sq += __shfl_xor_sync(~0u, sq, o);
    __syncthreads();
    if (lane == 0) s_red[warp] = sq;
    __syncthreads();
    float var = (s_red[0] + s_red[1] + s_red[2] + s_red[3]) * (1.0f / 128.0f);
    float inv = rsqrtf(var + 1e-5f);
    s_qn[tid] = dx * inv * g1[tid] + b1[tid];
    __syncthreads();

    int j = tid >> 3, seg = tid & 7;
    int o = h * 16 + j;
    float p = 0.0f;
    #pragma unroll
    for (int i = 0; i < 16; i++) p += s_qn[seg * 16 + i] * Wq[(seg * 16 + i) * 128 + o];
    #pragma unroll
    for (int off = 4; off; off >>= 1) p += __shfl_xor_sync(~0u, p, off);
    if (seg == 0) s_qh[j] = p + bq[o];
    __syncthreads();

    float acc = 0.0f;
    const float* wk = Wk + tid * 128 + h * 16;
    #pragma unroll
    for (int jj = 0; jj < 16; jj++) acc += s_qh[jj] * wk[jj];
    g_qk[th * 128 + tid] = acc * 0.25f;
}

// region-row offset within region for li (0..8); li>=9 -> 0 (padding)
__device__ __forceinline__ int loff(int li) {
    if (li >= 9) return 0;
    int a = li / 3, b = li - a * 3;
    return a * 9 + b;
}

// ---------------------------------------------------------------------------
// K1: fused attention — R9 structure; V phase fp16 with hoisted Wv registers.
// ---------------------------------------------------------------------------
__global__ __launch_bounds__(512, 1)
void attn_kernel(const float* __restrict__ tgt,
                 const float* __restrict__ Wv, const float* __restrict__ bv,
                 int B) {
    extern __shared__ float sm[];
    float* s_qkp = sm;                                    // 80*132 f32
    float* s_bv  = s_qkp + 80 * QS;                       // 128
    float* s_tgt = s_bv  + 128;                           // 2 * 54*132 f32
    unsigned* s_wh = reinterpret_cast<unsigned*>(s_tgt + 2 * L * TS);  // 64*69 half2
    float* s_p   = reinterpret_cast<float*>(s_wh + 64 * WHS2);         // 80*20 f32

    int tid = threadIdx.x;
    int warp = tid >> 5, lane = tid & 31;
    int g = lane >> 2, t4 = lane & 3;

    // prologue: cp.async first batch into buffer 0
    {
        int b0 = blockIdx.x * BPB;
        if (b0 < B) {
            const float4* src = reinterpret_cast<const float4*>(tgt + (size_t)b0 * L * C);
            for (int idx = tid; idx < L * 32; idx += 512) {
                int row = idx >> 5, j = idx & 31;
                unsigned dst = smem_u32(s_tgt + row * TS + j * 4);
                asm volatile("cp.async.ca.shared.global [%0], [%1], 16;\n"
                             :: "r"(dst), "l"(src + idx));
            }
        }
        asm volatile("cp.async.commit_group;\n");
    }

    // stage qk permuted (region-major rows)
    for (int idx = tid; idx < 64 * 128; idx += 512) {
        int tr = idx >> 7, c = idx & 127;
        int t = tr >> 3, h = tr & 7;
        int pos = t + (t == 1) - (t == 2);
        s_qkp[(pos * 8 + h) * QS + c] = g_qk[idx];
    }
    for (int i = 64 * QS + tid; i < 80 * QS; i += 512) s_qkp[i] = 0.0f;
    for (int i = tid; i < 80 * SPS; i += 512) s_p[i] = 0.0f;
    if (tid < 128) s_bv[tid] = bv[tid];

    // ---- per-warp job parameters (static across batches) ----
    bool okD = warp < 12;
    int rD  = warp >> 1, nhD = warp & 1;
    int mbD = (rD < 2) ? rD * 16 : 32 + (rD - 2) * 8;
    int blD = (rD / 3) * 27 + (rD % 3) * 3;
    int liD = nhD * 8 + g;
    int lD  = blD + loff(liD);
    int lW0 = blD + loff(t4);
    int lW1 = blD + loff(t4 + 4);
    int lW2 = blD + loff(t4 + 8);
    int lW3 = blD + loff(t4 + 12);
    int hV = warp >> 1, nhV = warp & 1;
    int o0 = hV * 16 + nhV * 8;

    // ---- hoist Wv B-fragments as half2 (static per warp) ----
    unsigned bwv2[8][2];
    #pragma unroll
    for (int m = 0; m < 8; m++) {
        int k0 = 16 * m + 2 * t4;
        int oc = o0 + g;
        bwv2[m][0] = ph2(Wv[k0 * 128 + oc],       Wv[(k0 + 1) * 128 + oc]);
        bwv2[m][1] = ph2(Wv[(k0 + 8) * 128 + oc], Wv[(k0 + 9) * 128 + oc]);
    }

    __syncthreads();

    for (int bi = 0; bi < BPB; bi++) {
        int b = blockIdx.x * BPB + bi;
        if (b >= B) break;

        float* cur = s_tgt + (bi & 1) * (L * TS);
        float* nxt = s_tgt + ((bi + 1) & 1) * (L * TS);

        int nb = b + 1;
        if (bi + 1 < BPB && nb < B) {
            const float4* src = reinterpret_cast<const float4*>(tgt + (size_t)nb * L * C);
            for (int idx = tid; idx < L * 32; idx += 512) {
                int row = idx >> 5, j = idx & 31;
                unsigned dst = smem_u32(nxt + row * TS + j * 4);
                asm volatile("cp.async.ca.shared.global [%0], [%1], 16;\n"
                             :: "r"(dst), "l"(src + idx));
            }
        }
        asm volatile("cp.async.commit_group;\n");
        asm volatile("cp.async.wait_group 1;\n");
        __syncthreads();

        // ---- D: dots via tf32 mma (two independent 8-deep chains) ----
        if (okD) {
            float accA[4] = {0.f, 0.f, 0.f, 0.f};
            float accB[4] = {0.f, 0.f, 0.f, 0.f};
            const float* Brow = cur + lD * TS;
            const float* Arow0 = s_qkp + (mbD + g) * QS;
            const float* Arow1 = s_qkp + (mbD + g + 8) * QS;
            #pragma unroll
            for (int k0 = 0; k0 < 64; k0 += 8) {
                int kr = k0 + t4;
                mma_tf32(accA,
                         f2u(Arow0[kr]), f2u(Arow1[kr]),
                         f2u(Arow0[kr + 4]), f2u(Arow1[kr + 4]),
                         f2u(Brow[kr]), f2u(Brow[kr + 4]));
                int ks = kr + 64;
                mma_tf32(accB,
                         f2u(Arow0[ks]), f2u(Arow1[ks]),
                         f2u(Arow0[ks + 4]), f2u(Arow1[ks + 4]),
                         f2u(Brow[ks]), f2u(Brow[ks + 4]));
            }
            float acc[4];
            #pragma unroll
            for (int i = 0; i < 4; i++) acc[i] = accA[i] + accB[i];
            int li0 = nhD * 8 + 2 * t4;
            if (li0 < 8) {
                *reinterpret_cast<float2*>(&s_p[(mbD + g) * SPS + li0]) =
                    make_float2(acc[0], acc[1]);
                if (rD < 2)
                    *reinterpret_cast<float2*>(&s_p[(mbD + g + 8) * SPS + li0]) =
                        make_float2(acc[2], acc[3]);
            } else if (li0 == 8) {
                s_p[(mbD + g) * SPS + 8] = acc[0];
                if (rD < 2) s_p[(mbD + g + 8) * SPS + 8] = acc[2];
            }
        }
        __syncthreads();

        // ---- softmax over 9 per row (64 rows) ----
        if (tid < 64) {
            float* pp = s_p + tid * SPS;
            float m = -1e30f;
            #pragma unroll
            for (int li = 0; li < 9; li++) m = fmaxf(m, pp[li]);
            float e[9]; float ssum = 0.0f;
            #pragma unroll
            for (int li = 0; li < 9; li++) { e[li] = expf(pp[li] - m); ssum += e[li]; }
            float invs = 1.0f / ssum;
            #pragma unroll
            for (int li = 0; li < 9; li++) pp[li] = e[li] * invs;
        }
        __syncthreads();

        // ---- W: weighted sum via tf32 mma, epilogue packs half2 into s_wh ----
        if (okD) {
            const float* Ar0 = s_p + (mbD + g) * SPS;
            const float* Ar1 = s_p + (mbD + g + 8) * SPS;
            unsigned a0 = f2u(Ar0[t4]),      a1 = f2u(Ar1[t4]);
            unsigned a2 = f2u(Ar0[t4 + 4]),  a3 = f2u(Ar1[t4 + 4]);
            unsigned a4 = f2u(Ar0[t4 + 8]),  a5 = f2u(Ar1[t4 + 8]);
            unsigned a6 = f2u(Ar0[t4 + 12]), a7 = f2u(Ar1[t4 + 12]);
            int p0 = mbD + g;
            int pos0 = p0 >> 3;
            int t0 = pos0 + (pos0 == 1) - (pos0 == 2);
            int v0 = (p0 & 7) * 8 + t0;
            int p1 = mbD + g + 8;
            int pos1 = p1 >> 3;
            int t1 = pos1 + (pos1 == 1) - (pos1 == 2);
            int v1 = (p1 & 7) * 8 + t1;

            #pragma unroll
            for (int nt = 0; nt < 8; nt++) {
                int c0 = nhD * 64 + nt * 8;
                float accA[4] = {0.f, 0.f, 0.f, 0.f};
                float accB[4] = {0.f, 0.f, 0.f, 0.f};
                mma_tf32(accA, a0, a1, a2, a3,
                         f2u(cur[lW0 * TS + c0 + g]), f2u(cur[lW1 * TS + c0 + g]));
                mma_tf32(accB, a4, a5, a6, a7,
                         f2u(cur[lW2 * TS + c0 + g]), f2u(cur[lW3 * TS + c0 + g]));
                int hc = (c0 >> 1) + t4;   // half2 index of cols (c0+2t4, c0+2t4+1)
                s_wh[v0 * WHS2 + hc] = ph2(accA[0] + accB[0], accA[1] + accB[1]);
                if (rD < 2)
                    s_wh[v1 * WHS2 + hc] = ph2(accA[2] + accB[2], accA[3] + accB[3]);
            }
        }
        __syncthreads();

        // ---- V: att[t, o] = w . Wv + bv  (fp16 mma, B hoisted in regs) ----
        {
            float accA[4] = {0.f, 0.f, 0.f, 0.f};
            float accB[4] = {0.f, 0.f, 0.f, 0.f};
            const unsigned* A0 = s_wh + (hV * 8 + g) * WHS2;
            #pragma unroll
            for (int m = 0; m < 4; m++) {
                int hp = 8 * m + t4;
                unsigned u0 = A0[hp], u1 = A0[hp + 4];
                mma_f16(accA, u0, u0, u1, u1, bwv2[m][0], bwv2[m][1]);
                int hq = 8 * (m + 4) + t4;
                unsigned u2 = A0[hq], u3 = A0[hq + 4];
                mma_f16(accB, u2, u2, u3, u3, bwv2[m + 4][0], bwv2[m + 4][1]);
            }
            int o = o0 + 2 * t4;
            float* op = g_att + ((size_t)b * NTOK + g) * C + o;
            *reinterpret_cast<float2*>(op) =
                make_float2(accA[0] + accB[0] + s_bv[o],
                            accA[1] + accB[1] + s_bv[o + 1]);
        }
        __syncthreads();
    }
}

// ---------------------------------------------------------------------------
// K2: FFN chain, fp16 mma (R8-verified, unchanged).
// ---------------------------------------------------------------------------
__device__ __forceinline__ void gemm_mma_h(const unsigned* __restrict__ P,
                                           const unsigned* __restrict__ WH,
                                           float acc[2][4][4], int RM, int CN, int lane) {
    #pragma unroll
    for (int mt = 0; mt < 2; mt++)
        #pragma unroll
        for (int nt = 0; nt < 4; nt++)
            #pragma unroll
            for (int i = 0; i < 4; i++) acc[mt][nt][i] = 0.0f;

    int g = lane >> 2, t4 = lane & 3;
    const unsigned* A0 = P + (RM + g) * PHS;
    const unsigned* A1 = P + (RM + g + 8) * PHS;
    const unsigned* A2 = P + (RM + 16 + g) * PHS;
    const unsigned* A3 = P + (RM + 16 + g + 8) * PHS;

    #pragma unroll
    for (int m = 0; m < 8; m++) {
        int hp = 8 * m + t4;
        unsigned a00 = A0[hp], a01 = A1[hp], a02 = A0[hp + 4], a03 = A1[hp + 4];
        unsigned a10 = A2[hp], a11 = A3[hp], a12 = A2[hp + 4], a13 = A3[hp + 4];
        const unsigned* W0 = WH + (8 * m + t4) * WFS + CN + g;
        const unsigned* W1 = WH + (8 * m + 4 + t4) * WFS + CN + g;
        #pragma unroll
        for (int nt = 0; nt < 4; nt++) {
            unsigned b0 = W0[nt * 8];
            unsigned b1 = W1[nt * 8];
            mma_f16(acc[0][nt], a00, a01, a02, a03, b0, b1);
            mma_f16(acc[1][nt], a10, a11, a12, a13, b0, b1);
        }
    }
}

__global__ __launch_bounds__(512, 1)
void ffn_kernel(const float* __restrict__ query,
                const float* __restrict__ g2, const float* __restrict__ b2,
                const float* __restrict__ Wp, const float* __restrict__ bp,
                const float* __restrict__ Wf1, const float* __restrict__ bf1,
                const float* __restrict__ Wf2, const float* __restrict__ bf2,
                float* __restrict__ out, int nrows) {
    extern __shared__ float sm[];
    unsigned* WH = reinterpret_cast<unsigned*>(sm);         // 64*136 half2
    unsigned* P  = WH + 64 * WFS;                           // 128*68 half2
    float* Q     = reinterpret_cast<float*>(P + 128 * PHS); // 128*132 f32
    float* s_qr  = Q + 128 * QAS;                           // 1024
    float* s_bp  = s_qr + 1024;
    float* s_bf1 = s_bp + 128;
    float* s_bf2 = s_bf1 + 128;
    float* s_g2  = s_bf2 + 128;
    float* s_b2  = s_g2 + 128;

    int tid = threadIdx.x;
    int warp = tid >> 5, lane = tid & 31;
    int g = lane >> 2, t4 = lane & 3;
    int RM = (warp >> 2) * 32, CN = (warp & 3) * 32;
    int R0 = blockIdx.x * 128;
    if (R0 >= nrows) return;

    {
        const float4* src = reinterpret_cast<const float4*>(g_att + (size_t)R0 * C);
        for (int idx = tid; idx < 4096; idx += 512) {
            int row = idx >> 5, j = idx & 31;
            float4 v = src[idx];
            P[row * PHS + 2 * j]     = ph2(v.x, v.y);
            P[row * PHS + 2 * j + 1] = ph2(v.z, v.w);
        }
        for (int idx = tid; idx < 8192; idx += 512) {
            int m = idx >> 7, c = idx & 127;
            WH[m * WFS + c] = ph2(Wp[2 * m * 128 + c], Wp[(2 * m + 1) * 128 + c]);
        }
        for (int i = tid; i < 1024; i += 512) s_qr[i] = query[i];
        if (tid < 128) {
            s_bp[tid] = bp[tid]; s_bf1[tid] = bf1[tid]; s_bf2[tid] = bf2[tid];
            s_g2[tid] = g2[tid]; s_b2[tid] = b2[tid];
        }
    }
    __syncthreads();

    float acc[2][4][4];

    // ---- GEMM1: X = att@Wp + bp + shortcut -> Q (f32) ----
    gemm_mma_h(P, WH, acc, RM, CN, lane);
    #pragma unroll
    for (int mt = 0; mt < 2; mt++) {
        int r = RM + mt * 16 + g;
        #pragma unroll
        for (int nt = 0; nt < 4; nt++) {
            int c = CN + nt * 8 + 2 * t4;
            int tq = r & 7;
            *reinterpret_cast<float2*>(&Q[r * QAS + c]) = make_float2(
                acc[mt][nt][0] + s_bp[c]     + s_qr[tq * 128 + c],
                acc[mt][nt][1] + s_bp[c + 1] + s_qr[tq * 128 + c + 1]);
            *reinterpret_cast<float2*>(&Q[(r + 8) * QAS + c]) = make_float2(
                acc[mt][nt][2] + s_bp[c]     + s_qr[tq * 128 + c],
                acc[mt][nt][3] + s_bp[c + 1] + s_qr[tq * 128 + c + 1]);
        }
    }
    __syncthreads();

    // ---- LN rows Q -> P (half2); load Wf1 -> WH ----
    {
        for (int r = warp; r < 128; r += 16) {
            float4 v = *reinterpret_cast<const float4*>(&Q[r * QAS + lane * 4]);
            float s = v.x + v.y + v.z + v.w;
            #pragma unroll
            for (int o = 16; o; o >>= 1) s += __shfl_xor_sync(~0u, s, o);
            float mean = s * (1.0f / 128.0f);
            float dx = v.x - mean, dy = v.y - mean, dz = v.z - mean, dw = v.w - mean;
            float sq = dx * dx + dy * dy + dz * dz + dw * dw;
            #pragma unroll
            for (int o = 16; o; o >>= 1) sq += __shfl_xor_sync(~0u, sq, o);
            float inv = rsqrtf(sq * (1.0f / 128.0f) + 1e-5f);
            int c = lane * 4;
            float4 gg = *reinterpret_cast<const float4*>(&s_g2[c]);
            float4 bb = *reinterpret_cast<const float4*>(&s_b2[c]);
            P[r * PHS + 2 * lane]     = ph2(dx * inv * gg.x + bb.x, dy * inv * gg.y + bb.y);
            P[r * PHS + 2 * lane + 1] = ph2(dz * inv * gg.z + bb.z, dw * inv * gg.w + bb.w);
        }
        for (int idx = tid; idx < 8192; idx += 512) {
            int m = idx >> 7, c = idx & 127;
            WH[m * WFS + c] = ph2(Wf1[2 * m * 128 + c], Wf1[(2 * m + 1) * 128 + c]);
        }
    }
    __syncthreads();

    // ---- GEMM2: H1 = gelu(Xn@Wf1 + bf1) -> P (half2) ----
    gemm_mma_h(P, WH, acc, RM, CN, lane);
    __syncthreads();
    #pragma unroll
    for (int mt = 0; mt < 2; mt++) {
        int r = RM + mt * 16 + g;
        #pragma unroll
        for (int nt = 0; nt < 4; nt++) {
            int c = CN + nt * 8 + 2 * t4;
            float v0 = acc[mt][nt][0] + s_bf1[c];
            float v1 = acc[mt][nt][1] + s_bf1[c + 1];
            float v2 = acc[mt][nt][2] + s_bf1[c];
            float v3 = acc[mt][nt][3] + s_bf1[c + 1];
            const float k = 0.70710678118654752f;
            P[r * PHS + (c >> 1)] =
                ph2(0.5f * v0 * (1.0f + erff(v0 * k)), 0.5f * v1 * (1.0f + erff(v1 * k)));
            P[(r + 8) * PHS + (c >> 1)] =
                ph2(0.5f * v2 * (1.0f + erff(v2 * k)), 0.5f * v3 * (1.0f + erff(v3 * k)));
        }
    }
    for (int idx = tid; idx < 8192; idx += 512) {
        int m = idx >> 7, c = idx & 127;
        WH[m * WFS + c] = ph2(Wf2[2 * m * 128 + c], Wf2[(2 * m + 1) * 128 + c]);
    }
    __syncthreads();

    // ---- GEMM3: out = X + H1@Wf2 + bf2 ----
    gemm_mma_h(P, WH, acc, RM, CN, lane);
    #pragma unroll
    for (int mt = 0; mt < 2; mt++) {
        int r = RM + mt * 16 + g;
        #pragma unroll
        for (int nt = 0; nt < 4; nt++) {
            int c = CN + nt * 8 + 2 * t4;
            float2 q0 = *reinterpret_cast<const float2*>(&Q[r * QAS + c]);
            float2 q1 = *reinterpret_cast<const float2*>(&Q[(r + 8) * QAS + c]);
            float* o0 = out + (size_t)(R0 + r) * C + c;
            float* o1 = out + (size_t)(R0 + r + 8) * C + c;
            *reinterpret_cast<float2*>(o0) = make_float2(
                acc[mt][nt][0] + s_bf2[c] + q0.x,
                acc[mt][nt][1] + s_bf2[c + 1] + q0.y);
            *reinterpret_cast<float2*>(o1) = make_float2(
                acc[mt][nt][2] + s_bf2[c] + q1.x,
                acc[mt][nt][3] + s_bf2[c + 1] + q1.y);
        }
    }
}

// ---------------------------------------------------------------------------
extern "C" void kernel_launch(void* const* d_in, const int* in_sizes, int n_in,
                              void* d_out, int out_size) {
    const float* query = (const float*)d_in[0];
    const float* tgt   = (const float*)d_in[1];
    const float* ln1g  = (const float*)d_in[2];
    const float* ln1b  = (const float*)d_in[3];
    const float* ln2g  = (const float*)d_in[4];
    const float* ln2b  = (const float*)d_in[5];
    const float* Wq    = (const float*)d_in[6];
    const float* bq    = (const float*)d_in[7];
    const float* Wk    = (const float*)d_in[8];
    // d_in[9] = bk (cancels in softmax)
    const float* Wv    = (const float*)d_in[10];
    const float* bv    = (const float*)d_in[11];
    const float* Wp    = (const float*)d_in[12];
    const float* bp    = (const float*)d_in[13];
    const float* Wf1   = (const float*)d_in[14];
    const float* bf1   = (const float*)d_in[15];
    const float* Wf2   = (const float*)d_in[16];
    const float* bf2   = (const float*)d_in[17];

    int B = in_sizes[1] / (L * C);
    if (B > MAXB) B = MAXB;

    const int K1_SMEM = (80 * QS + 128 + 2 * L * TS + 64 * WHS2 + 80 * SPS) * sizeof(float);
    const int K2_SMEM = (64 * WFS + 128 * PHS + 128 * QAS + 1024 + 5 * 128) * sizeof(float);

    cudaFuncSetAttribute(attn_kernel, cudaFuncAttributeMaxDynamicSharedMemorySize, K1_SMEM);
    cudaFuncSetAttribute(ffn_kernel,  cudaFuncAttributeMaxDynamicSharedMemorySize, K2_SMEM);

    prep_kernel<<<64, 128>>>(query, ln1g, ln1b, Wq, bq, Wk);
    attn_kernel<<<(B + BPB - 1) / BPB, 512, K1_SMEM>>>(tgt, Wv, bv, B);

    int nrows = B * NTOK;
    ffn_kernel<<<(nrows + 127) / 128, 512, K2_SMEM>>>(query, ln2g, ln2b,
                                                      Wp, bp, Wf1, bf1, Wf2, bf2,
                                                      (float*)d_out, nrows);
}

// round 11
// speedup vs baseline: 1.6667x; 1.0983x over previous
#include <cuda_runtime.h>
#include <cuda_fp16.h>
#include <math.h>

// Problem constants
#define C 128
#define L 54            // 6*9
#define NTOK 8
#define MAXB 8192
#define BPB 8

// attn smem strides
#define TS   132        // s_tgt f32 row stride
#define QS   132        // s_qkp f32 row stride
#define SPS  20         // probs f32 row stride
#define WHS2 69         // s_wh half2 row stride

// ffn strides (fp16 path)
#define PHS  68         // P half2 row stride
#define WFS  136        // WH half2 row stride (k-interleaved weights)
#define QAS  132        // Q f32 row stride

// Scratch
__device__ float g_qk[64 * 128];
__device__ float g_att[(size_t)MAXB * NTOK * C];

// ---------------------------------------------------------------------------
__device__ __forceinline__ unsigned smem_u32(const void* p) {
    unsigned a;
    asm("{ .reg .u64 t; cvta.to.shared.u64 t, %1; cvt.u32.u64 %0, t; }" : "=r"(a) : "l"(p));
    return a;
}

__device__ __forceinline__ void mma_tf32(float* acc, unsigned a0, unsigned a1,
                                         unsigned a2, unsigned a3,
                                         unsigned b0, unsigned b1) {
    asm volatile(
        "mma.sync.aligned.m16n8k8.row.col.f32.tf32.tf32.f32 "
        "{%0,%1,%2,%3},{%4,%5,%6,%7},{%8,%9},{%0,%1,%2,%3};\n"
        : "+f"(acc[0]), "+f"(acc[1]), "+f"(acc[2]), "+f"(acc[3])
        : "r"(a0), "r"(a1), "r"(a2), "r"(a3), "r"(b0), "r"(b1));
}

__device__ __forceinline__ void mma_f16(float* acc, unsigned a0, unsigned a1,
                                        unsigned a2, unsigned a3,
                                        unsigned b0, unsigned b1) {
    asm volatile(
        "mma.sync.aligned.m16n8k16.row.col.f32.f16.f16.f32 "
        "{%0,%1,%2,%3},{%4,%5,%6,%7},{%8,%9},{%0,%1,%2,%3};\n"
        : "+f"(acc[0]), "+f"(acc[1]), "+f"(acc[2]), "+f"(acc[3])
        : "r"(a0), "r"(a1), "r"(a2), "r"(a3), "r"(b0), "r"(b1));
}

__device__ __forceinline__ unsigned f2u(float x) { return __float_as_uint(x); }

__device__ __forceinline__ unsigned ph2(float a, float b) {
    __half2 h = __floats2half2_rn(a, b);
    return *reinterpret_cast<unsigned*>(&h);
}

// ---------------------------------------------------------------------------
// K0: prep (unchanged)
// ---------------------------------------------------------------------------
__global__ void prep_kernel(const float* __restrict__ q_in,
                            const float* __restrict__ g1, const float* __restrict__ b1,
                            const float* __restrict__ Wq, const float* __restrict__ bq,
                            const float* __restrict__ Wk) {
    __shared__ float s_qn[128];
    __shared__ float s_qh[16];
    __shared__ float s_red[8];
    int th = blockIdx.x, t = th >> 3, h = th & 7;
    int tid = threadIdx.x, lane = tid & 31, warp = tid >> 5;

    float x = q_in[t * 128 + tid];
    float s = x;
    #pragma unroll
    for (int o = 16; o; o >>= 1) s += __shfl_xor_sync(~0u, s, o);
    if (lane == 0) s_red[warp] = s;
    __syncthreads();
    float mean = (s_red[0] + s_red[1] + s_red[2] + s_red[3]) * (1.0f / 128.0f);
    float dx = x - mean;
    float sq = dx * dx;
    #pragma unroll
    for (int o = 16; o; o >>= 1) sq += __shfl_xor_sync(~0u, sq, o);
    __syncthreads();
    if (lane == 0) s_red[warp] = sq;
    __syncthreads();
    float var = (s_red[0] + s_red[1] + s_red[2] + s_red[3]) * (1.0f / 128.0f);
    float inv = rsqrtf(var + 1e-5f);
    s_qn[tid] = dx * inv * g1[tid] + b1[tid];
    __syncthreads();

    int j = tid >> 3, seg = tid & 7;
    int o = h * 16 + j;
    float p = 0.0f;
    #pragma unroll
    for (int i = 0; i < 16; i++) p += s_qn[seg * 16 + i] * Wq[(seg * 16 + i) * 128 + o];
    #pragma unroll
    for (int off = 4; off; off >>= 1) p += __shfl_xor_sync(~0u, p, off);
    if (seg == 0) s_qh[j] = p + bq[o];
    __syncthreads();

    float acc = 0.0f;
    const float* wk = Wk + tid * 128 + h * 16;
    #pragma unroll
    for (int jj = 0; jj < 16; jj++) acc += s_qh[jj] * wk[jj];
    g_qk[th * 128 + tid] = acc * 0.25f;
}

// region-row offset within region for li (0..8); li>=9 -> 0 (padding)
__device__ __forceinline__ int loff(int li) {
    if (li >= 9) return 0;
    int a = li / 3, b = li - a * 3;
    return a * 9 + b;
}

// ---------------------------------------------------------------------------
// K1: fused attention — R10 math verbatim; single tgt buffer, occupancy 2.
// ---------------------------------------------------------------------------
__global__ __launch_bounds__(512, 2)
void attn_kernel(const float* __restrict__ tgt,
                 const float* __restrict__ Wv, const float* __restrict__ bv,
                 int B) {
    extern __shared__ float sm[];
    float* s_qkp = sm;                                    // 72*132 f32
    float* s_bv  = s_qkp + 72 * QS;                       // 128
    float* s_tgt = s_bv  + 128;                           // 54*132 f32 (single buffer)
    unsigned* s_wh = reinterpret_cast<unsigned*>(s_tgt + L * TS);  // 64*69 half2
    float* s_p   = reinterpret_cast<float*>(s_wh + 64 * WHS2);     // 72*20 f32

    int tid = threadIdx.x;
    int warp = tid >> 5, lane = tid & 31;
    int g = lane >> 2, t4 = lane & 3;

    // prologue: cp.async first batch
    {
        int b0 = blockIdx.x * BPB;
        if (b0 < B) {
            const float4* src = reinterpret_cast<const float4*>(tgt + (size_t)b0 * L * C);
            for (int idx = tid; idx < L * 32; idx += 512) {
                int row = idx >> 5, j = idx & 31;
                unsigned dst = smem_u32(s_tgt + row * TS + j * 4);
                asm volatile("cp.async.ca.shared.global [%0], [%1], 16;\n"
                             :: "r"(dst), "l"(src + idx));
            }
            asm volatile("cp.async.commit_group;\n");
        }
    }

    // stage qk permuted (region-major rows)
    for (int idx = tid; idx < 64 * 128; idx += 512) {
        int tr = idx >> 7, c = idx & 127;
        int t = tr >> 3, h = tr & 7;
        int pos = t + (t == 1) - (t == 2);
        s_qkp[(pos * 8 + h) * QS + c] = g_qk[idx];
    }
    for (int i = 64 * QS + tid; i < 72 * QS; i += 512) s_qkp[i] = 0.0f;
    for (int i = tid; i < 72 * SPS; i += 512) s_p[i] = 0.0f;
    if (tid < 128) s_bv[tid] = bv[tid];

    // ---- per-warp job parameters (static across batches) ----
    bool okD = warp < 12;
    int rD  = warp >> 1, nhD = warp & 1;
    int mbD = (rD < 2) ? rD * 16 : 32 + (rD - 2) * 8;
    int blD = (rD / 3) * 27 + (rD % 3) * 3;
    int liD = nhD * 8 + g;
    int lD  = blD + loff(liD);
    int lW0 = blD + loff(t4);
    int lW1 = blD + loff(t4 + 4);
    int lW2 = blD + loff(t4 + 8);
    int lW3 = blD + loff(t4 + 12);
    int hV = warp >> 1, nhV = warp & 1;
    int o0 = hV * 16 + nhV * 8;

    // ---- hoist Wv B-fragments as half2 (static per warp) ----
    unsigned bwv2[8][2];
    #pragma unroll
    for (int m = 0; m < 8; m++) {
        int k0 = 16 * m + 2 * t4;
        int oc = o0 + g;
        bwv2[m][0] = ph2(Wv[k0 * 128 + oc],       Wv[(k0 + 1) * 128 + oc]);
        bwv2[m][1] = ph2(Wv[(k0 + 8) * 128 + oc], Wv[(k0 + 9) * 128 + oc]);
    }

    __syncthreads();

    for (int bi = 0; bi < BPB; bi++) {
        int b = blockIdx.x * BPB + bi;
        if (b >= B) break;

        const float* cur = s_tgt;

        asm volatile("cp.async.wait_group 0;\n");
        __syncthreads();   // tgt ready for all

        // ---- D: dots via tf32 mma (two independent 8-deep chains) ----
        if (okD) {
            float accA[4] = {0.f, 0.f, 0.f, 0.f};
            float accB[4] = {0.f, 0.f, 0.f, 0.f};
            const float* Brow = cur + lD * TS;
            const float* Arow0 = s_qkp + (mbD + g) * QS;
            const float* Arow1 = s_qkp + (mbD + g + 8) * QS;
            #pragma unroll
            for (int k0 = 0; k0 < 64; k0 += 8) {
                int kr = k0 + t4;
                mma_tf32(accA,
                         f2u(Arow0[kr]), f2u(Arow1[kr]),
                         f2u(Arow0[kr + 4]), f2u(Arow1[kr + 4]),
                         f2u(Brow[kr]), f2u(Brow[kr + 4]));
                int ks = kr + 64;
                mma_tf32(accB,
                         f2u(Arow0[ks]), f2u(Arow1[ks]),
                         f2u(Arow0[ks + 4]), f2u(Arow1[ks + 4]),
                         f2u(Brow[ks]), f2u(Brow[ks + 4]));
            }
            float acc[4];
            #pragma unroll
            for (int i = 0; i < 4; i++) acc[i] = accA[i] + accB[i];
            int li0 = nhD * 8 + 2 * t4;
            if (li0 < 8) {
                *reinterpret_cast<float2*>(&s_p[(mbD + g) * SPS + li0]) =
                    make_float2(acc[0], acc[1]);
                if (rD < 2)
                    *reinterpret_cast<float2*>(&s_p[(mbD + g + 8) * SPS + li0]) =
                        make_float2(acc[2], acc[3]);
            } else if (li0 == 8) {
                s_p[(mbD + g) * SPS + 8] = acc[0];
                if (rD < 2) s_p[(mbD + g + 8) * SPS + 8] = acc[2];
            }
        }
        __syncthreads();

        // ---- softmax over 9 per row (64 rows) ----
        if (tid < 64) {
            float* pp = s_p + tid * SPS;
            float m = -1e30f;
            #pragma unroll
            for (int li = 0; li < 9; li++) m = fmaxf(m, pp[li]);
            float e[9]; float ssum = 0.0f;
            #pragma unroll
            for (int li = 0; li < 9; li++) { e[li] = expf(pp[li] - m); ssum += e[li]; }
            float invs = 1.0f / ssum;
            #pragma unroll
            for (int li = 0; li < 9; li++) pp[li] = e[li] * invs;
        }
        __syncthreads();

        // ---- W: weighted sum via tf32 mma, epilogue packs half2 into s_wh ----
        if (okD) {
            const float* Ar0 = s_p + (mbD + g) * SPS;
            const float* Ar1 = s_p + (mbD + g + 8) * SPS;
            unsigned a0 = f2u(Ar0[t4]),      a1 = f2u(Ar1[t4]);
            unsigned a2 = f2u(Ar0[t4 + 4]),  a3 = f2u(Ar1[t4 + 4]);
            unsigned a4 = f2u(Ar0[t4 + 8]),  a5 = f2u(Ar1[t4 + 8]);
            unsigned a6 = f2u(Ar0[t4 + 12]), a7 = f2u(Ar1[t4 + 12]);
            int p0 = mbD + g;
            int pos0 = p0 >> 3;
            int t0 = pos0 + (pos0 == 1) - (pos0 == 2);
            int v0 = (p0 & 7) * 8 + t0;
            int p1 = mbD + g + 8;
            int pos1 = p1 >> 3;
            int t1 = pos1 + (pos1 == 1) - (pos1 == 2);
            int v1 = (p1 & 7) * 8 + t1;

            #pragma unroll
            for (int nt = 0; nt < 8; nt++) {
                int c0 = nhD * 64 + nt * 8;
                float accA[4] = {0.f, 0.f, 0.f, 0.f};
                float accB[4] = {0.f, 0.f, 0.f, 0.f};
                mma_tf32(accA, a0, a1, a2, a3,
                         f2u(cur[lW0 * TS + c0 + g]), f2u(cur[lW1 * TS + c0 + g]));
                mma_tf32(accB, a4, a5, a6, a7,
                         f2u(cur[lW2 * TS + c0 + g]), f2u(cur[lW3 * TS + c0 + g]));
                int hc = (c0 >> 1) + t4;
                s_wh[v0 * WHS2 + hc] = ph2(accA[0] + accB[0], accA[1] + accB[1]);
                if (rD < 2)
                    s_wh[v1 * WHS2 + hc] = ph2(accA[2] + accB[2], accA[3] + accB[3]);
            }
        }
        __syncthreads();   // s_wh complete; ALL tgt reads done

        // prefetch next batch into s_tgt (overlaps V; waited at top of next iter)
        int nb = b + 1;
        if (bi + 1 < BPB && nb < B) {
            const float4* src = reinterpret_cast<const float4*>(tgt + (size_t)nb * L * C);
            for (int idx = tid; idx < L * 32; idx += 512) {
                int row = idx >> 5, j = idx & 31;
                unsigned dst = smem_u32(s_tgt + row * TS + j * 4);
                asm volatile("cp.async.ca.shared.global [%0], [%1], 16;\n"
                             :: "r"(dst), "l"(src + idx));
            }
            asm volatile("cp.async.commit_group;\n");
        }

        // ---- V: att[t, o] = w . Wv + bv  (fp16 mma, B hoisted in regs) ----
        {
            float accA[4] = {0.f, 0.f, 0.f, 0.f};
            float accB[4] = {0.f, 0.f, 0.f, 0.f};
            const unsigned* A0 = s_wh + (hV * 8 + g) * WHS2;
            #pragma unroll
            for (int m = 0; m < 4; m++) {
                int hp = 8 * m + t4;
                unsigned u0 = A0[hp], u1 = A0[hp + 4];
                mma_f16(accA, u0, u0, u1, u1, bwv2[m][0], bwv2[m][1]);
                int hq = 8 * (m + 4) + t4;
                unsigned u2 = A0[hq], u3 = A0[hq + 4];
                mma_f16(accB, u2, u2, u3, u3, bwv2[m + 4][0], bwv2[m + 4][1]);
            }
            int o = o0 + 2 * t4;
            float* op = g_att + ((size_t)b * NTOK + g) * C + o;
            *reinterpret_cast<float2*>(op) =
                make_float2(accA[0] + accB[0] + s_bv[o],
                            accA[1] + accB[1] + s_bv[o + 1]);
        }
        __syncthreads();   // s_wh reads done before next W; tgt write ordered at top wait
    }
}

// ---------------------------------------------------------------------------
// K2: FFN chain, fp16 mma (unchanged from R10).
// ---------------------------------------------------------------------------
__device__ __forceinline__ void gemm_mma_h(const unsigned* __restrict__ P,
                                           const unsigned* __restrict__ WH,
                                           float acc[2][4][4], int RM, int CN, int lane) {
    #pragma unroll
    for (int mt = 0; mt < 2; mt++)
        #pragma unroll
        for (int nt = 0; nt < 4; nt++)
            #pragma unroll
            for (int i = 0; i < 4; i++) acc[mt][nt][i] = 0.0f;

    int g = lane >> 2, t4 = lane & 3;
    const unsigned* A0 = P + (RM + g) * PHS;
    const unsigned* A1 = P + (RM + g + 8) * PHS;
    const unsigned* A2 = P + (RM + 16 + g) * PHS;
    const unsigned* A3 = P + (RM + 16 + g + 8) * PHS;

    #pragma unroll
    for (int m = 0; m < 8; m++) {
        int hp = 8 * m + t4;
        unsigned a00 = A0[hp], a01 = A1[hp], a02 = A0[hp + 4], a03 = A1[hp + 4];
        unsigned a10 = A2[hp], a11 = A3[hp], a12 = A2[hp + 4], a13 = A3[hp + 4];
        const unsigned* W0 = WH + (8 * m + t4) * WFS + CN + g;
        const unsigned* W1 = WH + (8 * m + 4 + t4) * WFS + CN + g;
        #pragma unroll
        for (int nt = 0; nt < 4; nt++) {
            unsigned b0 = W0[nt * 8];
            unsigned b1 = W1[nt * 8];
            mma_f16(acc[0][nt], a00, a01, a02, a03, b0, b1);
            mma_f16(acc[1][nt], a10, a11, a12, a13, b0, b1);
        }
    }
}

__global__ __launch_bounds__(512, 1)
void ffn_kernel(const float* __restrict__ query,
                const float* __restrict__ g2, const float* __restrict__ b2,
                const float* __restrict__ Wp, const float* __restrict__ bp,
                const float* __restrict__ Wf1, const float* __restrict__ bf1,
                const float* __restrict__ Wf2, const float* __restrict__ bf2,
                float* __restrict__ out, int nrows) {
    extern __shared__ float sm[];
    unsigned* WH = reinterpret_cast<unsigned*>(sm);         // 64*136 half2
    unsigned* P  = WH + 64 * WFS;                           // 128*68 half2
    float* Q     = reinterpret_cast<float*>(P + 128 * PHS); // 128*132 f32
    float* s_qr  = Q + 128 * QAS;                           // 1024
    float* s_bp  = s_qr + 1024;
    float* s_bf1 = s_bp + 128;
    float* s_bf2 = s_bf1 + 128;
    float* s_g2  = s_bf2 + 128;
    float* s_b2  = s_g2 + 128;

    int tid = threadIdx.x;
    int warp = tid >> 5, lane = tid & 31;
    int g = lane >> 2, t4 = lane & 3;
    int RM = (warp >> 2) * 32, CN = (warp & 3) * 32;
    int R0 = blockIdx.x * 128;
    if (R0 >= nrows) return;

    {
        const float4* src = reinterpret_cast<const float4*>(g_att + (size_t)R0 * C);
        for (int idx = tid; idx < 4096; idx += 512) {
            int row = idx >> 5, j = idx & 31;
            float4 v = src[idx];
            P[row * PHS + 2 * j]     = ph2(v.x, v.y);
            P[row * PHS + 2 * j + 1] = ph2(v.z, v.w);
        }
        for (int idx = tid; idx < 8192; idx += 512) {
            int m = idx >> 7, c = idx & 127;
            WH[m * WFS + c] = ph2(Wp[2 * m * 128 + c], Wp[(2 * m + 1) * 128 + c]);
        }
        for (int i = tid; i < 1024; i += 512) s_qr[i] = query[i];
        if (tid < 128) {
            s_bp[tid] = bp[tid]; s_bf1[tid] = bf1[tid]; s_bf2[tid] = bf2[tid];
            s_g2[tid] = g2[tid]; s_b2[tid] = b2[tid];
        }
    }
    __syncthreads();

    float acc[2][4][4];

    // ---- GEMM1: X = att@Wp + bp + shortcut -> Q (f32) ----
    gemm_mma_h(P, WH, acc, RM, CN, lane);
    #pragma unroll
    for (int mt = 0; mt < 2; mt++) {
        int r = RM + mt * 16 + g;
        #pragma unroll
        for (int nt = 0; nt < 4; nt++) {
            int c = CN + nt * 8 + 2 * t4;
            int tq = r & 7;
            *reinterpret_cast<float2*>(&Q[r * QAS + c]) = make_float2(
                acc[mt][nt][0] + s_bp[c]     + s_qr[tq * 128 + c],
                acc[mt][nt][1] + s_bp[c + 1] + s_qr[tq * 128 + c + 1]);
            *reinterpret_cast<float2*>(&Q[(r + 8) * QAS + c]) = make_float2(
                acc[mt][nt][2] + s_bp[c]     + s_qr[tq * 128 + c],
                acc[mt][nt][3] + s_bp[c + 1] + s_qr[tq * 128 + c + 1]);
        }
    }
    __syncthreads();

    // ---- LN rows Q -> P (half2); load Wf1 -> WH ----
    {
        for (int r = warp; r < 128; r += 16) {
            float4 v = *reinterpret_cast<const float4*>(&Q[r * QAS + lane * 4]);
            float s = v.x + v.y + v.z + v.w;
            #pragma unroll
            for (int o = 16; o; o >>= 1) s += __shfl_xor_sync(~0u, s, o);
            float mean = s * (1.0f / 128.0f);
            float dx = v.x - mean, dy = v.y - mean, dz = v.z - mean, dw = v.w - mean;
            float sq = dx * dx + dy * dy + dz * dz + dw * dw;
            #pragma unroll
            for (int o = 16; o; o >>= 1) sq += __shfl_xor_sync(~0u, sq, o);
            float inv = rsqrtf(sq * (1.0f / 128.0f) + 1e-5f);
            int c = lane * 4;
            float4 gg = *reinterpret_cast<const float4*>(&s_g2[c]);
            float4 bb = *reinterpret_cast<const float4*>(&s_b2[c]);
            P[r * PHS + 2 * lane]     = ph2(dx * inv * gg.x + bb.x, dy * inv * gg.y + bb.y);
            P[r * PHS + 2 * lane + 1] = ph2(dz * inv * gg.z + bb.z, dw * inv * gg.w + bb.w);
        }
        for (int idx = tid; idx < 8192; idx += 512) {
            int m = idx >> 7, c = idx & 127;
            WH[m * WFS + c] = ph2(Wf1[2 * m * 128 + c], Wf1[(2 * m + 1) * 128 + c]);
        }
    }
    __syncthreads();

    // ---- GEMM2: H1 = gelu(Xn@Wf1 + bf1) -> P (half2) ----
    gemm_mma_h(P, WH, acc, RM, CN, lane);
    __syncthreads();
    #pragma unroll
    for (int mt = 0; mt < 2; mt++) {
        int r = RM + mt * 16 + g;
        #pragma unroll
        for (int nt = 0; nt < 4; nt++) {
            int c = CN + nt * 8 + 2 * t4;
            float v0 = acc[mt][nt][0] + s_bf1[c];
            float v1 = acc[mt][nt][1] + s_bf1[c + 1];
            float v2 = acc[mt][nt][2] + s_bf1[c];
            float v3 = acc[mt][nt][3] + s_bf1[c + 1];
            const float k = 0.70710678118654752f;
            P[r * PHS + (c >> 1)] =
                ph2(0.5f * v0 * (1.0f + erff(v0 * k)), 0.5f * v1 * (1.0f + erff(v1 * k)));
            P[(r + 8) * PHS + (c >> 1)] =
                ph2(0.5f * v2 * (1.0f + erff(v2 * k)), 0.5f * v3 * (1.0f + erff(v3 * k)));
        }
    }
    for (int idx = tid; idx < 8192; idx += 512) {
        int m = idx >> 7, c = idx & 127;
        WH[m * WFS + c] = ph2(Wf2[2 * m * 128 + c], Wf2[(2 * m + 1) * 128 + c]);
    }
    __syncthreads();

    // ---- GEMM3: out = X + H1@Wf2 + bf2 ----
    gemm_mma_h(P, WH, acc, RM, CN, lane);
    #pragma unroll
    for (int mt = 0; mt < 2; mt++) {
        int r = RM + mt * 16 + g;
        #pragma unroll
        for (int nt = 0; nt < 4; nt++) {
            int c = CN + nt * 8 + 2 * t4;
            float2 q0 = *reinterpret_cast<const float2*>(&Q[r * QAS + c]);
            float2 q1 = *reinterpret_cast<const float2*>(&Q[(r + 8) * QAS + c]);
            float* o0 = out + (size_t)(R0 + r) * C + c;
            float* o1 = out + (size_t)(R0 + r + 8) * C + c;
            *reinterpret_cast<float2*>(o0) = make_float2(
                acc[mt][nt][0] + s_bf2[c] + q0.x,
                acc[mt][nt][1] + s_bf2[c + 1] + q0.y);
            *reinterpret_cast<float2*>(o1) = make_float2(
                acc[mt][nt][2] + s_bf2[c] + q1.x,
                acc[mt][nt][3] + s_bf2[c + 1] + q1.y);
        }
    }
}

// ---------------------------------------------------------------------------
extern "C" void kernel_launch(void* const* d_in, const int* in_sizes, int n_in,
                              void* d_out, int out_size) {
    const float* query = (const float*)d_in[0];
    const float* tgt   = (const float*)d_in[1];
    const float* ln1g  = (const float*)d_in[2];
    const float* ln1b  = (const float*)d_in[3];
    const float* ln2g  = (const float*)d_in[4];
    const float* ln2b  = (const float*)d_in[5];
    const float* Wq    = (const float*)d_in[6];
    const float* bq    = (const float*)d_in[7];
    const float* Wk    = (const float*)d_in[8];
    // d_in[9] = bk (cancels in softmax)
    const float* Wv    = (const float*)d_in[10];
    const float* bv    = (const float*)d_in[11];
    const float* Wp    = (const float*)d_in[12];
    const float* bp    = (const float*)d_in[13];
    const float* Wf1   = (const float*)d_in[14];
    const float* bf1   = (const float*)d_in[15];
    const float* Wf2   = (const float*)d_in[16];
    const float* bf2   = (const float*)d_in[17];

    int B = in_sizes[1] / (L * C);
    if (B > MAXB) B = MAXB;

    const int K1_SMEM = (72 * QS + 128 + L * TS + 64 * WHS2 + 72 * SPS) * sizeof(float);
    const int K2_SMEM = (64 * WFS + 128 * PHS + 128 * QAS + 1024 + 5 * 128) * sizeof(float);

    cudaFuncSetAttribute(attn_kernel, cudaFuncAttributeMaxDynamicSharedMemorySize, K1_SMEM);
    cudaFuncSetAttribute(ffn_kernel,  cudaFuncAttributeMaxDynamicSharedMemorySize, K2_SMEM);

    prep_kernel<<<64, 128>>>(query, ln1g, ln1b, Wq, bq, Wk);
    attn_kernel<<<(B + BPB - 1) / BPB, 512, K1_SMEM>>>(tgt, Wv, bv, B);

    int nrows = B * NTOK;
    ffn_kernel<<<(nrows + 127) / 128, 512, K2_SMEM>>>(query, ln2g, ln2b,
                                                      Wp, bp, Wf1, bf1, Wf2, bf2,
                                                      (float*)d_out, nrows);
}

// round 12
// speedup vs baseline: 1.6691x; 1.0014x over previous
#include <cuda_runtime.h>
#include <cuda_fp16.h>
#include <math.h>

// Problem constants
#define C 128
#define L 54            // 6*9
#define NTOK 8
#define MAXB 8192
#define BPB 8

// attn smem strides
#define TS   132        // s_tgt f32 row stride
#define QS   132        // s_qkp f32 row stride
#define SPS  20         // probs f32 row stride
#define WHS2 69         // s_wh half2 row stride

// ffn strides (fp16 path)
#define PHS  68         // P half2 row stride
#define WFS  136        // WH half2 row stride (k-interleaved weights)
#define QAS  132        // Q f32 row stride

// Scratch
__device__ float g_qk[64 * 128];
__device__ float g_att[(size_t)MAXB * NTOK * C];

// ---------------------------------------------------------------------------
__device__ __forceinline__ unsigned smem_u32(const void* p) {
    unsigned a;
    asm("{ .reg .u64 t; cvta.to.shared.u64 t, %1; cvt.u32.u64 %0, t; }" : "=r"(a) : "l"(p));
    return a;
}

__device__ __forceinline__ void mma_tf32(float* acc, unsigned a0, unsigned a1,
                                         unsigned a2, unsigned a3,
                                         unsigned b0, unsigned b1) {
    asm volatile(
        "mma.sync.aligned.m16n8k8.row.col.f32.tf32.tf32.f32 "
        "{%0,%1,%2,%3},{%4,%5,%6,%7},{%8,%9},{%0,%1,%2,%3};\n"
        : "+f"(acc[0]), "+f"(acc[1]), "+f"(acc[2]), "+f"(acc[3])
        : "r"(a0), "r"(a1), "r"(a2), "r"(a3), "r"(b0), "r"(b1));
}

__device__ __forceinline__ void mma_f16(float* acc, unsigned a0, unsigned a1,
                                        unsigned a2, unsigned a3,
                                        unsigned b0, unsigned b1) {
    asm volatile(
        "mma.sync.aligned.m16n8k16.row.col.f32.f16.f16.f32 "
        "{%0,%1,%2,%3},{%4,%5,%6,%7},{%8,%9},{%0,%1,%2,%3};\n"
        : "+f"(acc[0]), "+f"(acc[1]), "+f"(acc[2]), "+f"(acc[3])
        : "r"(a0), "r"(a1), "r"(a2), "r"(a3), "r"(b0), "r"(b1));
}

__device__ __forceinline__ unsigned f2u(float x) { return __float_as_uint(x); }

__device__ __forceinline__ unsigned ph2(float a, float b) {
    __half2 h = __floats2half2_rn(a, b);
    return *reinterpret_cast<unsigned*>(&h);
}

// ---------------------------------------------------------------------------
// K0: prep (unchanged)
// ---------------------------------------------------------------------------
__global__ void prep_kernel(const float* __restrict__ q_in,
                            const float* __restrict__ g1, const float* __restrict__ b1,
                            const float* __restrict__ Wq, const float* __restrict__ bq,
                            const float* __restrict__ Wk) {
    __shared__ float s_qn[128];
    __shared__ float s_qh[16];
    __shared__ float s_red[8];
    int th = blockIdx.x, t = th >> 3, h = th & 7;
    int tid = threadIdx.x, lane = tid & 31, warp = tid >> 5;

    float x = q_in[t * 128 + tid];
    float s = x;
    #pragma unroll
    for (int o = 16; o; o >>= 1) s += __shfl_xor_sync(~0u, s, o);
    if (lane == 0) s_red[warp] = s;
    __syncthreads();
    float mean = (s_red[0] + s_red[1] + s_red[2] + s_red[3]) * (1.0f / 128.0f);
    float dx = x - mean;
    float sq = dx * dx;
    #pragma unroll
    for (int o = 16; o; o >>= 1) sq += __shfl_xor_sync(~0u, sq, o);
    __syncthreads();
    if (lane == 0) s_red[warp] = sq;
    __syncthreads();
    float var = (s_red[0] + s_red[1] + s_red[2] + s_red[3]) * (1.0f / 128.0f);
    float inv = rsqrtf(var + 1e-5f);
    s_qn[tid] = dx * inv * g1[tid] + b1[tid];
    __syncthreads();

    int j = tid >> 3, seg = tid & 7;
    int o = h * 16 + j;
    float p = 0.0f;
    #pragma unroll
    for (int i = 0; i < 16; i++) p += s_qn[seg * 16 + i] * Wq[(seg * 16 + i) * 128 + o];
    #pragma unroll
    for (int off = 4; off; off >>= 1) p += __shfl_xor_sync(~0u, p, off);
    if (seg == 0) s_qh[j] = p + bq[o];
    __syncthreads();

    float acc = 0.0f;
    const float* wk = Wk + tid * 128 + h * 16;
    #pragma unroll
    for (int jj = 0; jj < 16; jj++) acc += s_qh[jj] * wk[jj];
    g_qk[th * 128 + tid] = acc * 0.25f;
}

// region-row offset within region for li (0..8); li>=9 -> 0 (padding)
__device__ __forceinline__ int loff(int li) {
    if (li >= 9) return 0;
    int a = li / 3, b = li - a * 3;
    return a * 9 + b;
}

// ---------------------------------------------------------------------------
// K1: fused attention — R10 math verbatim; single tgt buffer, occupancy 2.
// ---------------------------------------------------------------------------
__global__ __launch_bounds__(512, 2)
void attn_kernel(const float* __restrict__ tgt,
                 const float* __restrict__ Wv, const float* __restrict__ bv,
                 int B) {
    extern __shared__ float sm[];
    float* s_qkp = sm;                                    // 72*132 f32
    float* s_bv  = s_qkp + 72 * QS;                       // 128
    float* s_tgt = s_bv  + 128;                           // 54*132 f32 (single buffer)
    unsigned* s_wh = reinterpret_cast<unsigned*>(s_tgt + L * TS);  // 64*69 half2
    float* s_p   = reinterpret_cast<float*>(s_wh + 64 * WHS2);     // 72*20 f32

    int tid = threadIdx.x;
    int warp = tid >> 5, lane = tid & 31;
    int g = lane >> 2, t4 = lane & 3;

    // prologue: cp.async first batch
    {
        int b0 = blockIdx.x * BPB;
        if (b0 < B) {
            const float4* src = reinterpret_cast<const float4*>(tgt + (size_t)b0 * L * C);
            for (int idx = tid; idx < L * 32; idx += 512) {
                int row = idx >> 5, j = idx & 31;
                unsigned dst = smem_u32(s_tgt + row * TS + j * 4);
                asm volatile("cp.async.ca.shared.global [%0], [%1], 16;\n"
                             :: "r"(dst), "l"(src + idx));
            }
            asm volatile("cp.async.commit_group;\n");
        }
    }

    // stage qk permuted (region-major rows)
    for (int idx = tid; idx < 64 * 128; idx += 512) {
        int tr = idx >> 7, c = idx & 127;
        int t = tr >> 3, h = tr & 7;
        int pos = t + (t == 1) - (t == 2);
        s_qkp[(pos * 8 + h) * QS + c] = g_qk[idx];
    }
    for (int i = 64 * QS + tid; i < 72 * QS; i += 512) s_qkp[i] = 0.0f;
    for (int i = tid; i < 72 * SPS; i += 512) s_p[i] = 0.0f;
    if (tid < 128) s_bv[tid] = bv[tid];

    // ---- per-warp job parameters (static across batches) ----
    bool okD = warp < 12;
    int rD  = warp >> 1, nhD = warp & 1;
    int mbD = (rD < 2) ? rD * 16 : 32 + (rD - 2) * 8;
    int blD = (rD / 3) * 27 + (rD % 3) * 3;
    int liD = nhD * 8 + g;
    int lD  = blD + loff(liD);
    int lW0 = blD + loff(t4);
    int lW1 = blD + loff(t4 + 4);
    int lW2 = blD + loff(t4 + 8);
    int lW3 = blD + loff(t4 + 12);
    int hV = warp >> 1, nhV = warp & 1;
    int o0 = hV * 16 + nhV * 8;

    // ---- hoist Wv B-fragments as half2 (static per warp) ----
    unsigned bwv2[8][2];
    #pragma unroll
    for (int m = 0; m < 8; m++) {
        int k0 = 16 * m + 2 * t4;
        int oc = o0 + g;
        bwv2[m][0] = ph2(Wv[k0 * 128 + oc],       Wv[(k0 + 1) * 128 + oc]);
        bwv2[m][1] = ph2(Wv[(k0 + 8) * 128 + oc], Wv[(k0 + 9) * 128 + oc]);
    }

    __syncthreads();

    for (int bi = 0; bi < BPB; bi++) {
        int b = blockIdx.x * BPB + bi;
        if (b >= B) break;

        const float* cur = s_tgt;

        asm volatile("cp.async.wait_group 0;\n");
        __syncthreads();   // tgt ready for all

        // ---- D: dots via tf32 mma (two independent 8-deep chains) ----
        if (okD) {
            float accA[4] = {0.f, 0.f, 0.f, 0.f};
            float accB[4] = {0.f, 0.f, 0.f, 0.f};
            const float* Brow = cur + lD * TS;
            const float* Arow0 = s_qkp + (mbD + g) * QS;
            const float* Arow1 = s_qkp + (mbD + g + 8) * QS;
            #pragma unroll
            for (int k0 = 0; k0 < 64; k0 += 8) {
                int kr = k0 + t4;
                mma_tf32(accA,
                         f2u(Arow0[kr]), f2u(Arow1[kr]),
                         f2u(Arow0[kr + 4]), f2u(Arow1[kr + 4]),
                         f2u(Brow[kr]), f2u(Brow[kr + 4]));
                int ks = kr + 64;
                mma_tf32(accB,
                         f2u(Arow0[ks]), f2u(Arow1[ks]),
                         f2u(Arow0[ks + 4]), f2u(Arow1[ks + 4]),
                         f2u(Brow[ks]), f2u(Brow[ks + 4]));
            }
            float acc[4];
            #pragma unroll
            for (int i = 0; i < 4; i++) acc[i] = accA[i] + accB[i];
            int li0 = nhD * 8 + 2 * t4;
            if (li0 < 8) {
                *reinterpret_cast<float2*>(&s_p[(mbD + g) * SPS + li0]) =
                    make_float2(acc[0], acc[1]);
                if (rD < 2)
                    *reinterpret_cast<float2*>(&s_p[(mbD + g + 8) * SPS + li0]) =
                        make_float2(acc[2], acc[3]);
            } else if (li0 == 8) {
                s_p[(mbD + g) * SPS + 8] = acc[0];
                if (rD < 2) s_p[(mbD + g + 8) * SPS + 8] = acc[2];
            }
        }
        __syncthreads();

        // ---- softmax over 9 per row (64 rows) ----
        if (tid < 64) {
            float* pp = s_p + tid * SPS;
            float m = -1e30f;
            #pragma unroll
            for (int li = 0; li < 9; li++) m = fmaxf(m, pp[li]);
            float e[9]; float ssum = 0.0f;
            #pragma unroll
            for (int li = 0; li < 9; li++) { e[li] = expf(pp[li] - m); ssum += e[li]; }
            float invs = 1.0f / ssum;
            #pragma unroll
            for (int li = 0; li < 9; li++) pp[li] = e[li] * invs;
        }
        __syncthreads();

        // ---- W: weighted sum via tf32 mma, epilogue packs half2 into s_wh ----
        if (okD) {
            const float* Ar0 = s_p + (mbD + g) * SPS;
            const float* Ar1 = s_p + (mbD + g + 8) * SPS;
            unsigned a0 = f2u(Ar0[t4]),      a1 = f2u(Ar1[t4]);
            unsigned a2 = f2u(Ar0[t4 + 4]),  a3 = f2u(Ar1[t4 + 4]);
            unsigned a4 = f2u(Ar0[t4 + 8]),  a5 = f2u(Ar1[t4 + 8]);
            unsigned a6 = f2u(Ar0[t4 + 12]), a7 = f2u(Ar1[t4 + 12]);
            int p0 = mbD + g;
            int pos0 = p0 >> 3;
            int t0 = pos0 + (pos0 == 1) - (pos0 == 2);
            int v0 = (p0 & 7) * 8 + t0;
            int p1 = mbD + g + 8;
            int pos1 = p1 >> 3;
            int t1 = pos1 + (pos1 == 1) - (pos1 == 2);
            int v1 = (p1 & 7) * 8 + t1;

            #pragma unroll
            for (int nt = 0; nt < 8; nt++) {
                int c0 = nhD * 64 + nt * 8;
                float accA[4] = {0.f, 0.f, 0.f, 0.f};
                float accB[4] = {0.f, 0.f, 0.f, 0.f};
                mma_tf32(accA, a0, a1, a2, a3,
                         f2u(cur[lW0 * TS + c0 + g]), f2u(cur[lW1 * TS + c0 + g]));
                mma_tf32(accB, a4, a5, a6, a7,
                         f2u(cur[lW2 * TS + c0 + g]), f2u(cur[lW3 * TS + c0 + g]));
                int hc = (c0 >> 1) + t4;
                s_wh[v0 * WHS2 + hc] = ph2(accA[0] + accB[0], accA[1] + accB[1]);
                if (rD < 2)
                    s_wh[v1 * WHS2 + hc] = ph2(accA[2] + accB[2], accA[3] + accB[3]);
            }
        }
        __syncthreads();   // s_wh complete; ALL tgt reads done

        // prefetch next batch into s_tgt (overlaps V; waited at top of next iter)
        int nb = b + 1;
        if (bi + 1 < BPB && nb < B) {
            const float4* src = reinterpret_cast<const float4*>(tgt + (size_t)nb * L * C);
            for (int idx = tid; idx < L * 32; idx += 512) {
                int row = idx >> 5, j = idx & 31;
                unsigned dst = smem_u32(s_tgt + row * TS + j * 4);
                asm volatile("cp.async.ca.shared.global [%0], [%1], 16;\n"
                             :: "r"(dst), "l"(src + idx));
            }
            asm volatile("cp.async.commit_group;\n");
        }

        // ---- V: att[t, o] = w . Wv + bv  (fp16 mma, B hoisted in regs) ----
        {
            float accA[4] = {0.f, 0.f, 0.f, 0.f};
            float accB[4] = {0.f, 0.f, 0.f, 0.f};
            const unsigned* A0 = s_wh + (hV * 8 + g) * WHS2;
            #pragma unroll
            for (int m = 0; m < 4; m++) {
                int hp = 8 * m + t4;
                unsigned u0 = A0[hp], u1 = A0[hp + 4];
                mma_f16(accA, u0, u0, u1, u1, bwv2[m][0], bwv2[m][1]);
                int hq = 8 * (m + 4) + t4;
                unsigned u2 = A0[hq], u3 = A0[hq + 4];
                mma_f16(accB, u2, u2, u3, u3, bwv2[m + 4][0], bwv2[m + 4][1]);
            }
            int o = o0 + 2 * t4;
            float* op = g_att + ((size_t)b * NTOK + g) * C + o;
            *reinterpret_cast<float2*>(op) =
                make_float2(accA[0] + accB[0] + s_bv[o],
                            accA[1] + accB[1] + s_bv[o + 1]);
        }
        __syncthreads();   // s_wh reads done before next W; tgt write ordered at top wait
    }
}

// ---------------------------------------------------------------------------
// K2: FFN chain, fp16 mma (unchanged from R10).
// ---------------------------------------------------------------------------
__device__ __forceinline__ void gemm_mma_h(const unsigned* __restrict__ P,
                                           const unsigned* __restrict__ WH,
                                           float acc[2][4][4], int RM, int CN, int lane) {
    #pragma unroll
    for (int mt = 0; mt < 2; mt++)
        #pragma unroll
        for (int nt = 0; nt < 4; nt++)
            #pragma unroll
            for (int i = 0; i < 4; i++) acc[mt][nt][i] = 0.0f;

    int g = lane >> 2, t4 = lane & 3;
    const unsigned* A0 = P + (RM + g) * PHS;
    const unsigned* A1 = P + (RM + g + 8) * PHS;
    const unsigned* A2 = P + (RM + 16 + g) * PHS;
    const unsigned* A3 = P + (RM + 16 + g + 8) * PHS;

    #pragma unroll
    for (int m = 0; m < 8; m++) {
        int hp = 8 * m + t4;
        unsigned a00 = A0[hp], a01 = A1[hp], a02 = A0[hp + 4], a03 = A1[hp + 4];
        unsigned a10 = A2[hp], a11 = A3[hp], a12 = A2[hp + 4], a13 = A3[hp + 4];
        const unsigned* W0 = WH + (8 * m + t4) * WFS + CN + g;
        const unsigned* W1 = WH + (8 * m + 4 + t4) * WFS + CN + g;
        #pragma unroll
        for (int nt = 0; nt < 4; nt++) {
            unsigned b0 = W0[nt * 8];
            unsigned b1 = W1[nt * 8];
            mma_f16(acc[0][nt], a00, a01, a02, a03, b0, b1);
            mma_f16(acc[1][nt], a10, a11, a12, a13, b0, b1);
        }
    }
}

__global__ __launch_bounds__(512, 1)
void ffn_kernel(const float* __restrict__ query,
                const float* __restrict__ g2, const float* __restrict__ b2,
                const float* __restrict__ Wp, const float* __restrict__ bp,
                const float* __restrict__ Wf1, const float* __restrict__ bf1,
                const float* __restrict__ Wf2, const float* __restrict__ bf2,
                float* __restrict__ out, int nrows) {
    extern __shared__ float sm[];
    unsigned* WH = reinterpret_cast<unsigned*>(sm);         // 64*136 half2
    unsigned* P  = WH + 64 * WFS;                           // 128*68 half2
    float* Q     = reinterpret_cast<float*>(P + 128 * PHS); // 128*132 f32
    float* s_qr  = Q + 128 * QAS;                           // 1024
    float* s_bp  = s_qr + 1024;
    float* s_bf1 = s_bp + 128;
    float* s_bf2 = s_bf1 + 128;
    float* s_g2  = s_bf2 + 128;
    float* s_b2  = s_g2 + 128;

    int tid = threadIdx.x;
    int warp = tid >> 5, lane = tid & 31;
    int g = lane >> 2, t4 = lane & 3;
    int RM = (warp >> 2) * 32, CN = (warp & 3) * 32;
    int R0 = blockIdx.x * 128;
    if (R0 >= nrows) return;

    {
        const float4* src = reinterpret_cast<const float4*>(g_att + (size_t)R0 * C);
        for (int idx = tid; idx < 4096; idx += 512) {
            int row = idx >> 5, j = idx & 31;
            float4 v = src[idx];
            P[row * PHS + 2 * j]     = ph2(v.x, v.y);
            P[row * PHS + 2 * j + 1] = ph2(v.z, v.w);
        }
        for (int idx = tid; idx < 8192; idx += 512) {
            int m = idx >> 7, c = idx & 127;
            WH[m * WFS + c] = ph2(Wp[2 * m * 128 + c], Wp[(2 * m + 1) * 128 + c]);
        }
        for (int i = tid; i < 1024; i += 512) s_qr[i] = query[i];
        if (tid < 128) {
            s_bp[tid] = bp[tid]; s_bf1[tid] = bf1[tid]; s_bf2[tid] = bf2[tid];
            s_g2[tid] = g2[tid]; s_b2[tid] = b2[tid];
        }
    }
    __syncthreads();

    float acc[2][4][4];

    // ---- GEMM1: X = att@Wp + bp + shortcut -> Q (f32) ----
    gemm_mma_h(P, WH, acc, RM, CN, lane);
    #pragma unroll
    for (int mt = 0; mt < 2; mt++) {
        int r = RM + mt * 16 + g;
        #pragma unroll
        for (int nt = 0; nt < 4; nt++) {
            int c = CN + nt * 8 + 2 * t4;
            int tq = r & 7;
            *reinterpret_cast<float2*>(&Q[r * QAS + c]) = make_float2(
                acc[mt][nt][0] + s_bp[c]     + s_qr[tq * 128 + c],
                acc[mt][nt][1] + s_bp[c + 1] + s_qr[tq * 128 + c + 1]);
            *reinterpret_cast<float2*>(&Q[(r + 8) * QAS + c]) = make_float2(
                acc[mt][nt][2] + s_bp[c]     + s_qr[tq * 128 + c],
                acc[mt][nt][3] + s_bp[c + 1] + s_qr[tq * 128 + c + 1]);
        }
    }
    __syncthreads();

    // ---- LN rows Q -> P (half2); load Wf1 -> WH ----
    {
        for (int r = warp; r < 128; r += 16) {
            float4 v = *reinterpret_cast<const float4*>(&Q[r * QAS + lane * 4]);
            float s = v.x + v.y + v.z + v.w;
            #pragma unroll
            for (int o = 16; o; o >>= 1) s += __shfl_xor_sync(~0u, s, o);
            float mean = s * (1.0f / 128.0f);
            float dx = v.x - mean, dy = v.y - mean, dz = v.z - mean, dw = v.w - mean;
            float sq = dx * dx + dy * dy + dz * dz + dw * dw;
            #pragma unroll
            for (int o = 16; o; o >>= 1) sq += __shfl_xor_sync(~0u, sq, o);
            float inv = rsqrtf(sq * (1.0f / 128.0f) + 1e-5f);
            int c = lane * 4;
            float4 gg = *reinterpret_cast<const float4*>(&s_g2[c]);
            float4 bb = *reinterpret_cast<const float4*>(&s_b2[c]);
            P[r * PHS + 2 * lane]     = ph2(dx * inv * gg.x + bb.x, dy * inv * gg.y + bb.y);
            P[r * PHS + 2 * lane + 1] = ph2(dz * inv * gg.z + bb.z, dw * inv * gg.w + bb.w);
        }
        for (int idx = tid; idx < 8192; idx += 512) {
            int m = idx >> 7, c = idx & 127;
            WH[m * WFS + c] = ph2(Wf1[2 * m * 128 + c], Wf1[(2 * m + 1) * 128 + c]);
        }
    }
    __syncthreads();

    // ---- GEMM2: H1 = gelu(Xn@Wf1 + bf1) -> P (half2) ----
    gemm_mma_h(P, WH, acc, RM, CN, lane);
    __syncthreads();
    #pragma unroll
    for (int mt = 0; mt < 2; mt++) {
        int r = RM + mt * 16 + g;
        #pragma unroll
        for (int nt = 0; nt < 4; nt++) {
            int c = CN + nt * 8 + 2 * t4;
            float v0 = acc[mt][nt][0] + s_bf1[c];
            float v1 = acc[mt][nt][1] + s_bf1[c + 1];
            float v2 = acc[mt][nt][2] + s_bf1[c];
            float v3 = acc[mt][nt][3] + s_bf1[c + 1];
            const float k = 0.70710678118654752f;
            P[r * PHS + (c >> 1)] =
                ph2(0.5f * v0 * (1.0f + erff(v0 * k)), 0.5f * v1 * (1.0f + erff(v1 * k)));
            P[(r + 8) * PHS + (c >> 1)] =
                ph2(0.5f * v2 * (1.0f + erff(v2 * k)), 0.5f * v3 * (1.0f + erff(v3 * k)));
        }
    }
    for (int idx = tid; idx < 8192; idx += 512) {
        int m = idx >> 7, c = idx & 127;
        WH[m * WFS + c] = ph2(Wf2[2 * m * 128 + c], Wf2[(2 * m + 1) * 128 + c]);
    }
    __syncthreads();

    // ---- GEMM3: out = X + H1@Wf2 + bf2 ----
    gemm_mma_h(P, WH, acc, RM, CN, lane);
    #pragma unroll
    for (int mt = 0; mt < 2; mt++) {
        int r = RM + mt * 16 + g;
        #pragma unroll
        for (int nt = 0; nt < 4; nt++) {
            int c = CN + nt * 8 + 2 * t4;
            float2 q0 = *reinterpret_cast<const float2*>(&Q[r * QAS + c]);
            float2 q1 = *reinterpret_cast<const float2*>(&Q[(r + 8) * QAS + c]);
            float* o0 = out + (size_t)(R0 + r) * C + c;
            float* o1 = out + (size_t)(R0 + r + 8) * C + c;
            *reinterpret_cast<float2*>(o0) = make_float2(
                acc[mt][nt][0] + s_bf2[c] + q0.x,
                acc[mt][nt][1] + s_bf2[c + 1] + q0.y);
            *reinterpret_cast<float2*>(o1) = make_float2(
                acc[mt][nt][2] + s_bf2[c] + q1.x,
                acc[mt][nt][3] + s_bf2[c + 1] + q1.y);
        }
    }
}

// ---------------------------------------------------------------------------
extern "C" void kernel_launch(void* const* d_in, const int* in_sizes, int n_in,
                              void* d_out, int out_size) {
    const float* query = (const float*)d_in[0];
    const float* tgt   = (const float*)d_in[1];
    const float* ln1g  = (const float*)d_in[2];
    const float* ln1b  = (const float*)d_in[3];
    const float* ln2g  = (const float*)d_in[4];
    const float* ln2b  = (const float*)d_in[5];
    const float* Wq    = (const float*)d_in[6];
    const float* bq    = (const float*)d_in[7];
    const float* Wk    = (const float*)d_in[8];
    // d_in[9] = bk (cancels in softmax)
    const float* Wv    = (const float*)d_in[10];
    const float* bv    = (const float*)d_in[11];
    const float* Wp    = (const float*)d_in[12];
    const float* bp    = (const float*)d_in[13];
    const float* Wf1   = (const float*)d_in[14];
    const float* bf1   = (const float*)d_in[15];
    const float* Wf2   = (const float*)d_in[16];
    const float* bf2   = (const float*)d_in[17];

    int B = in_sizes[1] / (L * C);
    if (B > MAXB) B = MAXB;

    const int K1_SMEM = (72 * QS + 128 + L * TS + 64 * WHS2 + 72 * SPS) * sizeof(float);
    const int K2_SMEM = (64 * WFS + 128 * PHS + 128 * QAS + 1024 + 5 * 128) * sizeof(float);

    cudaFuncSetAttribute(attn_kernel, cudaFuncAttributeMaxDynamicSharedMemorySize, K1_SMEM);
    cudaFuncSetAttribute(ffn_kernel,  cudaFuncAttributeMaxDynamicSharedMemorySize, K2_SMEM);

    prep_kernel<<<64, 128>>>(query, ln1g, ln1b, Wq, bq, Wk);
    attn_kernel<<<(B + BPB - 1) / BPB, 512, K1_SMEM>>>(tgt, Wv, bv, B);

    int nrows = B * NTOK;
    ffn_kernel<<<(nrows + 127) / 128, 512, K2_SMEM>>>(query, ln2g, ln2b,
                                                      Wp, bp, Wf1, bf1, Wf2, bf2,
                                                      (float*)d_out, nrows);
}

// round 16
// speedup vs baseline: 1.7776x; 1.0650x over previous
#include <cuda_runtime.h>
#include <cuda_fp16.h>
#include <math.h>

// Problem constants
#define C 128
#define L 54            // 6*9
#define NTOK 8
#define MAXB 8192
#define BPB 8

// attn smem strides
#define TS   132        // s_tgt f32 row stride
#define QHS  68         // s_qkh half2 row stride
#define SPS  20         // probs f32 row stride
#define WHS2 69         // s_wh half2 row stride

// ffn strides (fp16 path)
#define PHS  68         // P half2 row stride
#define WFS  136        // WH half2 row stride (k-interleaved weights)
#define QAS  132        // Q f32 row stride

// Scratch
__device__ float g_qk[64 * 128];
__device__ float g_att[(size_t)MAXB * NTOK * C];

// ---------------------------------------------------------------------------
__device__ __forceinline__ unsigned smem_u32(const void* p) {
    unsigned a;
    asm("{ .reg .u64 t; cvta.to.shared.u64 t, %1; cvt.u32.u64 %0, t; }" : "=r"(a) : "l"(p));
    return a;
}

__device__ __forceinline__ void mma_tf32(float* acc, unsigned a0, unsigned a1,
                                         unsigned a2, unsigned a3,
                                         unsigned b0, unsigned b1) {
    asm volatile(
        "mma.sync.aligned.m16n8k8.row.col.f32.tf32.tf32.f32 "
        "{%0,%1,%2,%3},{%4,%5,%6,%7},{%8,%9},{%0,%1,%2,%3};\n"
        : "+f"(acc[0]), "+f"(acc[1]), "+f"(acc[2]), "+f"(acc[3])
        : "r"(a0), "r"(a1), "r"(a2), "r"(a3), "r"(b0), "r"(b1));
}

__device__ __forceinline__ void mma_f16(float* acc, unsigned a0, unsigned a1,
                                        unsigned a2, unsigned a3,
                                        unsigned b0, unsigned b1) {
    asm volatile(
        "mma.sync.aligned.m16n8k16.row.col.f32.f16.f16.f32 "
        "{%0,%1,%2,%3},{%4,%5,%6,%7},{%8,%9},{%0,%1,%2,%3};\n"
        : "+f"(acc[0]), "+f"(acc[1]), "+f"(acc[2]), "+f"(acc[3])
        : "r"(a0), "r"(a1), "r"(a2), "r"(a3), "r"(b0), "r"(b1));
}

__device__ __forceinline__ unsigned f2u(float x) { return __float_as_uint(x); }

__device__ __forceinline__ unsigned ph2(float a, float b) {
    __half2 h = __floats2half2_rn(a, b);
    return *reinterpret_cast<unsigned*>(&h);
}

// ---------------------------------------------------------------------------
// K0: prep (unchanged)
// ---------------------------------------------------------------------------
__global__ void prep_kernel(const float* __restrict__ q_in,
                            const float* __restrict__ g1, const float* __restrict__ b1,
                            const float* __restrict__ Wq, const float* __restrict__ bq,
                            const float* __restrict__ Wk) {
    __shared__ float s_qn[128];
    __shared__ float s_qh[16];
    __shared__ float s_red[8];
    int th = blockIdx.x, t = th >> 3, h = th & 7;
    int tid = threadIdx.x, lane = tid & 31, warp = tid >> 5;

    float x = q_in[t * 128 + tid];
    float s = x;
    #pragma unroll
    for (int o = 16; o; o >>= 1) s += __shfl_xor_sync(~0u, s, o);
    if (lane == 0) s_red[warp] = s;
    __syncthreads();
    float mean = (s_red[0] + s_red[1] + s_red[2] + s_red[3]) * (1.0f / 128.0f);
    float dx = x - mean;
    float sq = dx * dx;
    #pragma unroll
    for (int o = 16; o; o >>= 1) sq += __shfl_xor_sync(~0u, sq, o);
    __syncthreads();
    if (lane == 0) s_red[warp] = sq;
    __syncthreads();
    float var = (s_red[0] + s_red[1] + s_red[2] + s_red[3]) * (1.0f / 128.0f);
    float inv = rsqrtf(var + 1e-5f);
    s_qn[tid] = dx * inv * g1[tid] + b1[tid];
    __syncthreads();

    int j = tid >> 3, seg = tid & 7;
    int o = h * 16 + j;
    float p = 0.0f;
    #pragma unroll
    for (int i = 0; i < 16; i++) p += s_qn[seg * 16 + i] * Wq[(seg * 16 + i) * 128 + o];
    #pragma unroll
    for (int off = 4; off; off >>= 1) p += __shfl_xor_sync(~0u, p, off);
    if (seg == 0) s_qh[j] = p + bq[o];
    __syncthreads();

    float acc = 0.0f;
    const float* wk = Wk + tid * 128 + h * 16;
    #pragma unroll
    for (int jj = 0; jj < 16; jj++) acc += s_qh[jj] * wk[jj];
    g_qk[th * 128 + tid] = acc * 0.25f;
}

// region-row offset within region for li (0..8); li>=9 -> 0 (padding)
__device__ __forceinline__ int loff(int li) {
    if (li >= 9) return 0;
    int a = li / 3, b = li - a * 3;
    return a * 9 + b;
}

// ---------------------------------------------------------------------------
// K1: fused attention — R12 structure; D phase fp16 (qk in half2).
// ---------------------------------------------------------------------------
__global__ __launch_bounds__(512, 2)
void attn_kernel(const float* __restrict__ tgt,
                 const float* __restrict__ Wv, const float* __restrict__ bv,
                 int B) {
    extern __shared__ float sm[];
    unsigned* s_qkh = reinterpret_cast<unsigned*>(sm);             // 72*68 half2
    float* s_bv  = sm + 72 * QHS;                                  // 128
    float* s_tgt = s_bv + 128;                                     // 54*132 f32
    unsigned* s_wh = reinterpret_cast<unsigned*>(s_tgt + L * TS);  // 64*69 half2
    float* s_p   = reinterpret_cast<float*>(s_wh + 64 * WHS2);     // 72*20 f32

    int tid = threadIdx.x;
    int warp = tid >> 5, lane = tid & 31;
    int g = lane >> 2, t4 = lane & 3;

    // prologue: cp.async first batch
    {
        int b0 = blockIdx.x * BPB;
        if (b0 < B) {
            const float4* src = reinterpret_cast<const float4*>(tgt + (size_t)b0 * L * C);
            for (int idx = tid; idx < L * 32; idx += 512) {
                int row = idx >> 5, j = idx & 31;
                unsigned dst = smem_u32(s_tgt + row * TS + j * 4);
                asm volatile("cp.async.ca.shared.global [%0], [%1], 16;\n"
                             :: "r"(dst), "l"(src + idx));
            }
            asm volatile("cp.async.commit_group;\n");
        }
    }

    // stage qk permuted (region-major rows) as half2
    for (int idx = tid; idx < 2048; idx += 512) {
        int tr = idx >> 5, j = idx & 31;
        int t = tr >> 3, h = tr & 7;
        int pos = t + (t == 1) - (t == 2);
        int prow = pos * 8 + h;
        float4 v = reinterpret_cast<const float4*>(g_qk)[idx];
        s_qkh[prow * QHS + 2 * j]     = ph2(v.x, v.y);
        s_qkh[prow * QHS + 2 * j + 1] = ph2(v.z, v.w);
    }
    for (int i = 64 * QHS + tid; i < 72 * QHS; i += 512) s_qkh[i] = 0u;
    for (int i = tid; i < 72 * SPS; i += 512) s_p[i] = 0.0f;
    if (tid < 128) s_bv[tid] = bv[tid];

    // ---- per-warp job parameters (static across batches) ----
    bool okD = warp < 12;
    int rD  = warp >> 1, nhD = warp & 1;
    int mbD = (rD < 2) ? rD * 16 : 32 + (rD - 2) * 8;
    int blD = (rD / 3) * 27 + (rD % 3) * 3;
    int liD = nhD * 8 + g;
    int lD  = blD + loff(liD);
    int lW0 = blD + loff(t4);
    int lW1 = blD + loff(t4 + 4);
    int lW2 = blD + loff(t4 + 8);
    int lW3 = blD + loff(t4 + 12);
    int hV = warp >> 1, nhV = warp & 1;
    int o0 = hV * 16 + nhV * 8;

    // ---- hoist Wv B-fragments as half2 (static per warp) ----
    unsigned bwv2[8][2];
    #pragma unroll
    for (int m = 0; m < 8; m++) {
        int k0 = 16 * m + 2 * t4;
        int oc = o0 + g;
        bwv2[m][0] = ph2(Wv[k0 * 128 + oc],       Wv[(k0 + 1) * 128 + oc]);
        bwv2[m][1] = ph2(Wv[(k0 + 8) * 128 + oc], Wv[(k0 + 9) * 128 + oc]);
    }

    __syncthreads();

    for (int bi = 0; bi < BPB; bi++) {
        int b = blockIdx.x * BPB + bi;
        if (b >= B) break;

        const float* cur = s_tgt;

        asm volatile("cp.async.wait_group 0;\n");
        __syncthreads();   // tgt ready for all

        // ---- D: dots via fp16 mma (two independent 4-deep chains) ----
        if (okD) {
            float accA[4] = {0.f, 0.f, 0.f, 0.f};
            float accB[4] = {0.f, 0.f, 0.f, 0.f};
            const unsigned* A0 = s_qkh + (mbD + g) * QHS;
            const unsigned* A1 = s_qkh + (mbD + g + 8) * QHS;
            const float* Br = cur + lD * TS;
            #pragma unroll
            for (int m = 0; m < 4; m++) {
                int hp = 8 * m + t4;
                float2 f0 = *reinterpret_cast<const float2*>(Br + 16 * m + 2 * t4);
                float2 f1 = *reinterpret_cast<const float2*>(Br + 16 * m + 2 * t4 + 8);
                mma_f16(accA, A0[hp], A1[hp], A0[hp + 4], A1[hp + 4],
                        ph2(f0.x, f0.y), ph2(f1.x, f1.y));
                int m2 = m + 4;
                int hq = 8 * m2 + t4;
                float2 f2 = *reinterpret_cast<const float2*>(Br + 16 * m2 + 2 * t4);
                float2 f3 = *reinterpret_cast<const float2*>(Br + 16 * m2 + 2 * t4 + 8);
                mma_f16(accB, A0[hq], A1[hq], A0[hq + 4], A1[hq + 4],
                        ph2(f2.x, f2.y), ph2(f3.x, f3.y));
            }
            float acc[4];
            #pragma unroll
            for (int i = 0; i < 4; i++) acc[i] = accA[i] + accB[i];
            int li0 = nhD * 8 + 2 * t4;
            if (li0 < 8) {
                *reinterpret_cast<float2*>(&s_p[(mbD + g) * SPS + li0]) =
                    make_float2(acc[0], acc[1]);
                if (rD < 2)
                    *reinterpret_cast<float2*>(&s_p[(mbD + g + 8) * SPS + li0]) =
                        make_float2(acc[2], acc[3]);
            } else if (li0 == 8) {
                s_p[(mbD + g) * SPS + 8] = acc[0];
                if (rD < 2) s_p[(mbD + g + 8) * SPS + 8] = acc[2];
            }
        }
        __syncthreads();

        // ---- softmax over 9 per row (64 rows) ----
        if (tid < 64) {
            float* pp = s_p + tid * SPS;
            float m = -1e30f;
            #pragma unroll
            for (int li = 0; li < 9; li++) m = fmaxf(m, pp[li]);
            float e[9]; float ssum = 0.0f;
            #pragma unroll
            for (int li = 0; li < 9; li++) { e[li] = expf(pp[li] - m); ssum += e[li]; }
            float invs = 1.0f / ssum;
            #pragma unroll
            for (int li = 0; li < 9; li++) pp[li] = e[li] * invs;
        }
        __syncthreads();

        // ---- W: weighted sum via tf32 mma, epilogue packs half2 into s_wh ----
        if (okD) {
            const float* Ar0 = s_p + (mbD + g) * SPS;
            const float* Ar1 = s_p + (mbD + g + 8) * SPS;
            unsigned a0 = f2u(Ar0[t4]),      a1 = f2u(Ar1[t4]);
            unsigned a2 = f2u(Ar0[t4 + 4]),  a3 = f2u(Ar1[t4 + 4]);
            unsigned a4 = f2u(Ar0[t4 + 8]),  a5 = f2u(Ar1[t4 + 8]);
            unsigned a6 = f2u(Ar0[t4 + 12]), a7 = f2u(Ar1[t4 + 12]);
            int p0 = mbD + g;
            int pos0 = p0 >> 3;
            int t0 = pos0 + (pos0 == 1) - (pos0 == 2);
            int v0 = (p0 & 7) * 8 + t0;
            int p1 = mbD + g + 8;
            int pos1 = p1 >> 3;
            int t1 = pos1 + (pos1 == 1) - (pos1 == 2);
            int v1 = (p1 & 7) * 8 + t1;

            #pragma unroll
            for (int nt = 0; nt < 8; nt++) {
                int c0 = nhD * 64 + nt * 8;
                float accA[4] = {0.f, 0.f, 0.f, 0.f};
                float accB[4] = {0.f, 0.f, 0.f, 0.f};
                mma_tf32(accA, a0, a1, a2, a3,
                         f2u(cur[lW0 * TS + c0 + g]), f2u(cur[lW1 * TS + c0 + g]));
                mma_tf32(accB, a4, a5, a6, a7,
                         f2u(cur[lW2 * TS + c0 + g]), f2u(cur[lW3 * TS + c0 + g]));
                int hc = (c0 >> 1) + t4;
                s_wh[v0 * WHS2 + hc] = ph2(accA[0] + accB[0], accA[1] + accB[1]);
                if (rD < 2)
                    s_wh[v1 * WHS2 + hc] = ph2(accA[2] + accB[2], accA[3] + accB[3]);
            }
        }
        __syncthreads();   // s_wh complete; ALL tgt reads done

        // prefetch next batch into s_tgt (overlaps V; waited at top of next iter)
        int nb = b + 1;
        if (bi + 1 < BPB && nb < B) {
            const float4* src = reinterpret_cast<const float4*>(tgt + (size_t)nb * L * C);
            for (int idx = tid; idx < L * 32; idx += 512) {
                int row = idx >> 5, j = idx & 31;
                unsigned dst = smem_u32(s_tgt + row * TS + j * 4);
                asm volatile("cp.async.ca.shared.global [%0], [%1], 16;\n"
                             :: "r"(dst), "l"(src + idx));
            }
            asm volatile("cp.async.commit_group;\n");
        }

        // ---- V: att[t, o] = w . Wv + bv  (fp16 mma, B hoisted in regs) ----
        {
            float accA[4] = {0.f, 0.f, 0.f, 0.f};
            float accB[4] = {0.f, 0.f, 0.f, 0.f};
            const unsigned* A0 = s_wh + (hV * 8 + g) * WHS2;
            #pragma unroll
            for (int m = 0; m < 4; m++) {
                int hp = 8 * m + t4;
                unsigned u0 = A0[hp], u1 = A0[hp + 4];
                mma_f16(accA, u0, u0, u1, u1, bwv2[m][0], bwv2[m][1]);
                int hq = 8 * (m + 4) + t4;
                unsigned u2 = A0[hq], u3 = A0[hq + 4];
                mma_f16(accB, u2, u2, u3, u3, bwv2[m + 4][0], bwv2[m + 4][1]);
            }
            int o = o0 + 2 * t4;
            float* op = g_att + ((size_t)b * NTOK + g) * C + o;
            *reinterpret_cast<float2*>(op) =
                make_float2(accA[0] + accB[0] + s_bv[o],
                            accA[1] + accB[1] + s_bv[o + 1]);
        }
        __syncthreads();   // s_wh reads done before next W; tgt write ordered at top wait
    }
}

// ---------------------------------------------------------------------------
// K2: FFN chain, fp16 mma (unchanged from R12).
// ---------------------------------------------------------------------------
__device__ __forceinline__ void gemm_mma_h(const unsigned* __restrict__ P,
                                           const unsigned* __restrict__ WH,
                                           float acc[2][4][4], int RM, int CN, int lane) {
    #pragma unroll
    for (int mt = 0; mt < 2; mt++)
        #pragma unroll
        for (int nt = 0; nt < 4; nt++)
            #pragma unroll
            for (int i = 0; i < 4; i++) acc[mt][nt][i] = 0.0f;

    int g = lane >> 2, t4 = lane & 3;
    const unsigned* A0 = P + (RM + g) * PHS;
    const unsigned* A1 = P + (RM + g + 8) * PHS;
    const unsigned* A2 = P + (RM + 16 + g) * PHS;
    const unsigned* A3 = P + (RM + 16 + g + 8) * PHS;

    #pragma unroll
    for (int m = 0; m < 8; m++) {
        int hp = 8 * m + t4;
        unsigned a00 = A0[hp], a01 = A1[hp], a02 = A0[hp + 4], a03 = A1[hp + 4];
        unsigned a10 = A2[hp], a11 = A3[hp], a12 = A2[hp + 4], a13 = A3[hp + 4];
        const unsigned* W0 = WH + (8 * m + t4) * WFS + CN + g;
        const unsigned* W1 = WH + (8 * m + 4 + t4) * WFS + CN + g;
        #pragma unroll
        for (int nt = 0; nt < 4; nt++) {
            unsigned b0 = W0[nt * 8];
            unsigned b1 = W1[nt * 8];
            mma_f16(acc[0][nt], a00, a01, a02, a03, b0, b1);
            mma_f16(acc[1][nt], a10, a11, a12, a13, b0, b1);
        }
    }
}

__global__ __launch_bounds__(512, 1)
void ffn_kernel(const float* __restrict__ query,
                const float* __restrict__ g2, const float* __restrict__ b2,
                const float* __restrict__ Wp, const float* __restrict__ bp,
                const float* __restrict__ Wf1, const float* __restrict__ bf1,
                const float* __restrict__ Wf2, const float* __restrict__ bf2,
                float* __restrict__ out, int nrows) {
    extern __shared__ float sm[];
    unsigned* WH = reinterpret_cast<unsigned*>(sm);         // 64*136 half2
    unsigned* P  = WH + 64 * WFS;                           // 128*68 half2
    float* Q     = reinterpret_cast<float*>(P + 128 * PHS); // 128*132 f32
    float* s_qr  = Q + 128 * QAS;                           // 1024
    float* s_bp  = s_qr + 1024;
    float* s_bf1 = s_bp + 128;
    float* s_bf2 = s_bf1 + 128;
    float* s_g2  = s_bf2 + 128;
    float* s_b2  = s_g2 + 128;

    int tid = threadIdx.x;
    int warp = tid >> 5, lane = tid & 31;
    int g = lane >> 2, t4 = lane & 3;
    int RM = (warp >> 2) * 32, CN = (warp & 3) * 32;
    int R0 = blockIdx.x * 128;
    if (R0 >= nrows) return;

    {
        const float4* src = reinterpret_cast<const float4*>(g_att + (size_t)R0 * C);
        for (int idx = tid; idx < 4096; idx += 512) {
            int row = idx >> 5, j = idx & 31;
            float4 v = src[idx];
            P[row * PHS + 2 * j]     = ph2(v.x, v.y);
            P[row * PHS + 2 * j + 1] = ph2(v.z, v.w);
        }
        for (int idx = tid; idx < 8192; idx += 512) {
            int m = idx >> 7, c = idx & 127;
            WH[m * WFS + c] = ph2(Wp[2 * m * 128 + c], Wp[(2 * m + 1) * 128 + c]);
        }
        for (int i = tid; i < 1024; i += 512) s_qr[i] = query[i];
        if (tid < 128) {
            s_bp[tid] = bp[tid]; s_bf1[tid] = bf1[tid]; s_bf2[tid] = bf2[tid];
            s_g2[tid] = g2[tid]; s_b2[tid] = b2[tid];
        }
    }
    __syncthreads();

    float acc[2][4][4];

    // ---- GEMM1: X = att@Wp + bp + shortcut -> Q (f32) ----
    gemm_mma_h(P, WH, acc, RM, CN, lane);
    #pragma unroll
    for (int mt = 0; mt < 2; mt++) {
        int r = RM + mt * 16 + g;
        #pragma unroll
        for (int nt = 0; nt < 4; nt++) {
            int c = CN + nt * 8 + 2 * t4;
            int tq = r & 7;
            *reinterpret_cast<float2*>(&Q[r * QAS + c]) = make_float2(
                acc[mt][nt][0] + s_bp[c]     + s_qr[tq * 128 + c],
                acc[mt][nt][1] + s_bp[c + 1] + s_qr[tq * 128 + c + 1]);
            *reinterpret_cast<float2*>(&Q[(r + 8) * QAS + c]) = make_float2(
                acc[mt][nt][2] + s_bp[c]     + s_qr[tq * 128 + c],
                acc[mt][nt][3] + s_bp[c + 1] + s_qr[tq * 128 + c + 1]);
        }
    }
    __syncthreads();

    // ---- LN rows Q -> P (half2); load Wf1 -> WH ----
    {
        for (int r = warp; r < 128; r += 16) {
            float4 v = *reinterpret_cast<const float4*>(&Q[r * QAS + lane * 4]);
            float s = v.x + v.y + v.z + v.w;
            #pragma unroll
            for (int o = 16; o; o >>= 1) s += __shfl_xor_sync(~0u, s, o);
            float mean = s * (1.0f / 128.0f);
            float dx = v.x - mean, dy = v.y - mean, dz = v.z - mean, dw = v.w - mean;
            float sq = dx * dx + dy * dy + dz * dz + dw * dw;
            #pragma unroll
            for (int o = 16; o; o >>= 1) sq += __shfl_xor_sync(~0u, sq, o);
            float inv = rsqrtf(sq * (1.0f / 128.0f) + 1e-5f);
            int c = lane * 4;
            float4 gg = *reinterpret_cast<const float4*>(&s_g2[c]);
            float4 bb = *reinterpret_cast<const float4*>(&s_b2[c]);
            P[r * PHS + 2 * lane]     = ph2(dx * inv * gg.x + bb.x, dy * inv * gg.y + bb.y);
            P[r * PHS + 2 * lane + 1] = ph2(dz * inv * gg.z + bb.z, dw * inv * gg.w + bb.w);
        }
        for (int idx = tid; idx < 8192; idx += 512) {
            int m = idx >> 7, c = idx & 127;
            WH[m * WFS + c] = ph2(Wf1[2 * m * 128 + c], Wf1[(2 * m + 1) * 128 + c]);
        }
    }
    __syncthreads();

    // ---- GEMM2: H1 = gelu(Xn@Wf1 + bf1) -> P (half2) ----
    gemm_mma_h(P, WH, acc, RM, CN, lane);
    __syncthreads();
    #pragma unroll
    for (int mt = 0; mt < 2; mt++) {
        int r = RM + mt * 16 + g;
        #pragma unroll
        for (int nt = 0; nt < 4; nt++) {
            int c = CN + nt * 8 + 2 * t4;
            float v0 = acc[mt][nt][0] + s_bf1[c];
            float v1 = acc[mt][nt][1] + s_bf1[c + 1];
            float v2 = acc[mt][nt][2] + s_bf1[c];
            float v3 = acc[mt][nt][3] + s_bf1[c + 1];
            const float k = 0.70710678118654752f;
            P[r * PHS + (c >> 1)] =
                ph2(0.5f * v0 * (1.0f + erff(v0 * k)), 0.5f * v1 * (1.0f + erff(v1 * k)));
            P[(r + 8) * PHS + (c >> 1)] =
                ph2(0.5f * v2 * (1.0f + erff(v2 * k)), 0.5f * v3 * (1.0f + erff(v3 * k)));
        }
    }
    for (int idx = tid; idx < 8192; idx += 512) {
        int m = idx >> 7, c = idx & 127;
        WH[m * WFS + c] = ph2(Wf2[2 * m * 128 + c], Wf2[(2 * m + 1) * 128 + c]);
    }
    __syncthreads();

    // ---- GEMM3: out = X + H1@Wf2 + bf2 ----
    gemm_mma_h(P, WH, acc, RM, CN, lane);
    #pragma unroll
    for (int mt = 0; mt < 2; mt++) {
        int r = RM + mt * 16 + g;
        #pragma unroll
        for (int nt = 0; nt < 4; nt++) {
            int c = CN + nt * 8 + 2 * t4;
            float2 q0 = *reinterpret_cast<const float2*>(&Q[r * QAS + c]);
            float2 q1 = *reinterpret_cast<const float2*>(&Q[(r + 8) * QAS + c]);
            float* o0 = out + (size_t)(R0 + r) * C + c;
            float* o1 = out + (size_t)(R0 + r + 8) * C + c;
            *reinterpret_cast<float2*>(o0) = make_float2(
                acc[mt][nt][0] + s_bf2[c] + q0.x,
                acc[mt][nt][1] + s_bf2[c + 1] + q0.y);
            *reinterpret_cast<float2*>(o1) = make_float2(
                acc[mt][nt][2] + s_bf2[c] + q1.x,
                acc[mt][nt][3] + s_bf2[c + 1] + q1.y);
        }
    }
}

// ---------------------------------------------------------------------------
extern "C" void kernel_launch(void* const* d_in, const int* in_sizes, int n_in,
                              void* d_out, int out_size) {
    const float* query = (const float*)d_in[0];
    const float* tgt   = (const float*)d_in[1];
    const float* ln1g  = (const float*)d_in[2];
    const float* ln1b  = (const float*)d_in[3];
    const float* ln2g  = (const float*)d_in[4];
    const float* ln2b  = (const float*)d_in[5];
    const float* Wq    = (const float*)d_in[6];
    const float* bq    = (const float*)d_in[7];
    const float* Wk    = (const float*)d_in[8];
    // d_in[9] = bk (cancels in softmax)
    const float* Wv    = (const float*)d_in[10];
    const float* bv    = (const float*)d_in[11];
    const float* Wp    = (const float*)d_in[12];
    const float* bp    = (const float*)d_in[13];
    const float* Wf1   = (const float*)d_in[14];
    const float* bf1   = (const float*)d_in[15];
    const float* Wf2   = (const float*)d_in[16];
    const float* bf2   = (const float*)d_in[17];

    int B = in_sizes[1] / (L * C);
    if (B > MAXB) B = MAXB;

    const int K1_SMEM = (72 * QHS + 128 + L * TS + 64 * WHS2 + 72 * SPS) * sizeof(float);
    const int K2_SMEM = (64 * WFS + 128 * PHS + 128 * QAS + 1024 + 5 * 128) * sizeof(float);

    cudaFuncSetAttribute(attn_kernel, cudaFuncAttributeMaxDynamicSharedMemorySize, K1_SMEM);
    cudaFuncSetAttribute(ffn_kernel,  cudaFuncAttributeMaxDynamicSharedMemorySize, K2_SMEM);

    prep_kernel<<<64, 128>>>(query, ln1g, ln1b, Wq, bq, Wk);
    attn_kernel<<<(B + BPB - 1) / BPB, 512, K1_SMEM>>>(tgt, Wv, bv, B);

    int nrows = B * NTOK;
    ffn_kernel<<<(nrows + 127) / 128, 512, K2_SMEM>>>(query, ln2g, ln2b,
                                                      Wp, bp, Wf1, bf1, Wf2, bf2,
                                                      (float*)d_out, nrows);
}